// round 7
// baseline (speedup 1.0000x reference)
#include <cuda_runtime.h>
#include <cstdint>

#define Bq 8192
#define Dm 1024
#define NBR 7
#define BD ((size_t)Bq * Dm)
#define DD ((size_t)Dm * Dm)

// ---------------- scratch ----------------
__device__ float g_Q[NBR * Dm];
__device__ float g_SC[(size_t)4 * Bq * 256];
__device__ float g_A[(size_t)NBR * 4 * Bq * 16];
__device__ float g_V[(size_t)19 * BD];
__device__ __align__(16) int8_t g_A0[4 * BD],   g_A1[4 * BD];     // x digit planes
__device__ __align__(16) int8_t g_W0[14 * DD],  g_W1[14 * DD];    // weight digit planes
__device__ __align__(16) int8_t g_O0[NBR * BD], g_O1[NBR * BD];   // attn-out digit planes
__device__ __align__(16) int8_t g_S0[256 * Dm], g_S1[256 * Dm];   // score-vec digit planes
__device__ float g_sA[4 * Bq], g_sW[14 * Dm], g_sO[NBR * Bq], g_sS[256];

__constant__ int c_nvec[NBR] = {2,2,2,3,3,3,4};
__constant__ int c_vidx[NBR][4] = {{0,1,0,0},{0,2,0,0},{0,3,0,0},{0,1,2,0},{0,1,3,0},{0,2,3,0},{0,1,2,3}};
__constant__ int c_poff[NBR] = {0,2,4,6,9,12,15};
__constant__ int c_pairi[19] = {0,0,1,1,2,2,3,3,3,4,4,4,5,5,5,6,6,6,6};
__constant__ int c_pairv[19] = {0,1,0,2,0,3,0,1,2,0,1,3,0,2,3,0,1,2,3};

// tiled+swizzled int8 offset within a [kc][R rows][32B] plane
__device__ __forceinline__ size_t toff8(int row, int k, int R) {
  return ((size_t)(k >> 5) * R + row) * 32 + ((k & 31) ^ (((row >> 2) & 1) << 4));
}

// ---------------- PTX helpers ----------------
__device__ __forceinline__ uint32_t smem_u32(const void* p) {
  uint32_t a;
  asm("{ .reg .u64 t; cvta.to.shared.u64 t, %1; cvt.u32.u64 %0, t; }" : "=r"(a) : "l"(p));
  return a;
}
#define MBAR_INIT(a, n) asm volatile("mbarrier.init.shared.b64 [%0], %1;" :: "r"(a), "r"(n) : "memory")
#define MBAR_EXPECT(a, b) asm volatile("mbarrier.arrive.expect_tx.shared.b64 _, [%0], %1;" :: "r"(a), "r"(b) : "memory")
#define MBAR_WAIT(a, ph) do { \
  uint32_t _m = (a), _p = (ph), _d; \
  asm volatile("{ .reg .pred p; mbarrier.try_wait.parity.acquire.cta.shared::cta.b64 p, [%1], %2; selp.b32 %0,1,0,p; }" \
    : "=r"(_d) : "r"(_m), "r"(_p) : "memory"); \
  if (!_d) { asm volatile("{ .reg .pred P1; WL_%=: mbarrier.try_wait.parity.acquire.cta.shared::cta.b64 P1, [%0], %1, 0x989680; @P1 bra.uni WD_%=; bra.uni WL_%=; WD_%=: }" \
    :: "r"(_m), "r"(_p) : "memory"); } } while (0)

__device__ __forceinline__ void bulk_g2s(uint32_t dst, const void* src, uint32_t bytes, uint32_t mbar) {
  asm volatile("cp.async.bulk.shared::cluster.global.mbarrier::complete_tx::bytes [%0], [%1], %2, [%3];"
               :: "r"(dst), "l"(src), "r"(bytes), "r"(mbar) : "memory");
}
__device__ __forceinline__ void ldsm4(uint32_t& r0, uint32_t& r1, uint32_t& r2, uint32_t& r3, uint32_t addr) {
  asm volatile("ldmatrix.sync.aligned.m8n8.x4.shared.b16 {%0,%1,%2,%3}, [%4];"
               : "=r"(r0), "=r"(r1), "=r"(r2), "=r"(r3) : "r"(addr));
}
__device__ __forceinline__ void mma_s8(int32_t* c, const uint32_t* a, const uint32_t* b) {
  asm volatile("mma.sync.aligned.m16n8k32.row.col.s32.s8.s8.s32 "
               "{%0,%1,%2,%3}, {%4,%5,%6,%7}, {%8,%9}, {%0,%1,%2,%3};"
               : "+r"(c[0]), "+r"(c[1]), "+r"(c[2]), "+r"(c[3])
               : "r"(a[0]), "r"(a[1]), "r"(a[2]), "r"(a[3]), "r"(b[0]), "r"(b[1]));
}

// ---------------- quant helpers ----------------
__device__ __forceinline__ float blockmax(float v, float* sm, int tid) {
  sm[tid] = v; __syncthreads();
  #pragma unroll
  for (int s = 128; s > 0; s >>= 1) {
    if (tid < s) sm[tid] = fmaxf(sm[tid], sm[tid + s]);
    __syncthreads();
  }
  float r = sm[0]; __syncthreads();
  return r;
}
__device__ __forceinline__ void quant1(float x, float inv, int8_t& d0, int8_t& d1) {
  float q = x * inv;
  int i0 = __float2int_rn(q);
  int i1 = __float2int_rn((q - (float)i0) * 254.f);
  d0 = (int8_t)i0; d1 = (int8_t)i1;
}

// ======================= prep / quant kernels =======================
__global__ void k_qh(const float* __restrict__ tokens, const float* __restrict__ w_in,
                     const float* __restrict__ b_in) {
  int i = blockIdx.x, t = threadIdx.x;
  __shared__ float tok[Dm];
  for (int k = t; k < Dm; k += 256) tok[k] = tokens[i * Dm + k];
  __syncthreads();
  const float* wq = w_in + (size_t)i * 3 * DD;
  for (int r = t; r < Dm; r += 256) {
    const float* row = wq + (size_t)r * Dm;
    float acc = b_in[i * 3 * Dm + r];
    for (int k = 0; k < Dm; k += 4) {
      float4 w = *(const float4*)(row + k);
      acc += w.x*tok[k] + w.y*tok[k+1] + w.z*tok[k+2] + w.w*tok[k+3];
    }
    g_Q[i * Dm + r] = acc;
  }
}

// quantize x planes: block per (row m, v)
__global__ void k_quantA(const float* __restrict__ xc, const float* __restrict__ xf,
                         const float* __restrict__ xbd, const float* __restrict__ xbg) {
  __shared__ float sm[256];
  int v = blockIdx.y, m = blockIdx.x, tid = threadIdx.x;
  const float* x = (v == 0) ? xc : (v == 1) ? xf : (v == 2) ? xbd : xbg;
  float4 val = ((const float4*)(x + (size_t)m * Dm))[tid];
  float mx = fmaxf(fmaxf(fabsf(val.x), fabsf(val.y)), fmaxf(fabsf(val.z), fabsf(val.w)));
  mx = fmaxf(blockmax(mx, sm, tid), 1e-20f);
  float inv = 127.f / mx;
  char4 d0, d1;
  quant1(val.x, inv, d0.x, d1.x); quant1(val.y, inv, d0.y, d1.y);
  quant1(val.z, inv, d0.z, d1.z); quant1(val.w, inv, d0.w, d1.w);
  size_t off = (size_t)v * BD + toff8(m, tid * 4, Bq);
  *(char4*)(g_A0 + off) = d0;
  *(char4*)(g_A1 + off) = d1;
  if (tid == 0) g_sA[v * Bq + m] = mx / 127.f;
}

// quantize weight planes: block per (row n, z)
__global__ void k_quantW(const float* __restrict__ w_in, const float* __restrict__ w_out) {
  __shared__ float sm[256];
  int z = blockIdx.y, n = blockIdx.x, tid = threadIdx.x;
  const float* src = (z < 7) ? (w_in + (size_t)z * 3 * DD + 2 * DD) : (w_out + (size_t)(z - 7) * DD);
  float4 val = ((const float4*)(src + (size_t)n * Dm))[tid];
  float mx = fmaxf(fmaxf(fabsf(val.x), fabsf(val.y)), fmaxf(fabsf(val.z), fabsf(val.w)));
  mx = fmaxf(blockmax(mx, sm, tid), 1e-20f);
  float inv = 127.f / mx;
  char4 d0, d1;
  quant1(val.x, inv, d0.x, d1.x); quant1(val.y, inv, d0.y, d1.y);
  quant1(val.z, inv, d0.z, d1.z); quant1(val.w, inv, d0.w, d1.w);
  size_t off = (size_t)z * DD + toff8(n, tid * 4, Dm);
  *(char4*)(g_W0 + off) = d0;
  *(char4*)(g_W1 + off) = d1;
  if (tid == 0) g_sW[z * Dm + n] = mx / 127.f;
}

__global__ void k_zq() {   // zero score digit planes + scales
  size_t i = ((size_t)blockIdx.x * 256 + threadIdx.x) * 4;
  *(char4*)(g_S0 + i) = make_char4(0,0,0,0);
  *(char4*)(g_S1 + i) = make_char4(0,0,0,0);
  if (blockIdx.x == 0) g_sS[threadIdx.x] = 0.f;
}

// s row (ih = i*16+h): s[k] = 0.125 * sum_j qh[h*64+j] * Wk[h*64+j][k]; quantize
__global__ void k_sq(const float* __restrict__ w_in) {
  __shared__ float sm[256];
  __shared__ float qh[64];
  int ih = blockIdx.x, tid = threadIdx.x;
  int i = ih >> 4, h = ih & 15;
  if (tid < 64) qh[tid] = g_Q[i * Dm + h * 64 + tid];
  __syncthreads();
  const float* wk = w_in + (size_t)i * 3 * DD + DD + (size_t)h * 64 * Dm;
  float4 acc = make_float4(0.f, 0.f, 0.f, 0.f);
  #pragma unroll 8
  for (int j = 0; j < 64; j++) {
    float qj = qh[j];
    float4 w = ((const float4*)(wk + (size_t)j * Dm))[tid];
    acc.x += qj * w.x; acc.y += qj * w.y; acc.z += qj * w.z; acc.w += qj * w.w;
  }
  acc.x *= 0.125f; acc.y *= 0.125f; acc.z *= 0.125f; acc.w *= 0.125f;
  float mx = fmaxf(fmaxf(fabsf(acc.x), fabsf(acc.y)), fmaxf(fabsf(acc.z), fabsf(acc.w)));
  mx = fmaxf(blockmax(mx, sm, tid), 1e-20f);
  float inv = 127.f / mx;
  char4 d0, d1;
  quant1(acc.x, inv, d0.x, d1.x); quant1(acc.y, inv, d0.y, d1.y);
  quant1(acc.z, inv, d0.z, d1.z); quant1(acc.w, inv, d0.w, d1.w);
  size_t off = toff8(ih, tid * 4, 256);
  *(char4*)(g_S0 + off) = d0;
  *(char4*)(g_S1 + off) = d1;
  if (tid == 0) g_sS[ih] = mx / 127.f;
}

__global__ void k_softmax() {
  int idx = blockIdx.x * 256 + threadIdx.x;
  int h = idx & 15;
  int b = (idx >> 4) & (Bq - 1);
  int i = idx >> 17;
  int L = c_nvec[i];
  float sc[4];
  float mx = -1e30f;
  #pragma unroll
  for (int l = 0; l < 4; l++) if (l < L) {
    sc[l] = g_SC[((size_t)c_vidx[i][l] * Bq + b) * 256 + i * 16 + h];
    mx = fmaxf(mx, sc[l]);
  }
  float sum = 0.f;
  #pragma unroll
  for (int l = 0; l < 4; l++) if (l < L) { sc[l] = expf(sc[l] - mx); sum += sc[l]; }
  float inv = 1.f / sum;
  #pragma unroll
  for (int l = 0; l < 4; l++) if (l < L)
    g_A[(((size_t)i * 4 + l) * Bq + b) * 16 + h] = sc[l] * inv;
}

// mix + quantize O: block per (b, i)
__global__ void k_mixq(const float* __restrict__ b_in) {
  __shared__ float sm[256];
  int b = blockIdx.x, i = blockIdx.y, tid = threadIdx.x;
  int k = tid * 4, h = tid >> 4;
  int L = c_nvec[i], p0 = c_poff[i];
  float4 o = ((const float4*)(b_in + ((size_t)i * 3 + 2) * Dm))[tid];
  #pragma unroll
  for (int l = 0; l < 4; l++) if (l < L) {
    float a = g_A[(((size_t)i * 4 + l) * Bq + b) * 16 + h];
    float4 vv = *(const float4*)(g_V + ((size_t)(p0 + l) * Bq + b) * Dm + k);
    o.x += a * vv.x; o.y += a * vv.y; o.z += a * vv.z; o.w += a * vv.w;
  }
  float mx = fmaxf(fmaxf(fabsf(o.x), fabsf(o.y)), fmaxf(fabsf(o.z), fabsf(o.w)));
  mx = fmaxf(blockmax(mx, sm, tid), 1e-20f);
  float inv = 127.f / mx;
  char4 d0, d1;
  quant1(o.x, inv, d0.x, d1.x); quant1(o.y, inv, d0.y, d1.y);
  quant1(o.z, inv, d0.z, d1.z); quant1(o.w, inv, d0.w, d1.w);
  size_t off = (size_t)i * BD + toff8(b, k, Bq);
  *(char4*)(g_O0 + off) = d0;
  *(char4*)(g_O1 + off) = d1;
  if (tid == 0) g_sO[i * Bq + b] = mx / 127.f;
}

// ======================= int8 digit GEMM =======================
// C[m,n] = sa[m]*sb[n]*(D0E0 + (D0E1 + D1E0)/254)
// CTA 128x128, 8 warps (2m x 4n) of 64x32, K-chunk 32, 6-stage bulk pipeline.
// Stage: A0 4K | A1 4K | B0 4K | B1 4K = 16KB.
#define NCH 32
#define STAGE 16384
#define NSTG 6
#define SMEM_SZ (1024 + NSTG * STAGE)

template<int MODE>
__global__ void __launch_bounds__(256, 1) k_i8(const float* __restrict__ b_out,
                                               float* __restrict__ dout) {
  extern __shared__ __align__(128) char smem[];
  const uint32_t sb = smem_u32(smem);
  const int tid = threadIdx.x;
  const int wid = tid >> 5, lane = tid & 31;
  const int m0 = blockIdx.x * 128, n0 = blockIdx.y * 128;
  const int wm = (wid & 1) * 64, wn = (wid >> 1) * 32;
  const int cst = (MODE == 2) ? 256 : 1024;
  const int RB  = (MODE == 2) ? 256 : 1024;

  const int8_t *A0, *A1, *B0, *B1;
  const float *sa, *sbn;
  float* C; const float* bias = nullptr;
  if (MODE == 0) {
    int p = blockIdx.z;
    int v = c_pairv[p], wi = c_pairi[p];
    A0 = g_A0 + (size_t)v * BD;  A1 = g_A1 + (size_t)v * BD;
    B0 = g_W0 + (size_t)wi * DD; B1 = g_W1 + (size_t)wi * DD;
    sa = g_sA + v * Bq; sbn = g_sW + wi * Dm;
    C = g_V + (size_t)p * BD;
  } else if (MODE == 1) {
    int i = blockIdx.z;
    A0 = g_O0 + (size_t)i * BD;  A1 = g_O1 + (size_t)i * BD;
    B0 = g_W0 + (size_t)(7 + i) * DD; B1 = g_W1 + (size_t)(7 + i) * DD;
    sa = g_sO + i * Bq; sbn = g_sW + (7 + i) * Dm;
    C = dout + (size_t)i * BD;
    bias = b_out + i * Dm;
  } else {
    int v = blockIdx.z;
    A0 = g_A0 + (size_t)v * BD;  A1 = g_A1 + (size_t)v * BD;
    B0 = g_S0; B1 = g_S1;
    sa = g_sA + v * Bq; sbn = g_sS;
    C = g_SC + (size_t)v * Bq * 256;
  }

  if (tid == 0) {
    #pragma unroll
    for (int s = 0; s < NSTG; s++) MBAR_INIT(sb + s * 8, 1);
  }
  __syncthreads();

  auto issue = [&](int c) {
    int s = c % NSTG;
    uint32_t st = sb + 1024 + s * STAGE;
    uint32_t mb = sb + s * 8;
    MBAR_EXPECT(mb, STAGE);
    bulk_g2s(st,         A0 + ((size_t)c * Bq + m0) * 32, 4096, mb);
    bulk_g2s(st + 4096,  A1 + ((size_t)c * Bq + m0) * 32, 4096, mb);
    bulk_g2s(st + 8192,  B0 + ((size_t)c * RB + n0) * 32, 4096, mb);
    bulk_g2s(st + 12288, B1 + ((size_t)c * RB + n0) * 32, 4096, mb);
  };
  if (tid == 0) {
    #pragma unroll
    for (int c = 0; c < NSTG; c++) issue(c);
  }

  int32_t acc0[4][4][4], acc1[4][4][4];
  #pragma unroll
  for (int mt = 0; mt < 4; mt++)
    #pragma unroll
    for (int nt = 0; nt < 4; nt++)
      #pragma unroll
      for (int r = 0; r < 4; r++) { acc0[mt][nt][r] = 0; acc1[mt][nt][r] = 0; }

  const int arow0 = wm + (lane & 15);
  const int agsel = lane >> 4;
  const int brow0 = wn + ((lane & 7) | ((lane & 16) >> 1));
  const int bgsel = (lane >> 3) & 1;

  for (int c = 0; c < NCH; c++) {
    const int s = c % NSTG;
    const uint32_t st = sb + 1024 + s * STAGE;
    MBAR_WAIT(sb + s * 8, (c / NSTG) & 1);

    uint32_t ad0[4][4], ad1[4][4], be0[4][2], be1[4][2];
    #pragma unroll
    for (int mt = 0; mt < 4; mt++) {
      int row = arow0 + mt * 16;
      uint32_t off = row * 32 + ((agsel ^ ((row >> 2) & 1)) << 4);
      ldsm4(ad0[mt][0], ad0[mt][1], ad0[mt][2], ad0[mt][3], st + off);
      ldsm4(ad1[mt][0], ad1[mt][1], ad1[mt][2], ad1[mt][3], st + 4096 + off);
    }
    #pragma unroll
    for (int np = 0; np < 2; np++) {
      int row = brow0 + np * 16;
      uint32_t off = row * 32 + ((bgsel ^ ((row >> 2) & 1)) << 4);
      ldsm4(be0[np*2][0], be0[np*2][1], be0[np*2+1][0], be0[np*2+1][1], st + 8192 + off);
      ldsm4(be1[np*2][0], be1[np*2][1], be1[np*2+1][0], be1[np*2+1][1], st + 12288 + off);
    }
    #pragma unroll
    for (int mt = 0; mt < 4; mt++)
      #pragma unroll
      for (int nt = 0; nt < 4; nt++) {
        mma_s8(acc0[mt][nt], ad0[mt], be0[nt]);
        mma_s8(acc1[mt][nt], ad0[mt], be1[nt]);
        mma_s8(acc1[mt][nt], ad1[mt], be0[nt]);
      }
    __syncthreads();
    if (tid == 0 && c + NSTG < NCH) issue(c + NSTG);
  }

  // epilogue: C = sa*sb*(acc0 + acc1/254) (+bias)
  #pragma unroll
  for (int mt = 0; mt < 4; mt++) {
    int m = m0 + wm + mt * 16 + (lane >> 2);
    float sa0 = __ldg(sa + m), sa1 = __ldg(sa + m + 8);
    #pragma unroll
    for (int nt = 0; nt < 4; nt++) {
      int n = n0 + wn + nt * 8 + (lane & 3) * 2;
      float sb0 = __ldg(sbn + n), sb1 = __ldg(sbn + n + 1);
      float f0 = (float)acc0[mt][nt][0] + (float)acc1[mt][nt][0] * (1.f/254.f);
      float f1 = (float)acc0[mt][nt][1] + (float)acc1[mt][nt][1] * (1.f/254.f);
      float f2 = (float)acc0[mt][nt][2] + (float)acc1[mt][nt][2] * (1.f/254.f);
      float f3 = (float)acc0[mt][nt][3] + (float)acc1[mt][nt][3] * (1.f/254.f);
      float2 v0 = make_float2(sa0 * sb0 * f0, sa0 * sb1 * f1);
      float2 v1 = make_float2(sa1 * sb0 * f2, sa1 * sb1 * f3);
      if (MODE == 1) {
        float b0 = __ldg(bias + n), b1 = __ldg(bias + n + 1);
        v0.x += b0; v0.y += b1; v1.x += b0; v1.y += b1;
      }
      *(float2*)(C + (size_t)m * cst + n) = v0;
      *(float2*)(C + (size_t)(m + 8) * cst + n) = v1;
    }
  }
}

// ======================================================================
extern "C" void kernel_launch(void* const* d_in, const int* in_sizes, int n_in,
                              void* d_out, int out_size) {
  const float* xc     = (const float*)d_in[0];
  const float* xf     = (const float*)d_in[1];
  const float* xbd    = (const float*)d_in[2];
  const float* xbg    = (const float*)d_in[3];
  const float* tokens = (const float*)d_in[4];
  const float* w_in   = (const float*)d_in[5];
  const float* b_in   = (const float*)d_in[6];
  const float* w_out  = (const float*)d_in[7];
  const float* b_out  = (const float*)d_in[8];
  float* out = (float*)d_out;

  cudaFuncSetAttribute(k_i8<0>, cudaFuncAttributeMaxDynamicSharedMemorySize, SMEM_SZ);
  cudaFuncSetAttribute(k_i8<1>, cudaFuncAttributeMaxDynamicSharedMemorySize, SMEM_SZ);
  cudaFuncSetAttribute(k_i8<2>, cudaFuncAttributeMaxDynamicSharedMemorySize, SMEM_SZ);

  k_quantA<<<dim3(Bq, 4), 256>>>(xc, xf, xbd, xbg);                    // 0
  k_quantW<<<dim3(Dm, 14), 256>>>(w_in, w_out);                        // 1
  k_qh<<<NBR, 256>>>(tokens, w_in, b_in);                              // 2
  k_i8<0><<<dim3(Bq/128, Dm/128, 19), 256, SMEM_SZ>>>(b_out, out);     // 3 <- ncu slot
  k_zq<<<256, 256>>>();                                                // 4
  k_sq<<<112, 256>>>(w_in);                                            // 5
  k_i8<2><<<dim3(Bq/128, 2, 4), 256, SMEM_SZ>>>(b_out, out);           // 6
  k_softmax<<<NBR * Bq * 16 / 256, 256>>>();                           // 7
  k_mixq<<<dim3(Bq, NBR), 256>>>(b_in);                                // 8
  k_i8<1><<<dim3(Bq/128, Dm/128, NBR), 256, SMEM_SZ>>>(b_out, out);    // 9
}

// round 8
// speedup vs baseline: 3.9864x; 3.9864x over previous
#include <cuda_runtime.h>
#include <cuda_fp16.h>
#include <cstdint>

#define Bq 8192
#define Dm 1024
#define NBR 7
#define BD ((size_t)Bq * Dm)
#define DD ((size_t)Dm * Dm)

// ---------------- scratch (tiled, pre-swizzled fp16 planes: [kc][rows][32]) ----------------
__device__ float g_Q[NBR * Dm];
__device__ float g_SC[(size_t)4 * Bq * 256];
__device__ float g_A[(size_t)NBR * 4 * Bq * 16];
__device__ float g_V[(size_t)19 * BD];
__device__ __align__(16) __half g_Sh[256 * Dm];
__device__ __align__(16) __half g_Sl[256 * Dm];
__device__ __align__(16) __half g_Ah[4 * BD];
__device__ __align__(16) __half g_Al[4 * BD];
__device__ __align__(16) __half g_Wh[14 * DD];            // weights: single plane
__device__ __align__(16) __half g_Oh[NBR * BD];
__device__ __align__(16) __half g_Ol[NBR * BD];

__constant__ int c_nvec[NBR] = {2,2,2,3,3,3,4};
__constant__ int c_vidx[NBR][4] = {{0,1,0,0},{0,2,0,0},{0,3,0,0},{0,1,2,0},{0,1,3,0},{0,2,3,0},{0,1,2,3}};
__constant__ int c_poff[NBR] = {0,2,4,6,9,12,15};
__constant__ int c_pairi[19] = {0,0,1,1,2,2,3,3,3,4,4,4,5,5,5,6,6,6,6};
__constant__ int c_pairv[19] = {0,1,0,2,0,3,0,1,2,0,1,3,0,2,3,0,1,2,3};

// tiled+swizzled element offset within a [R rows x 1024 k] fp16 plane
__device__ __forceinline__ size_t toff(int row, int k, int R) {
  return ((size_t)(k >> 5) * R + row) * 32 +
         (((((k >> 3) & 3) ^ ((row >> 1) & 3)) << 3) + (k & 7));
}

// ---------------- PTX helpers ----------------
__device__ __forceinline__ uint32_t smem_u32(const void* p) {
  uint32_t a;
  asm("{ .reg .u64 t; cvta.to.shared.u64 t, %1; cvt.u32.u64 %0, t; }" : "=r"(a) : "l"(p));
  return a;
}
#define MBAR_INIT(a, n) asm volatile("mbarrier.init.shared.b64 [%0], %1;" :: "r"(a), "r"(n) : "memory")
#define MBAR_EXPECT(a, b) asm volatile("mbarrier.arrive.expect_tx.shared.b64 _, [%0], %1;" :: "r"(a), "r"(b) : "memory")
#define MBAR_WAIT(a, ph) do { \
  uint32_t _m = (a), _p = (ph), _d; \
  asm volatile("{ .reg .pred p; mbarrier.try_wait.parity.acquire.cta.shared::cta.b64 p, [%1], %2; selp.b32 %0,1,0,p; }" \
    : "=r"(_d) : "r"(_m), "r"(_p) : "memory"); \
  if (!_d) { asm volatile("{ .reg .pred P1; WL_%=: mbarrier.try_wait.parity.acquire.cta.shared::cta.b64 P1, [%0], %1, 0x989680; @P1 bra.uni WD_%=; bra.uni WL_%=; WD_%=: }" \
    :: "r"(_m), "r"(_p) : "memory"); } } while (0)

__device__ __forceinline__ void bulk_g2s(uint32_t dst, const void* src, uint32_t bytes, uint32_t mbar) {
  asm volatile("cp.async.bulk.shared::cluster.global.mbarrier::complete_tx::bytes [%0], [%1], %2, [%3];"
               :: "r"(dst), "l"(src), "r"(bytes), "r"(mbar) : "memory");
}
__device__ __forceinline__ void ldsm4(uint32_t& r0, uint32_t& r1, uint32_t& r2, uint32_t& r3, uint32_t addr) {
  asm volatile("ldmatrix.sync.aligned.m8n8.x4.shared.b16 {%0,%1,%2,%3}, [%4];"
               : "=r"(r0), "=r"(r1), "=r"(r2), "=r"(r3) : "r"(addr));
}
__device__ __forceinline__ void mma_f16(float* c, const uint32_t* a, const uint32_t* b) {
  asm volatile("mma.sync.aligned.m16n8k16.row.col.f32.f16.f16.f32 "
               "{%0,%1,%2,%3}, {%4,%5,%6,%7}, {%8,%9}, {%0,%1,%2,%3};"
               : "+f"(c[0]), "+f"(c[1]), "+f"(c[2]), "+f"(c[3])
               : "r"(a[0]), "r"(a[1]), "r"(a[2]), "r"(a[3]), "r"(b[0]), "r"(b[1]));
}

// ======================= fp32 -> fp16 hi/lo split =======================
__device__ __forceinline__ void split4h(float4 v, uint2& hi, uint2& lo) {
  __half h0 = __float2half_rn(v.x), h1 = __float2half_rn(v.y);
  __half h2 = __float2half_rn(v.z), h3 = __float2half_rn(v.w);
  __half l0 = __float2half_rn(v.x - __half2float(h0));
  __half l1 = __float2half_rn(v.y - __half2float(h1));
  __half l2 = __float2half_rn(v.z - __half2float(h2));
  __half l3 = __float2half_rn(v.w - __half2float(h3));
  __half2 a{h0, h1}, b{h2, h3}, c{l0, l1}, d{l2, l3};
  hi = make_uint2(*(uint32_t*)&a, *(uint32_t*)&b);
  lo = make_uint2(*(uint32_t*)&c, *(uint32_t*)&d);
}
__device__ __forceinline__ uint2 pack4h(float4 v) {
  __half2 a{__float2half_rn(v.x), __float2half_rn(v.y)};
  __half2 b{__float2half_rn(v.z), __float2half_rn(v.w)};
  return make_uint2(*(uint32_t*)&a, *(uint32_t*)&b);
}

// ======================= prep / conversion kernels =======================
__global__ void k_qh(const float* __restrict__ tokens, const float* __restrict__ w_in,
                     const float* __restrict__ b_in) {
  int i = blockIdx.x, t = threadIdx.x;
  __shared__ float tok[Dm];
  for (int k = t; k < Dm; k += 256) tok[k] = tokens[i * Dm + k];
  __syncthreads();
  const float* wq = w_in + (size_t)i * 3 * DD;
  for (int r = t; r < Dm; r += 256) {
    const float* row = wq + (size_t)r * Dm;
    float acc = b_in[i * 3 * Dm + r];
    for (int k = 0; k < Dm; k += 4) {
      float4 w = *(const float4*)(row + k);
      acc += w.x*tok[k] + w.y*tok[k+1] + w.z*tok[k+2] + w.w*tok[k+3];
    }
    g_Q[i * Dm + r] = acc;
  }
}

__global__ void k_zs() {   // zero score planes (zeros are swizzle-invariant)
  size_t i = ((size_t)blockIdx.x * 256 + threadIdx.x) * 4;
  *(uint2*)(g_Sh + i) = make_uint2(0, 0);
  *(uint2*)(g_Sl + i) = make_uint2(0, 0);
}

__global__ void k_s(const float* __restrict__ w_in) {
  int i = blockIdx.x, kb = blockIdx.y * 128;
  __shared__ float qh[Dm];
  for (int k = threadIdx.x; k < Dm; k += 256) qh[k] = g_Q[i * Dm + k];
  __syncthreads();
  const float* wk = w_in + (size_t)i * 3 * DD + DD;
  for (int o = threadIdx.x; o < 16 * 128; o += 256) {
    int h = o >> 7, k = kb + (o & 127);
    float acc = 0.f;
    #pragma unroll 8
    for (int j = 0; j < 64; j++) acc += wk[(size_t)(h * 64 + j) * Dm + k] * qh[h * 64 + j];
    float val = 0.125f * acc;
    __half hi = __float2half_rn(val);
    size_t off = toff(i * 16 + h, k, 256);
    g_Sh[off] = hi;
    g_Sl[off] = __float2half_rn(val - __half2float(hi));
  }
}

__global__ void k_softmax() {
  int idx = blockIdx.x * 256 + threadIdx.x;
  int h = idx & 15;
  int b = (idx >> 4) & (Bq - 1);
  int i = idx >> 17;
  int L = c_nvec[i];
  float sc[4];
  float mx = -1e30f;
  #pragma unroll
  for (int l = 0; l < 4; l++) if (l < L) {
    sc[l] = g_SC[((size_t)c_vidx[i][l] * Bq + b) * 256 + i * 16 + h];
    mx = fmaxf(mx, sc[l]);
  }
  float sum = 0.f;
  #pragma unroll
  for (int l = 0; l < 4; l++) if (l < L) { sc[l] = expf(sc[l] - mx); sum += sc[l]; }
  float inv = 1.f / sum;
  #pragma unroll
  for (int l = 0; l < 4; l++) if (l < L)
    g_A[(((size_t)i * 4 + l) * Bq + b) * 16 + h] = sc[l] * inv;
}

__global__ void k_mix(const float* __restrict__ b_in) {
  size_t gid = (size_t)blockIdx.x * 256 + threadIdx.x;
  int i = (int)(gid >> 21);
  int rem = (int)(gid & ((1u << 21) - 1));
  int b = rem >> 8;
  int k = (rem & 255) * 4;
  int h = k >> 6;
  int L = c_nvec[i];
  int p0 = c_poff[i];
  float4 o = *(const float4*)(b_in + ((size_t)i * 3 + 2) * Dm + k);
  #pragma unroll
  for (int l = 0; l < 4; l++) if (l < L) {
    float a = g_A[(((size_t)i * 4 + l) * Bq + b) * 16 + h];
    float4 vv = *(const float4*)(g_V + ((size_t)(p0 + l) * Bq + b) * Dm + k);
    o.x += a * vv.x; o.y += a * vv.y; o.z += a * vv.z; o.w += a * vv.w;
  }
  uint2 hi, lo; split4h(o, hi, lo);
  size_t off = (size_t)i * BD + toff(b, k, Bq);
  *(uint2*)(g_Oh + off) = hi;
  *(uint2*)(g_Ol + off) = lo;
}

__global__ void k_convA(const float* __restrict__ xc, const float* __restrict__ xf,
                        const float* __restrict__ xbd, const float* __restrict__ xbg) {
  int v = blockIdx.y;
  const float* x = (v == 0) ? xc : (v == 1) ? xf : (v == 2) ? xbd : xbg;
  size_t i = (size_t)blockIdx.x * 256 + threadIdx.x;
  int m = (int)(i >> 8), k = ((int)i & 255) * 4;
  float4 val = ((const float4*)x)[i];
  uint2 hi, lo; split4h(val, hi, lo);
  size_t off = (size_t)v * BD + toff(m, k, Bq);
  *(uint2*)(g_Ah + off) = hi;
  *(uint2*)(g_Al + off) = lo;
}

__global__ void k_convW(const float* __restrict__ w_in, const float* __restrict__ w_out) {
  int z = blockIdx.y;
  const float* src = (z < 7) ? (w_in + (size_t)z * 3 * DD + 2 * DD) : (w_out + (size_t)(z - 7) * DD);
  size_t i = (size_t)blockIdx.x * 256 + threadIdx.x;
  int n = (int)(i >> 8), k = ((int)i & 255) * 4;
  float4 val = ((const float4*)src)[i];
  *(uint2*)(g_Wh + (size_t)z * DD + toff(n, k, Dm)) = pack4h(val);
}

// ======================= bulk-copy fp16 HMMA GEMM =======================
// MODE 0/1: CTA 128x256, B single plane, 2 terms (Ah*Bh + Al*Bh). Stage 32KB:
//   Ah 8K | Al 8K | Bh 16K.
// MODE 2 (scores): CTA 128x128, B = S 2 planes, 3 terms. Stage 32KB:
//   Ah 8K | Al 8K | Bh 8K | Bl 8K.
#define NCH 32
#define STAGE 32768
#define NSTG 5
#define SMEM_SZ (1024 + NSTG * STAGE)

__device__ __forceinline__ uint32_t sw(uint32_t row, uint32_t g) {
  return row * 64 + ((g ^ ((row >> 1) & 3)) << 4);
}

template<int MODE>
__global__ void __launch_bounds__(256, 1) k_mma(const float* __restrict__ b_out,
                                                float* __restrict__ dout) {
  extern __shared__ __align__(128) char smem[];
  const uint32_t sb = smem_u32(smem);
  const int tid = threadIdx.x;
  const int wid = tid >> 5, lane = tid & 31;
  constexpr int NT = (MODE == 2) ? 4 : 8;        // 8-col n-tiles per warp
  const int m0 = blockIdx.x * 128;
  const int n0 = blockIdx.y * ((MODE == 2) ? 128 : 256);
  const int wm = (wid & 1) * 64, wn = (wid >> 1) * (NT * 8);
  const int cst = (MODE == 2) ? 256 : 1024;
  const int RB  = (MODE == 2) ? 256 : 1024;      // B plane rows per k-chunk

  const __half *Ah, *Al, *Bh, *Bl = nullptr;
  float* C; const float* bias = nullptr;
  if (MODE == 0) {
    int p = blockIdx.z;
    int v = c_pairv[p], wi = c_pairi[p];
    Ah = g_Ah + (size_t)v * BD;  Al = g_Al + (size_t)v * BD;
    Bh = g_Wh + (size_t)wi * DD;
    C = g_V + (size_t)p * BD;
  } else if (MODE == 1) {
    int i = blockIdx.z;
    Ah = g_Oh + (size_t)i * BD;  Al = g_Ol + (size_t)i * BD;
    Bh = g_Wh + (size_t)(7 + i) * DD;
    C = dout + (size_t)i * BD;
    bias = b_out + i * Dm;
  } else {
    int v = blockIdx.z;
    Ah = g_Ah + (size_t)v * BD;  Al = g_Al + (size_t)v * BD;
    Bh = g_Sh; Bl = g_Sl;
    C = g_SC + (size_t)v * Bq * 256;
  }

  if (tid == 0) {
    #pragma unroll
    for (int s = 0; s < NSTG; s++) MBAR_INIT(sb + s * 8, 1);
  }
  __syncthreads();

  auto issue = [&](int c) {
    int s = c % NSTG;
    uint32_t st = sb + 1024 + s * STAGE;
    uint32_t mb = sb + s * 8;
    MBAR_EXPECT(mb, STAGE);
    bulk_g2s(st,        Ah + ((size_t)c * Bq + m0) * 32, 8192, mb);
    bulk_g2s(st + 8192, Al + ((size_t)c * Bq + m0) * 32, 8192, mb);
    if (MODE == 2) {
      bulk_g2s(st + 16384, Bh + ((size_t)c * RB + n0) * 32, 8192, mb);
      bulk_g2s(st + 24576, Bl + ((size_t)c * RB + n0) * 32, 8192, mb);
    } else {
      bulk_g2s(st + 16384, Bh + ((size_t)c * RB + n0) * 32, 16384, mb);
    }
  };
  if (tid == 0) {
    #pragma unroll
    for (int c = 0; c < NSTG; c++) issue(c);
  }

  float acc[4][NT][4];
  #pragma unroll
  for (int mt = 0; mt < 4; mt++)
    #pragma unroll
    for (int nt = 0; nt < NT; nt++)
      #pragma unroll
      for (int r = 0; r < 4; r++) acc[mt][nt][r] = 0.f;

  const int arow = wm + (lane & 15);
  const int agsel = lane >> 4;
  const int brow = wn + ((lane & 7) | ((lane & 16) >> 1));
  const int bgsel = (lane >> 3) & 1;

  for (int c = 0; c < NCH; c++) {
    const int s = c % NSTG;
    const uint32_t st = sb + 1024 + s * STAGE;
    MBAR_WAIT(sb + s * 8, (c / NSTG) & 1);
    #pragma unroll
    for (int ks = 0; ks < 2; ks++) {
      uint32_t ah[4][4], al[4][4], bh[NT][2];
      #pragma unroll
      for (int mt = 0; mt < 4; mt++) {
        uint32_t ad = st + sw(arow + mt * 16, ks * 2 + agsel);
        ldsm4(ah[mt][0], ah[mt][1], ah[mt][2], ah[mt][3], ad);
        ldsm4(al[mt][0], al[mt][1], al[mt][2], al[mt][3], ad + 8192);
      }
      #pragma unroll
      for (int np = 0; np < NT / 2; np++) {
        uint32_t bd = st + 16384 + sw(brow + np * 16, ks * 2 + bgsel);
        ldsm4(bh[np*2][0], bh[np*2][1], bh[np*2+1][0], bh[np*2+1][1], bd);
      }
      #pragma unroll
      for (int mt = 0; mt < 4; mt++)
        #pragma unroll
        for (int nt = 0; nt < NT; nt++) {
          mma_f16(acc[mt][nt], ah[mt], bh[nt]);
          mma_f16(acc[mt][nt], al[mt], bh[nt]);
        }
      if (MODE == 2) {
        uint32_t bl[NT][2];
        #pragma unroll
        for (int np = 0; np < NT / 2; np++) {
          uint32_t bd = st + 24576 + sw(brow + np * 16, ks * 2 + bgsel);
          ldsm4(bl[np*2][0], bl[np*2][1], bl[np*2+1][0], bl[np*2+1][1], bd);
        }
        #pragma unroll
        for (int mt = 0; mt < 4; mt++)
          #pragma unroll
          for (int nt = 0; nt < NT; nt++)
            mma_f16(acc[mt][nt], ah[mt], bl[nt]);
      }
    }
    __syncthreads();
    if (tid == 0 && c + NSTG < NCH) issue(c + NSTG);
  }

  // epilogue
  #pragma unroll
  for (int mt = 0; mt < 4; mt++) {
    int m = m0 + wm + mt * 16 + (lane >> 2);
    #pragma unroll
    for (int nt = 0; nt < NT; nt++) {
      int n = n0 + wn + nt * 8 + (lane & 3) * 2;
      float2 v0 = make_float2(acc[mt][nt][0], acc[mt][nt][1]);
      float2 v1 = make_float2(acc[mt][nt][2], acc[mt][nt][3]);
      if (MODE == 1) {
        float b0 = __ldg(bias + n), b1 = __ldg(bias + n + 1);
        v0.x += b0; v0.y += b1; v1.x += b0; v1.y += b1;
      }
      *(float2*)(C + (size_t)m * cst + n) = v0;
      *(float2*)(C + (size_t)(m + 8) * cst + n) = v1;
    }
  }
}

// ======================================================================
extern "C" void kernel_launch(void* const* d_in, const int* in_sizes, int n_in,
                              void* d_out, int out_size) {
  const float* xc     = (const float*)d_in[0];
  const float* xf     = (const float*)d_in[1];
  const float* xbd    = (const float*)d_in[2];
  const float* xbg    = (const float*)d_in[3];
  const float* tokens = (const float*)d_in[4];
  const float* w_in   = (const float*)d_in[5];
  const float* b_in   = (const float*)d_in[6];
  const float* w_out  = (const float*)d_in[7];
  const float* b_out  = (const float*)d_in[8];
  float* out = (float*)d_out;

  cudaFuncSetAttribute(k_mma<0>, cudaFuncAttributeMaxDynamicSharedMemorySize, SMEM_SZ);
  cudaFuncSetAttribute(k_mma<1>, cudaFuncAttributeMaxDynamicSharedMemorySize, SMEM_SZ);
  cudaFuncSetAttribute(k_mma<2>, cudaFuncAttributeMaxDynamicSharedMemorySize, SMEM_SZ);

  k_convA<<<dim3(Bq, 4), 256>>>(xc, xf, xbd, xbg);                     // 0
  k_convW<<<dim3(1024, 14), 256>>>(w_in, w_out);                       // 1
  k_qh<<<NBR, 256>>>(tokens, w_in, b_in);                              // 2
  k_mma<0><<<dim3(Bq/128, Dm/256, 19), 256, SMEM_SZ>>>(b_out, out);    // 3 <- ncu slot
  k_zs<<<256, 256>>>();                                                // 4
  k_s<<<dim3(NBR, 8), 256>>>(w_in);                                    // 5
  k_mma<2><<<dim3(Bq/128, 2, 4), 256, SMEM_SZ>>>(b_out, out);          // 6
  k_softmax<<<NBR * Bq * 16 / 256, 256>>>();                           // 7
  k_mix<<<NBR * Bq * (Dm / 4) / 256, 256>>>(b_in);                     // 8
  k_mma<1><<<dim3(Bq/128, Dm/256, NBR), 256, SMEM_SZ>>>(b_out, out);   // 9
}

// round 9
// speedup vs baseline: 5.2992x; 1.3293x over previous
#include <cuda_runtime.h>
#include <cuda_fp16.h>
#include <cstdint>

#define Bq 8192
#define Dm 1024
#define NBR 7
#define BD ((size_t)Bq * Dm)
#define DD ((size_t)Dm * Dm)

// ---------------- scratch (tiled, pre-swizzled fp16 planes: [kc][rows][32]) ----------------
__device__ float g_Q[NBR * Dm];
__device__ float g_SC[(size_t)4 * Bq * 256];
__device__ float g_A[(size_t)NBR * 4 * Bq * 16];
__device__ __align__(16) __half g_V[(size_t)19 * BD];     // v-proj results, fp16
__device__ __align__(16) __half g_Sh[256 * Dm];
__device__ __align__(16) __half g_Sl[256 * Dm];
__device__ __align__(16) __half g_Ah[4 * BD];
__device__ __align__(16) __half g_Al[4 * BD];
__device__ __align__(16) __half g_Wh[14 * DD];            // weights: single plane
__device__ __align__(16) __half g_Oh[NBR * BD];
__device__ __align__(16) __half g_Ol[NBR * BD];

__constant__ int c_nvec[NBR] = {2,2,2,3,3,3,4};
__constant__ int c_vidx[NBR][4] = {{0,1,0,0},{0,2,0,0},{0,3,0,0},{0,1,2,0},{0,1,3,0},{0,2,3,0},{0,1,2,3}};
__constant__ int c_poff[NBR] = {0,2,4,6,9,12,15};
__constant__ int c_pairi[19] = {0,0,1,1,2,2,3,3,3,4,4,4,5,5,5,6,6,6,6};
__constant__ int c_pairv[19] = {0,1,0,2,0,3,0,1,2,0,1,3,0,2,3,0,1,2,3};

// tiled+swizzled element offset within a [R rows x 1024 k] fp16 plane
__device__ __forceinline__ size_t toff(int row, int k, int R) {
  return ((size_t)(k >> 5) * R + row) * 32 +
         (((((k >> 3) & 3) ^ ((row >> 1) & 3)) << 3) + (k & 7));
}

// ---------------- PTX helpers ----------------
__device__ __forceinline__ uint32_t smem_u32(const void* p) {
  uint32_t a;
  asm("{ .reg .u64 t; cvta.to.shared.u64 t, %1; cvt.u32.u64 %0, t; }" : "=r"(a) : "l"(p));
  return a;
}
#define MBAR_INIT(a, n) asm volatile("mbarrier.init.shared.b64 [%0], %1;" :: "r"(a), "r"(n) : "memory")
#define MBAR_EXPECT(a, b) asm volatile("mbarrier.arrive.expect_tx.shared.b64 _, [%0], %1;" :: "r"(a), "r"(b) : "memory")
#define MBAR_WAIT(a, ph) do { \
  uint32_t _m = (a), _p = (ph), _d; \
  asm volatile("{ .reg .pred p; mbarrier.try_wait.parity.acquire.cta.shared::cta.b64 p, [%1], %2; selp.b32 %0,1,0,p; }" \
    : "=r"(_d) : "r"(_m), "r"(_p) : "memory"); \
  if (!_d) { asm volatile("{ .reg .pred P1; WL_%=: mbarrier.try_wait.parity.acquire.cta.shared::cta.b64 P1, [%0], %1, 0x989680; @P1 bra.uni WD_%=; bra.uni WL_%=; WD_%=: }" \
    :: "r"(_m), "r"(_p) : "memory"); } } while (0)

__device__ __forceinline__ void bulk_g2s(uint32_t dst, const void* src, uint32_t bytes, uint32_t mbar) {
  asm volatile("cp.async.bulk.shared::cluster.global.mbarrier::complete_tx::bytes [%0], [%1], %2, [%3];"
               :: "r"(dst), "l"(src), "r"(bytes), "r"(mbar) : "memory");
}
__device__ __forceinline__ void ldsm4(uint32_t& r0, uint32_t& r1, uint32_t& r2, uint32_t& r3, uint32_t addr) {
  asm volatile("ldmatrix.sync.aligned.m8n8.x4.shared.b16 {%0,%1,%2,%3}, [%4];"
               : "=r"(r0), "=r"(r1), "=r"(r2), "=r"(r3) : "r"(addr));
}
__device__ __forceinline__ void mma_f16(float* c, const uint32_t* a, const uint32_t* b) {
  asm volatile("mma.sync.aligned.m16n8k16.row.col.f32.f16.f16.f32 "
               "{%0,%1,%2,%3}, {%4,%5,%6,%7}, {%8,%9}, {%0,%1,%2,%3};"
               : "+f"(c[0]), "+f"(c[1]), "+f"(c[2]), "+f"(c[3])
               : "r"(a[0]), "r"(a[1]), "r"(a[2]), "r"(a[3]), "r"(b[0]), "r"(b[1]));
}

// ======================= fp32 -> fp16 split/pack =======================
__device__ __forceinline__ void split4h(float4 v, uint2& hi, uint2& lo) {
  __half h0 = __float2half_rn(v.x), h1 = __float2half_rn(v.y);
  __half h2 = __float2half_rn(v.z), h3 = __float2half_rn(v.w);
  __half l0 = __float2half_rn(v.x - __half2float(h0));
  __half l1 = __float2half_rn(v.y - __half2float(h1));
  __half l2 = __float2half_rn(v.z - __half2float(h2));
  __half l3 = __float2half_rn(v.w - __half2float(h3));
  __half2 a{h0, h1}, b{h2, h3}, c{l0, l1}, d{l2, l3};
  hi = make_uint2(*(uint32_t*)&a, *(uint32_t*)&b);
  lo = make_uint2(*(uint32_t*)&c, *(uint32_t*)&d);
}
__device__ __forceinline__ uint2 pack4h(float4 v) {
  __half2 a{__float2half_rn(v.x), __float2half_rn(v.y)};
  __half2 b{__float2half_rn(v.z), __float2half_rn(v.w)};
  return make_uint2(*(uint32_t*)&a, *(uint32_t*)&b);
}

// ======================= prep / conversion kernels =======================
__global__ void k_qh(const float* __restrict__ tokens, const float* __restrict__ w_in,
                     const float* __restrict__ b_in) {
  int i = blockIdx.x, t = threadIdx.x;
  __shared__ float tok[Dm];
  for (int k = t; k < Dm; k += 256) tok[k] = tokens[i * Dm + k];
  __syncthreads();
  const float* wq = w_in + (size_t)i * 3 * DD;
  for (int r = t; r < Dm; r += 256) {
    const float* row = wq + (size_t)r * Dm;
    float acc = b_in[i * 3 * Dm + r];
    for (int k = 0; k < Dm; k += 4) {
      float4 w = *(const float4*)(row + k);
      acc += w.x*tok[k] + w.y*tok[k+1] + w.z*tok[k+2] + w.w*tok[k+3];
    }
    g_Q[i * Dm + r] = acc;
  }
}

__global__ void k_zs() {
  size_t i = ((size_t)blockIdx.x * 256 + threadIdx.x) * 4;
  *(uint2*)(g_Sh + i) = make_uint2(0, 0);
  *(uint2*)(g_Sl + i) = make_uint2(0, 0);
}

__global__ void k_s(const float* __restrict__ w_in) {
  int i = blockIdx.x, kb = blockIdx.y * 128;
  __shared__ float qh[Dm];
  for (int k = threadIdx.x; k < Dm; k += 256) qh[k] = g_Q[i * Dm + k];
  __syncthreads();
  const float* wk = w_in + (size_t)i * 3 * DD + DD;
  for (int o = threadIdx.x; o < 16 * 128; o += 256) {
    int h = o >> 7, k = kb + (o & 127);
    float acc = 0.f;
    #pragma unroll 8
    for (int j = 0; j < 64; j++) acc += wk[(size_t)(h * 64 + j) * Dm + k] * qh[h * 64 + j];
    float val = 0.125f * acc;
    __half hi = __float2half_rn(val);
    size_t off = toff(i * 16 + h, k, 256);
    g_Sh[off] = hi;
    g_Sl[off] = __float2half_rn(val - __half2float(hi));
  }
}

__global__ void k_softmax() {
  int idx = blockIdx.x * 256 + threadIdx.x;
  int h = idx & 15;
  int b = (idx >> 4) & (Bq - 1);
  int i = idx >> 17;
  int L = c_nvec[i];
  float sc[4];
  float mx = -1e30f;
  #pragma unroll
  for (int l = 0; l < 4; l++) if (l < L) {
    sc[l] = g_SC[((size_t)c_vidx[i][l] * Bq + b) * 256 + i * 16 + h];
    mx = fmaxf(mx, sc[l]);
  }
  float sum = 0.f;
  #pragma unroll
  for (int l = 0; l < 4; l++) if (l < L) { sc[l] = expf(sc[l] - mx); sum += sc[l]; }
  float inv = 1.f / sum;
  #pragma unroll
  for (int l = 0; l < 4; l++) if (l < L)
    g_A[(((size_t)i * 4 + l) * Bq + b) * 16 + h] = sc[l] * inv;
}

__global__ void k_mix(const float* __restrict__ b_in) {
  size_t gid = (size_t)blockIdx.x * 256 + threadIdx.x;
  int i = (int)(gid >> 21);
  int rem = (int)(gid & ((1u << 21) - 1));
  int b = rem >> 8;
  int k = (rem & 255) * 4;
  int h = k >> 6;
  int L = c_nvec[i];
  int p0 = c_poff[i];
  float4 o = *(const float4*)(b_in + ((size_t)i * 3 + 2) * Dm + k);
  #pragma unroll
  for (int l = 0; l < 4; l++) if (l < L) {
    float a = g_A[(((size_t)i * 4 + l) * Bq + b) * 16 + h];
    const __half2* vp = (const __half2*)(g_V + ((size_t)(p0 + l) * Bq + b) * Dm + k);
    float2 f01 = __half22float2(vp[0]);
    float2 f23 = __half22float2(vp[1]);
    o.x += a * f01.x; o.y += a * f01.y; o.z += a * f23.x; o.w += a * f23.y;
  }
  uint2 hi, lo; split4h(o, hi, lo);
  size_t off = (size_t)i * BD + toff(b, k, Bq);
  *(uint2*)(g_Oh + off) = hi;
  *(uint2*)(g_Ol + off) = lo;
}

__global__ void k_convA(const float* __restrict__ xc, const float* __restrict__ xf,
                        const float* __restrict__ xbd, const float* __restrict__ xbg) {
  int v = blockIdx.y;
  const float* x = (v == 0) ? xc : (v == 1) ? xf : (v == 2) ? xbd : xbg;
  size_t i = (size_t)blockIdx.x * 256 + threadIdx.x;
  int m = (int)(i >> 8), k = ((int)i & 255) * 4;
  float4 val = ((const float4*)x)[i];
  uint2 hi, lo; split4h(val, hi, lo);
  size_t off = (size_t)v * BD + toff(m, k, Bq);
  *(uint2*)(g_Ah + off) = hi;
  *(uint2*)(g_Al + off) = lo;
}

__global__ void k_convW(const float* __restrict__ w_in, const float* __restrict__ w_out) {
  int z = blockIdx.y;
  const float* src = (z < 7) ? (w_in + (size_t)z * 3 * DD + 2 * DD) : (w_out + (size_t)(z - 7) * DD);
  size_t i = (size_t)blockIdx.x * 256 + threadIdx.x;
  int n = (int)(i >> 8), k = ((int)i & 255) * 4;
  float4 val = ((const float4*)src)[i];
  *(uint2*)(g_Wh + (size_t)z * DD + toff(n, k, Dm)) = pack4h(val);
}

// ======================= bulk-copy fp16 HMMA GEMM =======================
// MODE 0 (v-proj):  CTA 128x256, 1 term (Ah*Bh).  Stage 24KB: A 8K | B 16K. C fp16.
// MODE 1 (out):     CTA 128x256, 2 terms (Ah+Al)*Bh. Stage 32KB: Ah 8K | Al 8K | B 16K.
// MODE 2 (scores):  CTA 128x128, 3 terms. Stage 32KB: Ah | Al | Bh | Bl @ 8K each.
#define NCH 32

__device__ __forceinline__ uint32_t sw(uint32_t row, uint32_t g) {
  return row * 64 + ((g ^ ((row >> 1) & 3)) << 4);
}

template<int MODE>
__global__ void __launch_bounds__(256, 1) k_mma(const float* __restrict__ b_out,
                                                float* __restrict__ dout) {
  constexpr int STG  = (MODE == 0) ? 24576 : 32768;
  constexpr int NS   = (MODE == 0) ? 6 : 5;
  constexpr int NT   = (MODE == 2) ? 4 : 8;
  constexpr int BOFF = (MODE == 0) ? 8192 : 16384;
  extern __shared__ __align__(128) char smem[];
  const uint32_t sb = smem_u32(smem);
  const int tid = threadIdx.x;
  const int wid = tid >> 5, lane = tid & 31;
  const int m0 = blockIdx.x * 128;
  const int n0 = blockIdx.y * ((MODE == 2) ? 128 : 256);
  const int wm = (wid & 1) * 64, wn = (wid >> 1) * (NT * 8);
  const int cst = (MODE == 2) ? 256 : 1024;
  const int RB  = (MODE == 2) ? 256 : 1024;

  const __half *Ah, *Al = nullptr, *Bh, *Bl = nullptr;
  float* C = nullptr; __half* Ch = nullptr; const float* bias = nullptr;
  if (MODE == 0) {
    int p = blockIdx.z;
    int v = c_pairv[p], wi = c_pairi[p];
    Ah = g_Ah + (size_t)v * BD;
    Bh = g_Wh + (size_t)wi * DD;
    Ch = g_V + (size_t)p * BD;
  } else if (MODE == 1) {
    int i = blockIdx.z;
    Ah = g_Oh + (size_t)i * BD;  Al = g_Ol + (size_t)i * BD;
    Bh = g_Wh + (size_t)(7 + i) * DD;
    C = dout + (size_t)i * BD;
    bias = b_out + i * Dm;
  } else {
    int v = blockIdx.z;
    Ah = g_Ah + (size_t)v * BD;  Al = g_Al + (size_t)v * BD;
    Bh = g_Sh; Bl = g_Sl;
    C = g_SC + (size_t)v * Bq * 256;
  }

  if (tid == 0) {
    #pragma unroll
    for (int s = 0; s < NS; s++) MBAR_INIT(sb + s * 8, 1);
  }
  __syncthreads();

  auto issue = [&](int c) {
    int s = c % NS;
    uint32_t st = sb + 1024 + s * STG;
    uint32_t mb = sb + s * 8;
    MBAR_EXPECT(mb, STG);
    bulk_g2s(st, Ah + ((size_t)c * Bq + m0) * 32, 8192, mb);
    if (MODE != 0) bulk_g2s(st + 8192, Al + ((size_t)c * Bq + m0) * 32, 8192, mb);
    if (MODE == 2) {
      bulk_g2s(st + 16384, Bh + ((size_t)c * RB + n0) * 32, 8192, mb);
      bulk_g2s(st + 24576, Bl + ((size_t)c * RB + n0) * 32, 8192, mb);
    } else {
      bulk_g2s(st + BOFF, Bh + ((size_t)c * RB + n0) * 32, 16384, mb);
    }
  };
  if (tid == 0) {
    #pragma unroll
    for (int c = 0; c < NS; c++) issue(c);
  }

  float acc[4][NT][4];
  #pragma unroll
  for (int mt = 0; mt < 4; mt++)
    #pragma unroll
    for (int nt = 0; nt < NT; nt++)
      #pragma unroll
      for (int r = 0; r < 4; r++) acc[mt][nt][r] = 0.f;

  const int arow = wm + (lane & 15);
  const int agsel = lane >> 4;
  const int brow = wn + ((lane & 7) | ((lane & 16) >> 1));
  const int bgsel = (lane >> 3) & 1;

  for (int c = 0; c < NCH; c++) {
    const int s = c % NS;
    const uint32_t st = sb + 1024 + s * STG;
    MBAR_WAIT(sb + s * 8, (c / NS) & 1);
    #pragma unroll
    for (int ks = 0; ks < 2; ks++) {
      uint32_t ah[4][4], al[4][4], bh[NT][2];
      #pragma unroll
      for (int mt = 0; mt < 4; mt++) {
        uint32_t ad = st + sw(arow + mt * 16, ks * 2 + agsel);
        ldsm4(ah[mt][0], ah[mt][1], ah[mt][2], ah[mt][3], ad);
        if (MODE != 0) ldsm4(al[mt][0], al[mt][1], al[mt][2], al[mt][3], ad + 8192);
      }
      #pragma unroll
      for (int np = 0; np < NT / 2; np++) {
        uint32_t bd = st + BOFF + sw(brow + np * 16, ks * 2 + bgsel);
        ldsm4(bh[np*2][0], bh[np*2][1], bh[np*2+1][0], bh[np*2+1][1], bd);
      }
      #pragma unroll
      for (int mt = 0; mt < 4; mt++)
        #pragma unroll
        for (int nt = 0; nt < NT; nt++) {
          mma_f16(acc[mt][nt], ah[mt], bh[nt]);
          if (MODE != 0) mma_f16(acc[mt][nt], al[mt], bh[nt]);
        }
      if (MODE == 2) {
        uint32_t bl[NT][2];
        #pragma unroll
        for (int np = 0; np < NT / 2; np++) {
          uint32_t bd = st + 24576 + sw(brow + np * 16, ks * 2 + bgsel);
          ldsm4(bl[np*2][0], bl[np*2][1], bl[np*2+1][0], bl[np*2+1][1], bd);
        }
        #pragma unroll
        for (int mt = 0; mt < 4; mt++)
          #pragma unroll
          for (int nt = 0; nt < NT; nt++)
            mma_f16(acc[mt][nt], ah[mt], bl[nt]);
      }
    }
    __syncthreads();
    if (tid == 0 && c + NS < NCH) issue(c + NS);
  }

  // epilogue
  #pragma unroll
  for (int mt = 0; mt < 4; mt++) {
    int m = m0 + wm + mt * 16 + (lane >> 2);
    #pragma unroll
    for (int nt = 0; nt < NT; nt++) {
      int n = n0 + wn + nt * 8 + (lane & 3) * 2;
      float2 v0 = make_float2(acc[mt][nt][0], acc[mt][nt][1]);
      float2 v1 = make_float2(acc[mt][nt][2], acc[mt][nt][3]);
      if (MODE == 0) {
        __half2 h0{__float2half_rn(v0.x), __float2half_rn(v0.y)};
        __half2 h1{__float2half_rn(v1.x), __float2half_rn(v1.y)};
        *(__half2*)(Ch + (size_t)m * 1024 + n) = h0;
        *(__half2*)(Ch + (size_t)(m + 8) * 1024 + n) = h1;
      } else {
        if (MODE == 1) {
          float b0 = __ldg(bias + n), b1 = __ldg(bias + n + 1);
          v0.x += b0; v0.y += b1; v1.x += b0; v1.y += b1;
        }
        *(float2*)(C + (size_t)m * cst + n) = v0;
        *(float2*)(C + (size_t)(m + 8) * cst + n) = v1;
      }
    }
  }
}

// ======================================================================
extern "C" void kernel_launch(void* const* d_in, const int* in_sizes, int n_in,
                              void* d_out, int out_size) {
  const float* xc     = (const float*)d_in[0];
  const float* xf     = (const float*)d_in[1];
  const float* xbd    = (const float*)d_in[2];
  const float* xbg    = (const float*)d_in[3];
  const float* tokens = (const float*)d_in[4];
  const float* w_in   = (const float*)d_in[5];
  const float* b_in   = (const float*)d_in[6];
  const float* w_out  = (const float*)d_in[7];
  const float* b_out  = (const float*)d_in[8];
  float* out = (float*)d_out;

  cudaFuncSetAttribute(k_mma<0>, cudaFuncAttributeMaxDynamicSharedMemorySize, 1024 + 6 * 24576);
  cudaFuncSetAttribute(k_mma<1>, cudaFuncAttributeMaxDynamicSharedMemorySize, 1024 + 5 * 32768);
  cudaFuncSetAttribute(k_mma<2>, cudaFuncAttributeMaxDynamicSharedMemorySize, 1024 + 5 * 32768);

  k_convA<<<dim3(Bq, 4), 256>>>(xc, xf, xbd, xbg);                              // 0
  k_convW<<<dim3(1024, 14), 256>>>(w_in, w_out);                                // 1
  k_qh<<<NBR, 256>>>(tokens, w_in, b_in);                                       // 2
  k_mma<0><<<dim3(Bq/128, Dm/256, 19), 256, 1024 + 6*24576>>>(b_out, out);      // 3 <- ncu slot
  k_zs<<<256, 256>>>();                                                         // 4
  k_s<<<dim3(NBR, 8), 256>>>(w_in);                                             // 5
  k_mma<2><<<dim3(Bq/128, 2, 4), 256, 1024 + 5*32768>>>(b_out, out);            // 6
  k_softmax<<<NBR * Bq * 16 / 256, 256>>>();                                    // 7
  k_mix<<<NBR * Bq * (Dm / 4) / 256, 256>>>(b_in);                              // 8
  k_mma<1><<<dim3(Bq/128, Dm/256, NBR), 256, 1024 + 5*32768>>>(b_out, out);     // 9
}

// round 10
// speedup vs baseline: 6.0949x; 1.1502x over previous
#include <cuda_runtime.h>
#include <cuda_fp16.h>
#include <cstdint>

#define Bq 8192
#define Dm 1024
#define NBR 7
#define BD ((size_t)Bq * Dm)
#define DD ((size_t)Dm * Dm)

// ---------------- scratch (tiled, pre-swizzled fp16 planes: [kc][rows][32]) ----------------
__device__ float g_Q[NBR * Dm];
__device__ float g_SC[(size_t)4 * Bq * 256];
__device__ float g_A[(size_t)NBR * 4 * Bq * 16];
__device__ __align__(16) __half g_V[(size_t)19 * BD];     // v-proj results, fp16
__device__ __align__(16) __half g_Sh[256 * Dm];
__device__ __align__(16) __half g_Sl[256 * Dm];
__device__ __align__(16) __half g_Ah[4 * BD];
__device__ __align__(16) __half g_Al[4 * BD];
__device__ __align__(16) __half g_Wh[14 * DD];            // weights: single plane
__device__ __align__(16) __half g_Oh[NBR * BD];           // attn-out: single plane

__constant__ int c_nvec[NBR] = {2,2,2,3,3,3,4};
__constant__ int c_vidx[NBR][4] = {{0,1,0,0},{0,2,0,0},{0,3,0,0},{0,1,2,0},{0,1,3,0},{0,2,3,0},{0,1,2,3}};
__constant__ int c_poff[NBR] = {0,2,4,6,9,12,15};
__constant__ int c_pairi[19] = {0,0,1,1,2,2,3,3,3,4,4,4,5,5,5,6,6,6,6};
__constant__ int c_pairv[19] = {0,1,0,2,0,3,0,1,2,0,1,3,0,2,3,0,1,2,3};

// tiled+swizzled element offset within a [R rows x 1024 k] fp16 plane
__device__ __forceinline__ size_t toff(int row, int k, int R) {
  return ((size_t)(k >> 5) * R + row) * 32 +
         (((((k >> 3) & 3) ^ ((row >> 1) & 3)) << 3) + (k & 7));
}

// ---------------- PTX helpers ----------------
__device__ __forceinline__ uint32_t smem_u32(const void* p) {
  uint32_t a;
  asm("{ .reg .u64 t; cvta.to.shared.u64 t, %1; cvt.u32.u64 %0, t; }" : "=r"(a) : "l"(p));
  return a;
}
#define MBAR_INIT(a, n) asm volatile("mbarrier.init.shared.b64 [%0], %1;" :: "r"(a), "r"(n) : "memory")
#define MBAR_EXPECT(a, b) asm volatile("mbarrier.arrive.expect_tx.shared.b64 _, [%0], %1;" :: "r"(a), "r"(b) : "memory")
#define MBAR_WAIT(a, ph) do { \
  uint32_t _m = (a), _p = (ph), _d; \
  asm volatile("{ .reg .pred p; mbarrier.try_wait.parity.acquire.cta.shared::cta.b64 p, [%1], %2; selp.b32 %0,1,0,p; }" \
    : "=r"(_d) : "r"(_m), "r"(_p) : "memory"); \
  if (!_d) { asm volatile("{ .reg .pred P1; WL_%=: mbarrier.try_wait.parity.acquire.cta.shared::cta.b64 P1, [%0], %1, 0x989680; @P1 bra.uni WD_%=; bra.uni WL_%=; WD_%=: }" \
    :: "r"(_m), "r"(_p) : "memory"); } } while (0)

__device__ __forceinline__ void bulk_g2s(uint32_t dst, const void* src, uint32_t bytes, uint32_t mbar) {
  asm volatile("cp.async.bulk.shared::cluster.global.mbarrier::complete_tx::bytes [%0], [%1], %2, [%3];"
               :: "r"(dst), "l"(src), "r"(bytes), "r"(mbar) : "memory");
}
__device__ __forceinline__ void ldsm4(uint32_t& r0, uint32_t& r1, uint32_t& r2, uint32_t& r3, uint32_t addr) {
  asm volatile("ldmatrix.sync.aligned.m8n8.x4.shared.b16 {%0,%1,%2,%3}, [%4];"
               : "=r"(r0), "=r"(r1), "=r"(r2), "=r"(r3) : "r"(addr));
}
__device__ __forceinline__ void mma_f16(float* c, const uint32_t* a, const uint32_t* b) {
  asm volatile("mma.sync.aligned.m16n8k16.row.col.f32.f16.f16.f32 "
               "{%0,%1,%2,%3}, {%4,%5,%6,%7}, {%8,%9}, {%0,%1,%2,%3};"
               : "+f"(c[0]), "+f"(c[1]), "+f"(c[2]), "+f"(c[3])
               : "r"(a[0]), "r"(a[1]), "r"(a[2]), "r"(a[3]), "r"(b[0]), "r"(b[1]));
}

// ======================= fp32 -> fp16 split/pack =======================
__device__ __forceinline__ void split4h(float4 v, uint2& hi, uint2& lo) {
  __half h0 = __float2half_rn(v.x), h1 = __float2half_rn(v.y);
  __half h2 = __float2half_rn(v.z), h3 = __float2half_rn(v.w);
  __half l0 = __float2half_rn(v.x - __half2float(h0));
  __half l1 = __float2half_rn(v.y - __half2float(h1));
  __half l2 = __float2half_rn(v.z - __half2float(h2));
  __half l3 = __float2half_rn(v.w - __half2float(h3));
  __half2 a{h0, h1}, b{h2, h3}, c{l0, l1}, d{l2, l3};
  hi = make_uint2(*(uint32_t*)&a, *(uint32_t*)&b);
  lo = make_uint2(*(uint32_t*)&c, *(uint32_t*)&d);
}
__device__ __forceinline__ uint2 pack4h(float4 v) {
  __half2 a{__float2half_rn(v.x), __float2half_rn(v.y)};
  __half2 b{__float2half_rn(v.z), __float2half_rn(v.w)};
  return make_uint2(*(uint32_t*)&a, *(uint32_t*)&b);
}

// ======================= prep / conversion kernels =======================
__global__ void k_qh(const float* __restrict__ tokens, const float* __restrict__ w_in,
                     const float* __restrict__ b_in) {
  int i = blockIdx.x, t = threadIdx.x;
  __shared__ float tok[Dm];
  for (int k = t; k < Dm; k += 256) tok[k] = tokens[i * Dm + k];
  __syncthreads();
  const float* wq = w_in + (size_t)i * 3 * DD;
  for (int r = t; r < Dm; r += 256) {
    const float* row = wq + (size_t)r * Dm;
    float acc = b_in[i * 3 * Dm + r];
    for (int k = 0; k < Dm; k += 4) {
      float4 w = *(const float4*)(row + k);
      acc += w.x*tok[k] + w.y*tok[k+1] + w.z*tok[k+2] + w.w*tok[k+3];
    }
    g_Q[i * Dm + r] = acc;
  }
}

__global__ void k_zs() {
  size_t i = ((size_t)blockIdx.x * 256 + threadIdx.x) * 4;
  *(uint2*)(g_Sh + i) = make_uint2(0, 0);
  *(uint2*)(g_Sl + i) = make_uint2(0, 0);
}

__global__ void k_s(const float* __restrict__ w_in) {
  int i = blockIdx.x, kb = blockIdx.y * 128;
  __shared__ float qh[Dm];
  for (int k = threadIdx.x; k < Dm; k += 256) qh[k] = g_Q[i * Dm + k];
  __syncthreads();
  const float* wk = w_in + (size_t)i * 3 * DD + DD;
  for (int o = threadIdx.x; o < 16 * 128; o += 256) {
    int h = o >> 7, k = kb + (o & 127);
    float acc = 0.f;
    #pragma unroll 8
    for (int j = 0; j < 64; j++) acc += wk[(size_t)(h * 64 + j) * Dm + k] * qh[h * 64 + j];
    float val = 0.125f * acc;
    __half hi = __float2half_rn(val);
    size_t off = toff(i * 16 + h, k, 256);
    g_Sh[off] = hi;
    g_Sl[off] = __float2half_rn(val - __half2float(hi));
  }
}

__global__ void k_softmax() {
  int idx = blockIdx.x * 256 + threadIdx.x;
  int h = idx & 15;
  int b = (idx >> 4) & (Bq - 1);
  int i = idx >> 17;
  int L = c_nvec[i];
  float sc[4];
  float mx = -1e30f;
  #pragma unroll
  for (int l = 0; l < 4; l++) if (l < L) {
    sc[l] = g_SC[((size_t)c_vidx[i][l] * Bq + b) * 256 + i * 16 + h];
    mx = fmaxf(mx, sc[l]);
  }
  float sum = 0.f;
  #pragma unroll
  for (int l = 0; l < 4; l++) if (l < L) { sc[l] = expf(sc[l] - mx); sum += sc[l]; }
  float inv = 1.f / sum;
  #pragma unroll
  for (int l = 0; l < 4; l++) if (l < L)
    g_A[(((size_t)i * 4 + l) * Bq + b) * 16 + h] = sc[l] * inv;
}

__global__ void k_mix(const float* __restrict__ b_in) {
  size_t gid = (size_t)blockIdx.x * 256 + threadIdx.x;
  int i = (int)(gid >> 21);
  int rem = (int)(gid & ((1u << 21) - 1));
  int b = rem >> 8;
  int k = (rem & 255) * 4;
  int h = k >> 6;
  int L = c_nvec[i];
  int p0 = c_poff[i];
  float4 o = *(const float4*)(b_in + ((size_t)i * 3 + 2) * Dm + k);
  #pragma unroll
  for (int l = 0; l < 4; l++) if (l < L) {
    float a = g_A[(((size_t)i * 4 + l) * Bq + b) * 16 + h];
    const __half2* vp = (const __half2*)(g_V + ((size_t)(p0 + l) * Bq + b) * Dm + k);
    float2 f01 = __half22float2(vp[0]);
    float2 f23 = __half22float2(vp[1]);
    o.x += a * f01.x; o.y += a * f01.y; o.z += a * f23.x; o.w += a * f23.y;
  }
  *(uint2*)(g_Oh + (size_t)i * BD + toff(b, k, Bq)) = pack4h(o);
}

__global__ void k_convA(const float* __restrict__ xc, const float* __restrict__ xf,
                        const float* __restrict__ xbd, const float* __restrict__ xbg) {
  int v = blockIdx.y;
  const float* x = (v == 0) ? xc : (v == 1) ? xf : (v == 2) ? xbd : xbg;
  size_t i = (size_t)blockIdx.x * 256 + threadIdx.x;
  int m = (int)(i >> 8), k = ((int)i & 255) * 4;
  float4 val = ((const float4*)x)[i];
  uint2 hi, lo; split4h(val, hi, lo);
  size_t off = (size_t)v * BD + toff(m, k, Bq);
  *(uint2*)(g_Ah + off) = hi;
  *(uint2*)(g_Al + off) = lo;
}

__global__ void k_convW(const float* __restrict__ w_in, const float* __restrict__ w_out) {
  int z = blockIdx.y;
  const float* src = (z < 7) ? (w_in + (size_t)z * 3 * DD + 2 * DD) : (w_out + (size_t)(z - 7) * DD);
  size_t i = (size_t)blockIdx.x * 256 + threadIdx.x;
  int n = (int)(i >> 8), k = ((int)i & 255) * 4;
  float4 val = ((const float4*)src)[i];
  *(uint2*)(g_Wh + (size_t)z * DD + toff(n, k, Dm)) = pack4h(val);
}

// ======================= bulk-copy fp16 HMMA GEMM =======================
// MODE 0 (v-proj): CTA 128x256, 1 term. Stage 24KB: A 8K | B 16K. C fp16.
// MODE 1 (out):    CTA 128x256, 1 term. Stage 24KB: A 8K | B 16K. C fp32 + bias.
// MODE 2 (scores): CTA 128x128, 3 terms. Stage 32KB: Ah | Al | Bh | Bl @ 8K each.
#define NCH 32

__device__ __forceinline__ uint32_t sw(uint32_t row, uint32_t g) {
  return row * 64 + ((g ^ ((row >> 1) & 3)) << 4);
}

template<int MODE>
__global__ void __launch_bounds__(256, 1) k_mma(const float* __restrict__ b_out,
                                                float* __restrict__ dout) {
  constexpr int STG  = (MODE == 2) ? 32768 : 24576;
  constexpr int NS   = (MODE == 2) ? 5 : 8;
  constexpr int NT   = (MODE == 2) ? 4 : 8;
  constexpr int BOFF = (MODE == 2) ? 16384 : 8192;
  extern __shared__ __align__(128) char smem[];
  const uint32_t sb = smem_u32(smem);
  const int tid = threadIdx.x;
  const int wid = tid >> 5, lane = tid & 31;
  const int m0 = blockIdx.x * 128;
  const int n0 = blockIdx.y * ((MODE == 2) ? 128 : 256);
  const int wm = (wid & 1) * 64, wn = (wid >> 1) * (NT * 8);
  const int cst = (MODE == 2) ? 256 : 1024;
  const int RB  = (MODE == 2) ? 256 : 1024;

  const __half *Ah, *Al = nullptr, *Bh, *Bl = nullptr;
  float* C = nullptr; __half* Ch = nullptr; const float* bias = nullptr;
  if (MODE == 0) {
    int p = blockIdx.z;
    int v = c_pairv[p], wi = c_pairi[p];
    Ah = g_Ah + (size_t)v * BD;
    Bh = g_Wh + (size_t)wi * DD;
    Ch = g_V + (size_t)p * BD;
  } else if (MODE == 1) {
    int i = blockIdx.z;
    Ah = g_Oh + (size_t)i * BD;
    Bh = g_Wh + (size_t)(7 + i) * DD;
    C = dout + (size_t)i * BD;
    bias = b_out + i * Dm;
  } else {
    int v = blockIdx.z;
    Ah = g_Ah + (size_t)v * BD;  Al = g_Al + (size_t)v * BD;
    Bh = g_Sh; Bl = g_Sl;
    C = g_SC + (size_t)v * Bq * 256;
  }

  if (tid == 0) {
    #pragma unroll
    for (int s = 0; s < NS; s++) MBAR_INIT(sb + s * 8, 1);
  }
  __syncthreads();

  auto issue = [&](int c) {
    int s = c % NS;
    uint32_t st = sb + 1024 + s * STG;
    uint32_t mb = sb + s * 8;
    MBAR_EXPECT(mb, STG);
    bulk_g2s(st, Ah + ((size_t)c * Bq + m0) * 32, 8192, mb);
    if (MODE == 2) {
      bulk_g2s(st + 8192,  Al + ((size_t)c * Bq + m0) * 32, 8192, mb);
      bulk_g2s(st + 16384, Bh + ((size_t)c * RB + n0) * 32, 8192, mb);
      bulk_g2s(st + 24576, Bl + ((size_t)c * RB + n0) * 32, 8192, mb);
    } else {
      bulk_g2s(st + BOFF, Bh + ((size_t)c * RB + n0) * 32, 16384, mb);
    }
  };
  if (tid == 0) {
    #pragma unroll
    for (int c = 0; c < NS; c++) issue(c);
  }

  float acc[4][NT][4];
  #pragma unroll
  for (int mt = 0; mt < 4; mt++)
    #pragma unroll
    for (int nt = 0; nt < NT; nt++)
      #pragma unroll
      for (int r = 0; r < 4; r++) acc[mt][nt][r] = 0.f;

  const int arow = wm + (lane & 15);
  const int agsel = lane >> 4;
  const int brow = wn + ((lane & 7) | ((lane & 16) >> 1));
  const int bgsel = (lane >> 3) & 1;

  for (int c = 0; c < NCH; c++) {
    const int s = c % NS;
    const uint32_t st = sb + 1024 + s * STG;
    MBAR_WAIT(sb + s * 8, (c / NS) & 1);
    #pragma unroll
    for (int ks = 0; ks < 2; ks++) {
      uint32_t ah[4][4], al[4][4], bh[NT][2];
      #pragma unroll
      for (int mt = 0; mt < 4; mt++) {
        uint32_t ad = st + sw(arow + mt * 16, ks * 2 + agsel);
        ldsm4(ah[mt][0], ah[mt][1], ah[mt][2], ah[mt][3], ad);
        if (MODE == 2) ldsm4(al[mt][0], al[mt][1], al[mt][2], al[mt][3], ad + 8192);
      }
      #pragma unroll
      for (int np = 0; np < NT / 2; np++) {
        uint32_t bd = st + BOFF + sw(brow + np * 16, ks * 2 + bgsel);
        ldsm4(bh[np*2][0], bh[np*2][1], bh[np*2+1][0], bh[np*2+1][1], bd);
      }
      #pragma unroll
      for (int mt = 0; mt < 4; mt++)
        #pragma unroll
        for (int nt = 0; nt < NT; nt++) {
          mma_f16(acc[mt][nt], ah[mt], bh[nt]);
          if (MODE == 2) mma_f16(acc[mt][nt], al[mt], bh[nt]);
        }
      if (MODE == 2) {
        uint32_t bl[NT][2];
        #pragma unroll
        for (int np = 0; np < NT / 2; np++) {
          uint32_t bd = st + 24576 + sw(brow + np * 16, ks * 2 + bgsel);
          ldsm4(bl[np*2][0], bl[np*2][1], bl[np*2+1][0], bl[np*2+1][1], bd);
        }
        #pragma unroll
        for (int mt = 0; mt < 4; mt++)
          #pragma unroll
          for (int nt = 0; nt < NT; nt++)
            mma_f16(acc[mt][nt], ah[mt], bl[nt]);
      }
    }
    __syncthreads();
    if (tid == 0 && c + NS < NCH) issue(c + NS);
  }

  // epilogue
  #pragma unroll
  for (int mt = 0; mt < 4; mt++) {
    int m = m0 + wm + mt * 16 + (lane >> 2);
    #pragma unroll
    for (int nt = 0; nt < NT; nt++) {
      int n = n0 + wn + nt * 8 + (lane & 3) * 2;
      float2 v0 = make_float2(acc[mt][nt][0], acc[mt][nt][1]);
      float2 v1 = make_float2(acc[mt][nt][2], acc[mt][nt][3]);
      if (MODE == 0) {
        __half2 h0{__float2half_rn(v0.x), __float2half_rn(v0.y)};
        __half2 h1{__float2half_rn(v1.x), __float2half_rn(v1.y)};
        *(__half2*)(Ch + (size_t)m * 1024 + n) = h0;
        *(__half2*)(Ch + (size_t)(m + 8) * 1024 + n) = h1;
      } else {
        if (MODE == 1) {
          float b0 = __ldg(bias + n), b1 = __ldg(bias + n + 1);
          v0.x += b0; v0.y += b1; v1.x += b0; v1.y += b1;
        }
        *(float2*)(C + (size_t)m * cst + n) = v0;
        *(float2*)(C + (size_t)(m + 8) * cst + n) = v1;
      }
    }
  }
}

// ======================================================================
extern "C" void kernel_launch(void* const* d_in, const int* in_sizes, int n_in,
                              void* d_out, int out_size) {
  const float* xc     = (const float*)d_in[0];
  const float* xf     = (const float*)d_in[1];
  const float* xbd    = (const float*)d_in[2];
  const float* xbg    = (const float*)d_in[3];
  const float* tokens = (const float*)d_in[4];
  const float* w_in   = (const float*)d_in[5];
  const float* b_in   = (const float*)d_in[6];
  const float* w_out  = (const float*)d_in[7];
  const float* b_out  = (const float*)d_in[8];
  float* out = (float*)d_out;

  cudaFuncSetAttribute(k_mma<0>, cudaFuncAttributeMaxDynamicSharedMemorySize, 1024 + 8 * 24576);
  cudaFuncSetAttribute(k_mma<1>, cudaFuncAttributeMaxDynamicSharedMemorySize, 1024 + 8 * 24576);
  cudaFuncSetAttribute(k_mma<2>, cudaFuncAttributeMaxDynamicSharedMemorySize, 1024 + 5 * 32768);

  k_convA<<<dim3(Bq, 4), 256>>>(xc, xf, xbd, xbg);                              // 0
  k_convW<<<dim3(1024, 14), 256>>>(w_in, w_out);                                // 1
  k_qh<<<NBR, 256>>>(tokens, w_in, b_in);                                       // 2
  k_mma<0><<<dim3(Bq/128, Dm/256, 19), 256, 1024 + 8*24576>>>(b_out, out);      // 3 <- ncu slot
  k_zs<<<256, 256>>>();                                                         // 4
  k_s<<<dim3(NBR, 8), 256>>>(w_in);                                             // 5
  k_mma<2><<<dim3(Bq/128, 2, 4), 256, 1024 + 5*32768>>>(b_out, out);            // 6
  k_softmax<<<NBR * Bq * 16 / 256, 256>>>();                                    // 7
  k_mix<<<NBR * Bq * (Dm / 4) / 256, 256>>>(b_in);                              // 8
  k_mma<1><<<dim3(Bq/128, Dm/256, NBR), 256, 1024 + 8*24576>>>(b_out, out);     // 9
}

// round 11
// speedup vs baseline: 7.2251x; 1.1854x over previous
#include <cuda_runtime.h>
#include <cuda_fp16.h>
#include <cstdint>

#define Bq 8192
#define Dm 1024
#define NBR 7
#define BD ((size_t)Bq * Dm)
#define DD ((size_t)Dm * Dm)

// ---------------- scratch (tiled, pre-swizzled fp16 planes: [kc][rows][32]) ----------------
__device__ float g_Q[NBR * Dm];
__device__ float g_SC[(size_t)4 * Bq * 256];
__device__ float g_A[(size_t)NBR * 4 * Bq * 16];
__device__ __align__(16) __half g_V[(size_t)19 * BD];     // v-proj results, fp16
__device__ __align__(16) __half g_Sh[256 * Dm];
__device__ __align__(16) __half g_Sl[256 * Dm];
__device__ __align__(16) __half g_Ah[4 * BD];
__device__ __align__(16) __half g_Al[4 * BD];
__device__ __align__(16) __half g_Wh[14 * DD];            // weights: single plane
__device__ __align__(16) __half g_Oh[NBR * BD];           // attn-out: single plane

__constant__ int c_nvec[NBR] = {2,2,2,3,3,3,4};
__constant__ int c_vidx[NBR][4] = {{0,1,0,0},{0,2,0,0},{0,3,0,0},{0,1,2,0},{0,1,3,0},{0,2,3,0},{0,1,2,3}};
__constant__ int c_poff[NBR] = {0,2,4,6,9,12,15};
__constant__ int c_pairi[19] = {0,0,1,1,2,2,3,3,3,4,4,4,5,5,5,6,6,6,6};
__constant__ int c_pairv[19] = {0,1,0,2,0,3,0,1,2,0,1,3,0,2,3,0,1,2,3};

// tiled+swizzled element offset within a [R rows x 1024 k] fp16 plane
__device__ __forceinline__ size_t toff(int row, int k, int R) {
  return ((size_t)(k >> 5) * R + row) * 32 +
         (((((k >> 3) & 3) ^ ((row >> 1) & 3)) << 3) + (k & 7));
}

// ---------------- PTX helpers ----------------
__device__ __forceinline__ uint32_t smem_u32(const void* p) {
  uint32_t a;
  asm("{ .reg .u64 t; cvta.to.shared.u64 t, %1; cvt.u32.u64 %0, t; }" : "=r"(a) : "l"(p));
  return a;
}
#define MBAR_INIT(a, n) asm volatile("mbarrier.init.shared.b64 [%0], %1;" :: "r"(a), "r"(n) : "memory")
#define MBAR_EXPECT(a, b) asm volatile("mbarrier.arrive.expect_tx.shared.b64 _, [%0], %1;" :: "r"(a), "r"(b) : "memory")
#define MBAR_WAIT(a, ph) do { \
  uint32_t _m = (a), _p = (ph), _d; \
  asm volatile("{ .reg .pred p; mbarrier.try_wait.parity.acquire.cta.shared::cta.b64 p, [%1], %2; selp.b32 %0,1,0,p; }" \
    : "=r"(_d) : "r"(_m), "r"(_p) : "memory"); \
  if (!_d) { asm volatile("{ .reg .pred P1; WL_%=: mbarrier.try_wait.parity.acquire.cta.shared::cta.b64 P1, [%0], %1, 0x989680; @P1 bra.uni WD_%=; bra.uni WL_%=; WD_%=: }" \
    :: "r"(_m), "r"(_p) : "memory"); } } while (0)

__device__ __forceinline__ void bulk_g2s(uint32_t dst, const void* src, uint32_t bytes, uint32_t mbar) {
  asm volatile("cp.async.bulk.shared::cluster.global.mbarrier::complete_tx::bytes [%0], [%1], %2, [%3];"
               :: "r"(dst), "l"(src), "r"(bytes), "r"(mbar) : "memory");
}
__device__ __forceinline__ void ldsm4(uint32_t& r0, uint32_t& r1, uint32_t& r2, uint32_t& r3, uint32_t addr) {
  asm volatile("ldmatrix.sync.aligned.m8n8.x4.shared.b16 {%0,%1,%2,%3}, [%4];"
               : "=r"(r0), "=r"(r1), "=r"(r2), "=r"(r3) : "r"(addr));
}
__device__ __forceinline__ void mma_f16(float* c, const uint32_t* a, const uint32_t* b) {
  asm volatile("mma.sync.aligned.m16n8k16.row.col.f32.f16.f16.f32 "
               "{%0,%1,%2,%3}, {%4,%5,%6,%7}, {%8,%9}, {%0,%1,%2,%3};"
               : "+f"(c[0]), "+f"(c[1]), "+f"(c[2]), "+f"(c[3])
               : "r"(a[0]), "r"(a[1]), "r"(a[2]), "r"(a[3]), "r"(b[0]), "r"(b[1]));
}

// ======================= fp32 -> fp16 split/pack =======================
__device__ __forceinline__ void split4h(float4 v, uint2& hi, uint2& lo) {
  __half h0 = __float2half_rn(v.x), h1 = __float2half_rn(v.y);
  __half h2 = __float2half_rn(v.z), h3 = __float2half_rn(v.w);
  __half l0 = __float2half_rn(v.x - __half2float(h0));
  __half l1 = __float2half_rn(v.y - __half2float(h1));
  __half l2 = __float2half_rn(v.z - __half2float(h2));
  __half l3 = __float2half_rn(v.w - __half2float(h3));
  __half2 a{h0, h1}, b{h2, h3}, c{l0, l1}, d{l2, l3};
  hi = make_uint2(*(uint32_t*)&a, *(uint32_t*)&b);
  lo = make_uint2(*(uint32_t*)&c, *(uint32_t*)&d);
}
__device__ __forceinline__ uint2 pack4h(float4 v) {
  __half2 a{__float2half_rn(v.x), __float2half_rn(v.y)};
  __half2 b{__float2half_rn(v.z), __float2half_rn(v.w)};
  return make_uint2(*(uint32_t*)&a, *(uint32_t*)&b);
}

// ======================= prep / conversion kernels =======================
__global__ void k_qh(const float* __restrict__ tokens, const float* __restrict__ w_in,
                     const float* __restrict__ b_in) {
  int i = blockIdx.x, t = threadIdx.x;
  __shared__ float tok[Dm];
  for (int k = t; k < Dm; k += 256) tok[k] = tokens[i * Dm + k];
  __syncthreads();
  const float* wq = w_in + (size_t)i * 3 * DD;
  for (int r = t; r < Dm; r += 256) {
    const float* row = wq + (size_t)r * Dm;
    float acc = b_in[i * 3 * Dm + r];
    for (int k = 0; k < Dm; k += 4) {
      float4 w = *(const float4*)(row + k);
      acc += w.x*tok[k] + w.y*tok[k+1] + w.z*tok[k+2] + w.w*tok[k+3];
    }
    g_Q[i * Dm + r] = acc;
  }
}

__global__ void k_zs() {
  size_t i = ((size_t)blockIdx.x * 256 + threadIdx.x) * 4;
  *(uint2*)(g_Sh + i) = make_uint2(0, 0);
  *(uint2*)(g_Sl + i) = make_uint2(0, 0);
}

__global__ void k_s(const float* __restrict__ w_in) {
  int i = blockIdx.x, kb = blockIdx.y * 128;
  __shared__ float qh[Dm];
  for (int k = threadIdx.x; k < Dm; k += 256) qh[k] = g_Q[i * Dm + k];
  __syncthreads();
  const float* wk = w_in + (size_t)i * 3 * DD + DD;
  for (int o = threadIdx.x; o < 16 * 128; o += 256) {
    int h = o >> 7, k = kb + (o & 127);
    float acc = 0.f;
    #pragma unroll 8
    for (int j = 0; j < 64; j++) acc += wk[(size_t)(h * 64 + j) * Dm + k] * qh[h * 64 + j];
    float val = 0.125f * acc;
    __half hi = __float2half_rn(val);
    size_t off = toff(i * 16 + h, k, 256);
    g_Sh[off] = hi;
    g_Sl[off] = __float2half_rn(val - __half2float(hi));
  }
}

__global__ void k_softmax() {
  int idx = blockIdx.x * 256 + threadIdx.x;
  int h = idx & 15;
  int b = (idx >> 4) & (Bq - 1);
  int i = idx >> 17;
  int L = c_nvec[i];
  float sc[4];
  float mx = -1e30f;
  #pragma unroll
  for (int l = 0; l < 4; l++) if (l < L) {
    sc[l] = g_SC[((size_t)c_vidx[i][l] * Bq + b) * 256 + i * 16 + h];
    mx = fmaxf(mx, sc[l]);
  }
  float sum = 0.f;
  #pragma unroll
  for (int l = 0; l < 4; l++) if (l < L) { sc[l] = expf(sc[l] - mx); sum += sc[l]; }
  float inv = 1.f / sum;
  #pragma unroll
  for (int l = 0; l < 4; l++) if (l < L)
    g_A[(((size_t)i * 4 + l) * Bq + b) * 16 + h] = sc[l] * inv;
}

__global__ void k_mix(const float* __restrict__ b_in) {
  size_t gid = (size_t)blockIdx.x * 256 + threadIdx.x;
  int i = (int)(gid >> 21);
  int rem = (int)(gid & ((1u << 21) - 1));
  int b = rem >> 8;
  int k = (rem & 255) * 4;
  int h = k >> 6;
  int L = c_nvec[i];
  int p0 = c_poff[i];
  float4 o = *(const float4*)(b_in + ((size_t)i * 3 + 2) * Dm + k);
  #pragma unroll
  for (int l = 0; l < 4; l++) if (l < L) {
    float a = g_A[(((size_t)i * 4 + l) * Bq + b) * 16 + h];
    const __half2* vp = (const __half2*)(g_V + ((size_t)(p0 + l) * Bq + b) * Dm + k);
    float2 f01 = __half22float2(vp[0]);
    float2 f23 = __half22float2(vp[1]);
    o.x += a * f01.x; o.y += a * f01.y; o.z += a * f23.x; o.w += a * f23.y;
  }
  *(uint2*)(g_Oh + (size_t)i * BD + toff(b, k, Bq)) = pack4h(o);
}

__global__ void k_convA(const float* __restrict__ xc, const float* __restrict__ xf,
                        const float* __restrict__ xbd, const float* __restrict__ xbg) {
  int v = blockIdx.y;
  const float* x = (v == 0) ? xc : (v == 1) ? xf : (v == 2) ? xbd : xbg;
  size_t i = (size_t)blockIdx.x * 256 + threadIdx.x;
  int m = (int)(i >> 8), k = ((int)i & 255) * 4;
  float4 val = ((const float4*)x)[i];
  uint2 hi, lo; split4h(val, hi, lo);
  size_t off = (size_t)v * BD + toff(m, k, Bq);
  *(uint2*)(g_Ah + off) = hi;
  *(uint2*)(g_Al + off) = lo;
}

__global__ void k_convW(const float* __restrict__ w_in, const float* __restrict__ w_out) {
  int z = blockIdx.y;
  const float* src = (z < 7) ? (w_in + (size_t)z * 3 * DD + 2 * DD) : (w_out + (size_t)(z - 7) * DD);
  size_t i = (size_t)blockIdx.x * 256 + threadIdx.x;
  int n = (int)(i >> 8), k = ((int)i & 255) * 4;
  float4 val = ((const float4*)src)[i];
  *(uint2*)(g_Wh + (size_t)z * DD + toff(n, k, Dm)) = pack4h(val);
}

// ======================= bulk-copy fp16 HMMA GEMM (K-chunk 64) =======================
// MODE 0 (v-proj): CTA 128x256, 1 term. Stage 48KB: A0 8K|A1 8K|B0 16K|B1 16K. C fp16.
// MODE 1 (out):    same, C fp32 + bias.
// MODE 2 (scores): CTA 128x128, 3 terms. Stage 64KB: Ah0|Ah1|Al0|Al1|Bh0|Bh1|Bl0|Bl1 @8K.
#define NCH 16
#define SMEM_SZ (1024 + 196608)

__device__ __forceinline__ uint32_t sw(uint32_t row, uint32_t g) {
  return row * 64 + ((g ^ ((row >> 1) & 3)) << 4);
}

template<int MODE>
__global__ void __launch_bounds__(256, 1) k_mma(const float* __restrict__ b_out,
                                                float* __restrict__ dout) {
  constexpr int STG = (MODE == 2) ? 65536 : 49152;
  constexpr int NS  = (MODE == 2) ? 3 : 4;
  constexpr int NT  = (MODE == 2) ? 4 : 8;
  extern __shared__ __align__(128) char smem[];
  const uint32_t sb = smem_u32(smem);
  const int tid = threadIdx.x;
  const int wid = tid >> 5, lane = tid & 31;
  const int m0 = blockIdx.x * 128;
  const int n0 = blockIdx.y * ((MODE == 2) ? 128 : 256);
  const int wm = (wid & 1) * 64, wn = (wid >> 1) * (NT * 8);
  const int cst = (MODE == 2) ? 256 : 1024;
  const int RB  = (MODE == 2) ? 256 : 1024;
  constexpr uint32_t BOFF = (MODE == 2) ? 32768 : 16384;

  const __half *Ah, *Al = nullptr, *Bh, *Bl = nullptr;
  float* C = nullptr; __half* Ch = nullptr; const float* bias = nullptr;
  if (MODE == 0) {
    int p = blockIdx.z;
    int v = c_pairv[p], wi = c_pairi[p];
    Ah = g_Ah + (size_t)v * BD;
    Bh = g_Wh + (size_t)wi * DD;
    Ch = g_V + (size_t)p * BD;
  } else if (MODE == 1) {
    int i = blockIdx.z;
    Ah = g_Oh + (size_t)i * BD;
    Bh = g_Wh + (size_t)(7 + i) * DD;
    C = dout + (size_t)i * BD;
    bias = b_out + i * Dm;
  } else {
    int v = blockIdx.z;
    Ah = g_Ah + (size_t)v * BD;  Al = g_Al + (size_t)v * BD;
    Bh = g_Sh; Bl = g_Sl;
    C = g_SC + (size_t)v * Bq * 256;
  }

  if (tid == 0) {
    #pragma unroll
    for (int s = 0; s < NS; s++) MBAR_INIT(sb + s * 8, 1);
  }
  __syncthreads();

  auto issue = [&](int c) {
    int s = c % NS;
    uint32_t st = sb + 1024 + s * STG;
    uint32_t mb = sb + s * 8;
    MBAR_EXPECT(mb, STG);
    bulk_g2s(st,        Ah + ((size_t)(2*c)   * Bq + m0) * 32, 8192, mb);
    bulk_g2s(st + 8192, Ah + ((size_t)(2*c+1) * Bq + m0) * 32, 8192, mb);
    if (MODE == 2) {
      bulk_g2s(st + 16384, Al + ((size_t)(2*c)   * Bq + m0) * 32, 8192, mb);
      bulk_g2s(st + 24576, Al + ((size_t)(2*c+1) * Bq + m0) * 32, 8192, mb);
      bulk_g2s(st + 32768, Bh + ((size_t)(2*c)   * RB + n0) * 32, 8192, mb);
      bulk_g2s(st + 40960, Bh + ((size_t)(2*c+1) * RB + n0) * 32, 8192, mb);
      bulk_g2s(st + 49152, Bl + ((size_t)(2*c)   * RB + n0) * 32, 8192, mb);
      bulk_g2s(st + 57344, Bl + ((size_t)(2*c+1) * RB + n0) * 32, 8192, mb);
    } else {
      bulk_g2s(st + 16384, Bh + ((size_t)(2*c)   * RB + n0) * 32, 16384, mb);
      bulk_g2s(st + 32768, Bh + ((size_t)(2*c+1) * RB + n0) * 32, 16384, mb);
    }
  };
  if (tid == 0) {
    #pragma unroll
    for (int c = 0; c < NS; c++) issue(c);
  }

  float acc[4][NT][4];
  #pragma unroll
  for (int mt = 0; mt < 4; mt++)
    #pragma unroll
    for (int nt = 0; nt < NT; nt++)
      #pragma unroll
      for (int r = 0; r < 4; r++) acc[mt][nt][r] = 0.f;

  const int arow = wm + (lane & 15);
  const int agsel = lane >> 4;
  const int brow = wn + ((lane & 7) | ((lane & 16) >> 1));
  const int bgsel = (lane >> 3) & 1;

  for (int c = 0; c < NCH; c++) {
    const int s = c % NS;
    const uint32_t st = sb + 1024 + s * STG;
    MBAR_WAIT(sb + s * 8, (c / NS) & 1);
    #pragma unroll
    for (int ks = 0; ks < 4; ks++) {
      const int kp = ks >> 1, kk = (ks & 1) * 2;
      const uint32_t stA = st + kp * 8192;
      const uint32_t stB = st + BOFF + kp * ((MODE == 2) ? 8192 : 16384);
      uint32_t ah[4][4], al[4][4], bh[NT][2];
      #pragma unroll
      for (int mt = 0; mt < 4; mt++) {
        uint32_t ad = stA + sw(arow + mt * 16, kk + agsel);
        ldsm4(ah[mt][0], ah[mt][1], ah[mt][2], ah[mt][3], ad);
        if (MODE == 2) ldsm4(al[mt][0], al[mt][1], al[mt][2], al[mt][3], ad + 16384);
      }
      #pragma unroll
      for (int np = 0; np < NT / 2; np++) {
        uint32_t bd = stB + sw(brow + np * 16, kk + bgsel);
        ldsm4(bh[np*2][0], bh[np*2][1], bh[np*2+1][0], bh[np*2+1][1], bd);
      }
      #pragma unroll
      for (int mt = 0; mt < 4; mt++)
        #pragma unroll
        for (int nt = 0; nt < NT; nt++) {
          mma_f16(acc[mt][nt], ah[mt], bh[nt]);
          if (MODE == 2) mma_f16(acc[mt][nt], al[mt], bh[nt]);
        }
      if (MODE == 2) {
        uint32_t bl[NT][2];
        #pragma unroll
        for (int np = 0; np < NT / 2; np++) {
          uint32_t bd = stB + 16384 + sw(brow + np * 16, kk + bgsel);
          ldsm4(bl[np*2][0], bl[np*2][1], bl[np*2+1][0], bl[np*2+1][1], bd);
        }
        #pragma unroll
        for (int mt = 0; mt < 4; mt++)
          #pragma unroll
          for (int nt = 0; nt < NT; nt++)
            mma_f16(acc[mt][nt], ah[mt], bl[nt]);
      }
    }
    __syncthreads();
    if (tid == 0 && c + NS < NCH) issue(c + NS);
  }

  // epilogue
  #pragma unroll
  for (int mt = 0; mt < 4; mt++) {
    int m = m0 + wm + mt * 16 + (lane >> 2);
    #pragma unroll
    for (int nt = 0; nt < NT; nt++) {
      int n = n0 + wn + nt * 8 + (lane & 3) * 2;
      float2 v0 = make_float2(acc[mt][nt][0], acc[mt][nt][1]);
      float2 v1 = make_float2(acc[mt][nt][2], acc[mt][nt][3]);
      if (MODE == 0) {
        __half2 h0{__float2half_rn(v0.x), __float2half_rn(v0.y)};
        __half2 h1{__float2half_rn(v1.x), __float2half_rn(v1.y)};
        *(__half2*)(Ch + (size_t)m * 1024 + n) = h0;
        *(__half2*)(Ch + (size_t)(m + 8) * 1024 + n) = h1;
      } else {
        if (MODE == 1) {
          float b0 = __ldg(bias + n), b1 = __ldg(bias + n + 1);
          v0.x += b0; v0.y += b1; v1.x += b0; v1.y += b1;
        }
        *(float2*)(C + (size_t)m * cst + n) = v0;
        *(float2*)(C + (size_t)(m + 8) * cst + n) = v1;
      }
    }
  }
}

// ======================= streams (created pre-main; capture-safe reuse) =======================
static cudaStream_t g_s1;
static cudaEvent_t g_evA, g_evB;
namespace {
struct StreamInit {
  StreamInit() {
    cudaStreamCreateWithFlags(&g_s1, cudaStreamNonBlocking);
    cudaEventCreateWithFlags(&g_evA, cudaEventDisableTiming);
    cudaEventCreateWithFlags(&g_evB, cudaEventDisableTiming);
  }
};
StreamInit g_si;
}

// ======================================================================
extern "C" void kernel_launch(void* const* d_in, const int* in_sizes, int n_in,
                              void* d_out, int out_size) {
  const float* xc     = (const float*)d_in[0];
  const float* xf     = (const float*)d_in[1];
  const float* xbd    = (const float*)d_in[2];
  const float* xbg    = (const float*)d_in[3];
  const float* tokens = (const float*)d_in[4];
  const float* w_in   = (const float*)d_in[5];
  const float* b_in   = (const float*)d_in[6];
  const float* w_out  = (const float*)d_in[7];
  const float* b_out  = (const float*)d_in[8];
  float* out = (float*)d_out;

  cudaFuncSetAttribute(k_mma<0>, cudaFuncAttributeMaxDynamicSharedMemorySize, SMEM_SZ);
  cudaFuncSetAttribute(k_mma<1>, cudaFuncAttributeMaxDynamicSharedMemorySize, SMEM_SZ);
  cudaFuncSetAttribute(k_mma<2>, cudaFuncAttributeMaxDynamicSharedMemorySize, SMEM_SZ);

  // main stream: conversions, then the big v-proj GEMM
  k_convA<<<dim3(Bq, 4), 256>>>(xc, xf, xbd, xbg);
  cudaEventRecord(g_evA, 0);

  // side stream: scores pipeline (independent of MODE0), joined before k_mix
  cudaStreamWaitEvent(g_s1, g_evA, 0);
  k_qh<<<NBR, 256, 0, g_s1>>>(tokens, w_in, b_in);
  k_zs<<<256, 256, 0, g_s1>>>();
  k_s<<<dim3(NBR, 8), 256, 0, g_s1>>>(w_in);
  k_mma<2><<<dim3(Bq/128, 2, 4), 256, SMEM_SZ, g_s1>>>(b_out, out);
  k_softmax<<<NBR * Bq * 16 / 256, 256, 0, g_s1>>>();
  cudaEventRecord(g_evB, g_s1);

  k_convW<<<dim3(1024, 14), 256>>>(w_in, w_out);
  k_mma<0><<<dim3(Bq/128, Dm/256, 19), 256, SMEM_SZ>>>(b_out, out);

  cudaStreamWaitEvent(0, g_evB, 0);
  k_mix<<<NBR * Bq * (Dm / 4) / 256, 256>>>(b_in);
  k_mma<1><<<dim3(Bq/128, Dm/256, NBR), 256, SMEM_SZ>>>(b_out, out);
}

// round 12
// speedup vs baseline: 7.8073x; 1.0806x over previous
#include <cuda_runtime.h>
#include <cuda_fp16.h>
#include <cstdint>

#define Bq 8192
#define Dm 1024
#define NBR 7
#define BD ((size_t)Bq * Dm)
#define DD ((size_t)Dm * Dm)

// ---------------- scratch (tiled, pre-swizzled fp16 planes: [kc][rows][32]) ----------------
__device__ float g_Q[NBR * Dm];
__device__ float g_SC[(size_t)4 * Bq * 256];
__device__ float g_A[(size_t)NBR * 4 * Bq * 16];
__device__ __align__(16) __half g_V[(size_t)19 * BD];     // v-proj results, fp16
__device__ __align__(16) __half g_Sh[256 * Dm];
__device__ __align__(16) __half g_Sl[256 * Dm];
__device__ __align__(16) __half g_Ah[4 * BD];
__device__ __align__(16) __half g_Al[4 * BD];
__device__ __align__(16) __half g_Wh[14 * DD];            // weights: single plane
__device__ __align__(16) __half g_Oh[NBR * BD];           // attn-out: single plane

__constant__ int c_nvec[NBR] = {2,2,2,3,3,3,4};
__constant__ int c_vidx[NBR][4] = {{0,1,0,0},{0,2,0,0},{0,3,0,0},{0,1,2,0},{0,1,3,0},{0,2,3,0},{0,1,2,3}};
__constant__ int c_poff[NBR] = {0,2,4,6,9,12,15};
__constant__ int c_pairi[19] = {0,0,1,1,2,2,3,3,3,4,4,4,5,5,5,6,6,6,6};
__constant__ int c_pairv[19] = {0,1,0,2,0,3,0,1,2,0,1,3,0,2,3,0,1,2,3};

// tiled+swizzled element offset within a [R rows x 1024 k] fp16 plane
__device__ __forceinline__ size_t toff(int row, int k, int R) {
  return ((size_t)(k >> 5) * R + row) * 32 +
         (((((k >> 3) & 3) ^ ((row >> 1) & 3)) << 3) + (k & 7));
}

// ---------------- PTX helpers ----------------
__device__ __forceinline__ uint32_t smem_u32(const void* p) {
  uint32_t a;
  asm("{ .reg .u64 t; cvta.to.shared.u64 t, %1; cvt.u32.u64 %0, t; }" : "=r"(a) : "l"(p));
  return a;
}
#define MBAR_INIT(a, n) asm volatile("mbarrier.init.shared.b64 [%0], %1;" :: "r"(a), "r"(n) : "memory")
#define MBAR_EXPECT(a, b) asm volatile("mbarrier.arrive.expect_tx.shared.b64 _, [%0], %1;" :: "r"(a), "r"(b) : "memory")
#define MBAR_ARRIVE(a) asm volatile("mbarrier.arrive.shared.b64 _, [%0];" :: "r"(a) : "memory")
#define MBAR_WAIT(a, ph) do { \
  uint32_t _m = (a), _p = (ph), _d; \
  asm volatile("{ .reg .pred p; mbarrier.try_wait.parity.acquire.cta.shared::cta.b64 p, [%1], %2; selp.b32 %0,1,0,p; }" \
    : "=r"(_d) : "r"(_m), "r"(_p) : "memory"); \
  if (!_d) { asm volatile("{ .reg .pred P1; WL_%=: mbarrier.try_wait.parity.acquire.cta.shared::cta.b64 P1, [%0], %1, 0x989680; @P1 bra.uni WD_%=; bra.uni WL_%=; WD_%=: }" \
    :: "r"(_m), "r"(_p) : "memory"); } } while (0)

__device__ __forceinline__ void bulk_g2s(uint32_t dst, const void* src, uint32_t bytes, uint32_t mbar) {
  asm volatile("cp.async.bulk.shared::cluster.global.mbarrier::complete_tx::bytes [%0], [%1], %2, [%3];"
               :: "r"(dst), "l"(src), "r"(bytes), "r"(mbar) : "memory");
}
__device__ __forceinline__ void ldsm4(uint32_t& r0, uint32_t& r1, uint32_t& r2, uint32_t& r3, uint32_t addr) {
  asm volatile("ldmatrix.sync.aligned.m8n8.x4.shared.b16 {%0,%1,%2,%3}, [%4];"
               : "=r"(r0), "=r"(r1), "=r"(r2), "=r"(r3) : "r"(addr));
}
__device__ __forceinline__ void mma_f16(float* c, const uint32_t* a, const uint32_t* b) {
  asm volatile("mma.sync.aligned.m16n8k16.row.col.f32.f16.f16.f32 "
               "{%0,%1,%2,%3}, {%4,%5,%6,%7}, {%8,%9}, {%0,%1,%2,%3};"
               : "+f"(c[0]), "+f"(c[1]), "+f"(c[2]), "+f"(c[3])
               : "r"(a[0]), "r"(a[1]), "r"(a[2]), "r"(a[3]), "r"(b[0]), "r"(b[1]));
}

// ======================= fp32 -> fp16 split/pack =======================
__device__ __forceinline__ void split4h(float4 v, uint2& hi, uint2& lo) {
  __half h0 = __float2half_rn(v.x), h1 = __float2half_rn(v.y);
  __half h2 = __float2half_rn(v.z), h3 = __float2half_rn(v.w);
  __half l0 = __float2half_rn(v.x - __half2float(h0));
  __half l1 = __float2half_rn(v.y - __half2float(h1));
  __half l2 = __float2half_rn(v.z - __half2float(h2));
  __half l3 = __float2half_rn(v.w - __half2float(h3));
  __half2 a{h0, h1}, b{h2, h3}, c{l0, l1}, d{l2, l3};
  hi = make_uint2(*(uint32_t*)&a, *(uint32_t*)&b);
  lo = make_uint2(*(uint32_t*)&c, *(uint32_t*)&d);
}
__device__ __forceinline__ uint2 pack4h(float4 v) {
  __half2 a{__float2half_rn(v.x), __float2half_rn(v.y)};
  __half2 b{__float2half_rn(v.z), __float2half_rn(v.w)};
  return make_uint2(*(uint32_t*)&a, *(uint32_t*)&b);
}

// ======================= prep / conversion kernels =======================
__global__ void k_qh(const float* __restrict__ tokens, const float* __restrict__ w_in,
                     const float* __restrict__ b_in) {
  int i = blockIdx.x, t = threadIdx.x;
  __shared__ float tok[Dm];
  for (int k = t; k < Dm; k += 256) tok[k] = tokens[i * Dm + k];
  __syncthreads();
  const float* wq = w_in + (size_t)i * 3 * DD;
  for (int r = t; r < Dm; r += 256) {
    const float* row = wq + (size_t)r * Dm;
    float acc = b_in[i * 3 * Dm + r];
    for (int k = 0; k < Dm; k += 4) {
      float4 w = *(const float4*)(row + k);
      acc += w.x*tok[k] + w.y*tok[k+1] + w.z*tok[k+2] + w.w*tok[k+3];
    }
    g_Q[i * Dm + r] = acc;
  }
}

__global__ void k_zs() {
  size_t i = ((size_t)blockIdx.x * 256 + threadIdx.x) * 4;
  *(uint2*)(g_Sh + i) = make_uint2(0, 0);
  *(uint2*)(g_Sl + i) = make_uint2(0, 0);
}

__global__ void k_s(const float* __restrict__ w_in) {
  int i = blockIdx.x, kb = blockIdx.y * 128;
  __shared__ float qh[Dm];
  for (int k = threadIdx.x; k < Dm; k += 256) qh[k] = g_Q[i * Dm + k];
  __syncthreads();
  const float* wk = w_in + (size_t)i * 3 * DD + DD;
  for (int o = threadIdx.x; o < 16 * 128; o += 256) {
    int h = o >> 7, k = kb + (o & 127);
    float acc = 0.f;
    #pragma unroll 8
    for (int j = 0; j < 64; j++) acc += wk[(size_t)(h * 64 + j) * Dm + k] * qh[h * 64 + j];
    float val = 0.125f * acc;
    __half hi = __float2half_rn(val);
    size_t off = toff(i * 16 + h, k, 256);
    g_Sh[off] = hi;
    g_Sl[off] = __float2half_rn(val - __half2float(hi));
  }
}

__global__ void k_softmax() {
  int idx = blockIdx.x * 256 + threadIdx.x;
  int h = idx & 15;
  int b = (idx >> 4) & (Bq - 1);
  int i = idx >> 17;
  int L = c_nvec[i];
  float sc[4];
  float mx = -1e30f;
  #pragma unroll
  for (int l = 0; l < 4; l++) if (l < L) {
    sc[l] = g_SC[((size_t)c_vidx[i][l] * Bq + b) * 256 + i * 16 + h];
    mx = fmaxf(mx, sc[l]);
  }
  float sum = 0.f;
  #pragma unroll
  for (int l = 0; l < 4; l++) if (l < L) { sc[l] = expf(sc[l] - mx); sum += sc[l]; }
  float inv = 1.f / sum;
  #pragma unroll
  for (int l = 0; l < 4; l++) if (l < L)
    g_A[(((size_t)i * 4 + l) * Bq + b) * 16 + h] = sc[l] * inv;
}

__global__ void k_mix(const float* __restrict__ b_in) {
  size_t gid = (size_t)blockIdx.x * 256 + threadIdx.x;
  int i = (int)(gid >> 21);
  int rem = (int)(gid & ((1u << 21) - 1));
  int b = rem >> 8;
  int k = (rem & 255) * 4;
  int h = k >> 6;
  int L = c_nvec[i];
  int p0 = c_poff[i];
  float4 o = *(const float4*)(b_in + ((size_t)i * 3 + 2) * Dm + k);
  #pragma unroll
  for (int l = 0; l < 4; l++) if (l < L) {
    float a = g_A[(((size_t)i * 4 + l) * Bq + b) * 16 + h];
    const __half2* vp = (const __half2*)(g_V + ((size_t)(p0 + l) * Bq + b) * Dm + k);
    float2 f01 = __half22float2(vp[0]);
    float2 f23 = __half22float2(vp[1]);
    o.x += a * f01.x; o.y += a * f01.y; o.z += a * f23.x; o.w += a * f23.y;
  }
  *(uint2*)(g_Oh + (size_t)i * BD + toff(b, k, Bq)) = pack4h(o);
}

__global__ void k_convA(const float* __restrict__ xc, const float* __restrict__ xf,
                        const float* __restrict__ xbd, const float* __restrict__ xbg) {
  int v = blockIdx.y;
  const float* x = (v == 0) ? xc : (v == 1) ? xf : (v == 2) ? xbd : xbg;
  size_t i = (size_t)blockIdx.x * 256 + threadIdx.x;
  int m = (int)(i >> 8), k = ((int)i & 255) * 4;
  float4 val = ((const float4*)x)[i];
  uint2 hi, lo; split4h(val, hi, lo);
  size_t off = (size_t)v * BD + toff(m, k, Bq);
  *(uint2*)(g_Ah + off) = hi;
  *(uint2*)(g_Al + off) = lo;
}

__global__ void k_convW(const float* __restrict__ w_in, const float* __restrict__ w_out) {
  int z = blockIdx.y;
  const float* src = (z < 7) ? (w_in + (size_t)z * 3 * DD + 2 * DD) : (w_out + (size_t)(z - 7) * DD);
  size_t i = (size_t)blockIdx.x * 256 + threadIdx.x;
  int n = (int)(i >> 8), k = ((int)i & 255) * 4;
  float4 val = ((const float4*)src)[i];
  *(uint2*)(g_Wh + (size_t)z * DD + toff(n, k, Dm)) = pack4h(val);
}

// ======================= bulk-copy fp16 HMMA GEMM (K-chunk 64, warp-desynced) =======================
// full mbar[s] at sb+8s (count 1, tx); empty mbar[s] at sb+128+8s (count 8, 1 arrive/warp).
// MODE 0 (v-proj): CTA 128x256, 1 term. Stage 48KB. C fp16.
// MODE 1 (out):    same, C fp32 + bias.
// MODE 2 (scores): CTA 128x128, 3 terms. Stage 64KB.
#define NCH 16
#define SMEM_SZ (1024 + 196608)

__device__ __forceinline__ uint32_t sw(uint32_t row, uint32_t g) {
  return row * 64 + ((g ^ ((row >> 1) & 3)) << 4);
}

template<int MODE>
__global__ void __launch_bounds__(256, 1) k_mma(const float* __restrict__ b_out,
                                                float* __restrict__ dout) {
  constexpr int STG = (MODE == 2) ? 65536 : 49152;
  constexpr int NS  = (MODE == 2) ? 3 : 4;
  constexpr int NT  = (MODE == 2) ? 4 : 8;
  extern __shared__ __align__(128) char smem[];
  const uint32_t sb = smem_u32(smem);
  const int tid = threadIdx.x;
  const int wid = tid >> 5, lane = tid & 31;
  const int m0 = blockIdx.x * 128;
  const int n0 = blockIdx.y * ((MODE == 2) ? 128 : 256);
  const int wm = (wid & 1) * 64, wn = (wid >> 1) * (NT * 8);
  const int cst = (MODE == 2) ? 256 : 1024;
  const int RB  = (MODE == 2) ? 256 : 1024;
  constexpr uint32_t BOFF = (MODE == 2) ? 32768 : 16384;

  const __half *Ah, *Al = nullptr, *Bh, *Bl = nullptr;
  float* C = nullptr; __half* Ch = nullptr; const float* bias = nullptr;
  if (MODE == 0) {
    int p = blockIdx.z;
    int v = c_pairv[p], wi = c_pairi[p];
    Ah = g_Ah + (size_t)v * BD;
    Bh = g_Wh + (size_t)wi * DD;
    Ch = g_V + (size_t)p * BD;
  } else if (MODE == 1) {
    int i = blockIdx.z;
    Ah = g_Oh + (size_t)i * BD;
    Bh = g_Wh + (size_t)(7 + i) * DD;
    C = dout + (size_t)i * BD;
    bias = b_out + i * Dm;
  } else {
    int v = blockIdx.z;
    Ah = g_Ah + (size_t)v * BD;  Al = g_Al + (size_t)v * BD;
    Bh = g_Sh; Bl = g_Sl;
    C = g_SC + (size_t)v * Bq * 256;
  }

  if (tid == 0) {
    #pragma unroll
    for (int s = 0; s < NS; s++) {
      MBAR_INIT(sb + s * 8, 1);          // full (tx-based)
      MBAR_INIT(sb + 128 + s * 8, 8);    // empty (8 warp arrivals)
    }
  }
  __syncthreads();

  auto issue = [&](int c) {
    int s = c % NS;
    uint32_t st = sb + 1024 + s * STG;
    uint32_t mb = sb + s * 8;
    MBAR_EXPECT(mb, STG);
    bulk_g2s(st,        Ah + ((size_t)(2*c)   * Bq + m0) * 32, 8192, mb);
    bulk_g2s(st + 8192, Ah + ((size_t)(2*c+1) * Bq + m0) * 32, 8192, mb);
    if (MODE == 2) {
      bulk_g2s(st + 16384, Al + ((size_t)(2*c)   * Bq + m0) * 32, 8192, mb);
      bulk_g2s(st + 24576, Al + ((size_t)(2*c+1) * Bq + m0) * 32, 8192, mb);
      bulk_g2s(st + 32768, Bh + ((size_t)(2*c)   * RB + n0) * 32, 8192, mb);
      bulk_g2s(st + 40960, Bh + ((size_t)(2*c+1) * RB + n0) * 32, 8192, mb);
      bulk_g2s(st + 49152, Bl + ((size_t)(2*c)   * RB + n0) * 32, 8192, mb);
      bulk_g2s(st + 57344, Bl + ((size_t)(2*c+1) * RB + n0) * 32, 8192, mb);
    } else {
      bulk_g2s(st + 16384, Bh + ((size_t)(2*c)   * RB + n0) * 32, 16384, mb);
      bulk_g2s(st + 32768, Bh + ((size_t)(2*c+1) * RB + n0) * 32, 16384, mb);
    }
  };
  if (tid == 0) {
    #pragma unroll
    for (int c = 0; c < NS; c++) issue(c);
  }

  float acc[4][NT][4];
  #pragma unroll
  for (int mt = 0; mt < 4; mt++)
    #pragma unroll
    for (int nt = 0; nt < NT; nt++)
      #pragma unroll
      for (int r = 0; r < 4; r++) acc[mt][nt][r] = 0.f;

  const int arow = wm + (lane & 15);
  const int agsel = lane >> 4;
  const int brow = wn + ((lane & 7) | ((lane & 16) >> 1));
  const int bgsel = (lane >> 3) & 1;

  for (int c = 0; c < NCH; c++) {
    const int s = c % NS;
    const uint32_t st = sb + 1024 + s * STG;
    MBAR_WAIT(sb + s * 8, (c / NS) & 1);
    #pragma unroll
    for (int ks = 0; ks < 4; ks++) {
      const int kp = ks >> 1, kk = (ks & 1) * 2;
      const uint32_t stA = st + kp * 8192;
      const uint32_t stB = st + BOFF + kp * ((MODE == 2) ? 8192 : 16384);
      uint32_t ah[4][4], al[4][4], bh[NT][2];
      #pragma unroll
      for (int mt = 0; mt < 4; mt++) {
        uint32_t ad = stA + sw(arow + mt * 16, kk + agsel);
        ldsm4(ah[mt][0], ah[mt][1], ah[mt][2], ah[mt][3], ad);
        if (MODE == 2) ldsm4(al[mt][0], al[mt][1], al[mt][2], al[mt][3], ad + 16384);
      }
      #pragma unroll
      for (int np = 0; np < NT / 2; np++) {
        uint32_t bd = stB + sw(brow + np * 16, kk + bgsel);
        ldsm4(bh[np*2][0], bh[np*2][1], bh[np*2+1][0], bh[np*2+1][1], bd);
      }
      uint32_t bl[NT][2];
      if (MODE == 2) {
        #pragma unroll
        for (int np = 0; np < NT / 2; np++) {
          uint32_t bd = stB + 16384 + sw(brow + np * 16, kk + bgsel);
          ldsm4(bl[np*2][0], bl[np*2][1], bl[np*2+1][0], bl[np*2+1][1], bd);
        }
      }
      #pragma unroll
      for (int mt = 0; mt < 4; mt++)
        #pragma unroll
        for (int nt = 0; nt < NT; nt++) {
          mma_f16(acc[mt][nt], ah[mt], bh[nt]);
          if (MODE == 2) {
            mma_f16(acc[mt][nt], al[mt], bh[nt]);
            mma_f16(acc[mt][nt], ah[mt], bl[nt]);
          }
        }
    }
    // this warp is done reading stage s
    if (lane == 0) MBAR_ARRIVE(sb + 128 + s * 8);
    // producer: refill stage s once all 8 warps have arrived
    if (tid == 0 && c + NS < NCH) {
      MBAR_WAIT(sb + 128 + s * 8, (c / NS) & 1);
      issue(c + NS);
    }
  }

  // epilogue
  #pragma unroll
  for (int mt = 0; mt < 4; mt++) {
    int m = m0 + wm + mt * 16 + (lane >> 2);
    #pragma unroll
    for (int nt = 0; nt < NT; nt++) {
      int n = n0 + wn + nt * 8 + (lane & 3) * 2;
      float2 v0 = make_float2(acc[mt][nt][0], acc[mt][nt][1]);
      float2 v1 = make_float2(acc[mt][nt][2], acc[mt][nt][3]);
      if (MODE == 0) {
        __half2 h0{__float2half_rn(v0.x), __float2half_rn(v0.y)};
        __half2 h1{__float2half_rn(v1.x), __float2half_rn(v1.y)};
        *(__half2*)(Ch + (size_t)m * 1024 + n) = h0;
        *(__half2*)(Ch + (size_t)(m + 8) * 1024 + n) = h1;
      } else {
        if (MODE == 1) {
          float b0 = __ldg(bias + n), b1 = __ldg(bias + n + 1);
          v0.x += b0; v0.y += b1; v1.x += b0; v1.y += b1;
        }
        *(float2*)(C + (size_t)m * cst + n) = v0;
        *(float2*)(C + (size_t)(m + 8) * cst + n) = v1;
      }
    }
  }
}

// ======================= streams (created pre-main; capture-safe reuse) =======================
static cudaStream_t g_s1;
static cudaEvent_t g_evA, g_evB;
namespace {
struct StreamInit {
  StreamInit() {
    cudaStreamCreateWithFlags(&g_s1, cudaStreamNonBlocking);
    cudaEventCreateWithFlags(&g_evA, cudaEventDisableTiming);
    cudaEventCreateWithFlags(&g_evB, cudaEventDisableTiming);
  }
};
StreamInit g_si;
}

// ======================================================================
extern "C" void kernel_launch(void* const* d_in, const int* in_sizes, int n_in,
                              void* d_out, int out_size) {
  const float* xc     = (const float*)d_in[0];
  const float* xf     = (const float*)d_in[1];
  const float* xbd    = (const float*)d_in[2];
  const float* xbg    = (const float*)d_in[3];
  const float* tokens = (const float*)d_in[4];
  const float* w_in   = (const float*)d_in[5];
  const float* b_in   = (const float*)d_in[6];
  const float* w_out  = (const float*)d_in[7];
  const float* b_out  = (const float*)d_in[8];
  float* out = (float*)d_out;

  cudaFuncSetAttribute(k_mma<0>, cudaFuncAttributeMaxDynamicSharedMemorySize, SMEM_SZ);
  cudaFuncSetAttribute(k_mma<1>, cudaFuncAttributeMaxDynamicSharedMemorySize, SMEM_SZ);
  cudaFuncSetAttribute(k_mma<2>, cudaFuncAttributeMaxDynamicSharedMemorySize, SMEM_SZ);

  // main stream: conversions, then the big v-proj GEMM
  k_convA<<<dim3(Bq, 4), 256>>>(xc, xf, xbd, xbg);
  cudaEventRecord(g_evA, 0);

  // side stream: scores pipeline (independent of MODE0), joined before k_mix
  cudaStreamWaitEvent(g_s1, g_evA, 0);
  k_qh<<<NBR, 256, 0, g_s1>>>(tokens, w_in, b_in);
  k_zs<<<256, 256, 0, g_s1>>>();
  k_s<<<dim3(NBR, 8), 256, 0, g_s1>>>(w_in);
  k_mma<2><<<dim3(Bq/128, 2, 4), 256, SMEM_SZ, g_s1>>>(b_out, out);
  k_softmax<<<NBR * Bq * 16 / 256, 256, 0, g_s1>>>();
  cudaEventRecord(g_evB, g_s1);

  k_convW<<<dim3(1024, 14), 256>>>(w_in, w_out);
  k_mma<0><<<dim3(Bq/128, Dm/256, 19), 256, SMEM_SZ>>>(b_out, out);

  cudaStreamWaitEvent(0, g_evB, 0);
  k_mix<<<NBR * Bq * (Dm / 4) / 256, 256>>>(b_in);
  k_mma<1><<<dim3(Bq/128, Dm/256, NBR), 256, SMEM_SZ>>>(b_out, out);
}

// round 13
// speedup vs baseline: 8.0504x; 1.0311x over previous
#include <cuda_runtime.h>
#include <cuda_fp16.h>
#include <cstdint>

#define Bq 8192
#define Dm 1024
#define NBR 7
#define BD ((size_t)Bq * Dm)
#define DD ((size_t)Dm * Dm)

// ---------------- scratch (tiled, pre-swizzled fp16 planes: [kc][rows][32]) ----------------
__device__ float g_Q[NBR * Dm];
__device__ float g_SC[(size_t)4 * Bq * 256];
__device__ float g_A[(size_t)NBR * 4 * Bq * 16];
__device__ __align__(16) __half g_V[(size_t)19 * BD];
__device__ __align__(16) __half g_Sh[256 * Dm];
__device__ __align__(16) __half g_Sl[256 * Dm];
__device__ __align__(16) __half g_Ah[4 * BD];
__device__ __align__(16) __half g_Al[4 * BD];
__device__ __align__(16) __half g_Wh[14 * DD];
__device__ __align__(16) __half g_Oh[NBR * BD];

__constant__ int c_nvec[NBR] = {2,2,2,3,3,3,4};
__constant__ int c_vidx[NBR][4] = {{0,1,0,0},{0,2,0,0},{0,3,0,0},{0,1,2,0},{0,1,3,0},{0,2,3,0},{0,1,2,3}};
__constant__ int c_poff[NBR] = {0,2,4,6,9,12,15};
__constant__ int c_pairi[19] = {0,0,1,1,2,2,3,3,3,4,4,4,5,5,5,6,6,6,6};
__constant__ int c_pairv[19] = {0,1,0,2,0,3,0,1,2,0,1,3,0,2,3,0,1,2,3};

__device__ __forceinline__ size_t toff(int row, int k, int R) {
  return ((size_t)(k >> 5) * R + row) * 32 +
         (((((k >> 3) & 3) ^ ((row >> 1) & 3)) << 3) + (k & 7));
}

// ---------------- PTX helpers ----------------
__device__ __forceinline__ uint32_t smem_u32(const void* p) {
  uint32_t a;
  asm("{ .reg .u64 t; cvta.to.shared.u64 t, %1; cvt.u32.u64 %0, t; }" : "=r"(a) : "l"(p));
  return a;
}
#define MBAR_INIT(a, n) asm volatile("mbarrier.init.shared.b64 [%0], %1;" :: "r"(a), "r"(n) : "memory")
#define MBAR_EXPECT(a, b) asm volatile("mbarrier.arrive.expect_tx.shared.b64 _, [%0], %1;" :: "r"(a), "r"(b) : "memory")
#define MBAR_ARRIVE(a) asm volatile("mbarrier.arrive.shared.b64 _, [%0];" :: "r"(a) : "memory")
#define MBAR_WAIT(a, ph) do { \
  uint32_t _m = (a), _p = (ph), _d; \
  asm volatile("{ .reg .pred p; mbarrier.try_wait.parity.acquire.cta.shared::cta.b64 p, [%1], %2; selp.b32 %0,1,0,p; }" \
    : "=r"(_d) : "r"(_m), "r"(_p) : "memory"); \
  if (!_d) { asm volatile("{ .reg .pred P1; WL_%=: mbarrier.try_wait.parity.acquire.cta.shared::cta.b64 P1, [%0], %1, 0x989680; @P1 bra.uni WD_%=; bra.uni WL_%=; WD_%=: }" \
    :: "r"(_m), "r"(_p) : "memory"); } } while (0)

__device__ __forceinline__ void bulk_g2s(uint32_t dst, const void* src, uint32_t bytes, uint32_t mbar) {
  asm volatile("cp.async.bulk.shared::cluster.global.mbarrier::complete_tx::bytes [%0], [%1], %2, [%3];"
               :: "r"(dst), "l"(src), "r"(bytes), "r"(mbar) : "memory");
}
__device__ __forceinline__ void ldsm4(uint32_t& r0, uint32_t& r1, uint32_t& r2, uint32_t& r3, uint32_t addr) {
  asm volatile("ldmatrix.sync.aligned.m8n8.x4.shared.b16 {%0,%1,%2,%3}, [%4];"
               : "=r"(r0), "=r"(r1), "=r"(r2), "=r"(r3) : "r"(addr));
}
__device__ __forceinline__ void mma_f16(float* c, const uint32_t* a, const uint32_t* b) {
  asm volatile("mma.sync.aligned.m16n8k16.row.col.f32.f16.f16.f32 "
               "{%0,%1,%2,%3}, {%4,%5,%6,%7}, {%8,%9}, {%0,%1,%2,%3};"
               : "+f"(c[0]), "+f"(c[1]), "+f"(c[2]), "+f"(c[3])
               : "r"(a[0]), "r"(a[1]), "r"(a[2]), "r"(a[3]), "r"(b[0]), "r"(b[1]));
}

// ======================= fp32 -> fp16 split/pack =======================
__device__ __forceinline__ void split4h(float4 v, uint2& hi, uint2& lo) {
  __half h0 = __float2half_rn(v.x), h1 = __float2half_rn(v.y);
  __half h2 = __float2half_rn(v.z), h3 = __float2half_rn(v.w);
  __half l0 = __float2half_rn(v.x - __half2float(h0));
  __half l1 = __float2half_rn(v.y - __half2float(h1));
  __half l2 = __float2half_rn(v.z - __half2float(h2));
  __half l3 = __float2half_rn(v.w - __half2float(h3));
  __half2 a{h0, h1}, b{h2, h3}, c{l0, l1}, d{l2, l3};
  hi = make_uint2(*(uint32_t*)&a, *(uint32_t*)&b);
  lo = make_uint2(*(uint32_t*)&c, *(uint32_t*)&d);
}
__device__ __forceinline__ uint2 pack4h(float4 v) {
  __half2 a{__float2half_rn(v.x), __float2half_rn(v.y)};
  __half2 b{__float2half_rn(v.z), __float2half_rn(v.w)};
  return make_uint2(*(uint32_t*)&a, *(uint32_t*)&b);
}

// ======================= prep / conversion kernels =======================
// warp-per-row qh: grid (NBR, 16), 256 thr
__global__ void k_qh(const float* __restrict__ tokens, const float* __restrict__ w_in,
                     const float* __restrict__ b_in) {
  int i = blockIdx.x, rb = blockIdx.y, tid = threadIdx.x;
  int wid = tid >> 5, lane = tid & 31;
  __shared__ float tok[Dm];
  for (int k = tid; k < Dm; k += 256) tok[k] = tokens[i * Dm + k];
  __syncthreads();
  const float* wq = w_in + (size_t)i * 3 * DD;
  #pragma unroll
  for (int rr = 0; rr < 8; rr++) {
    int r = rb * 64 + wid * 8 + rr;
    const float4* row = (const float4*)(wq + (size_t)r * Dm);
    float acc = 0.f;
    #pragma unroll
    for (int j = 0; j < 8; j++) {
      float4 w = row[lane + j * 32];
      float4 t = *(const float4*)&tok[(lane + j * 32) * 4];
      acc += w.x * t.x + w.y * t.y + w.z * t.z + w.w * t.w;
    }
    #pragma unroll
    for (int o = 16; o; o >>= 1) acc += __shfl_xor_sync(0xFFFFFFFFu, acc, o);
    if (lane == 0) g_Q[i * Dm + r] = acc + b_in[i * 3 * Dm + r];
  }
}

__global__ void k_zs() {
  size_t i = ((size_t)blockIdx.x * 256 + threadIdx.x) * 4;
  *(uint2*)(g_Sh + i) = make_uint2(0, 0);
  *(uint2*)(g_Sl + i) = make_uint2(0, 0);
}

// thread-per-(ih,k): grid (112, 4), 256 thr
__global__ void k_s(const float* __restrict__ w_in) {
  int ih = blockIdx.x, tid = threadIdx.x;
  int i = ih >> 4, h = ih & 15;
  int k = blockIdx.y * 256 + tid;
  __shared__ float qh[64];
  if (tid < 64) qh[tid] = g_Q[i * Dm + h * 64 + tid];
  __syncthreads();
  const float* wk = w_in + (size_t)i * 3 * DD + DD + (size_t)(h * 64) * Dm + k;
  float acc = 0.f;
  #pragma unroll 8
  for (int j = 0; j < 64; j++) acc += wk[(size_t)j * Dm] * qh[j];
  float val = 0.125f * acc;
  __half hi = __float2half_rn(val);
  size_t off = toff(ih, k, 256);
  g_Sh[off] = hi;
  g_Sl[off] = __float2half_rn(val - __half2float(hi));
}

__global__ void k_softmax() {
  int idx = blockIdx.x * 256 + threadIdx.x;
  int h = idx & 15;
  int b = (idx >> 4) & (Bq - 1);
  int i = idx >> 17;
  int L = c_nvec[i];
  float sc[4];
  float mx = -1e30f;
  #pragma unroll
  for (int l = 0; l < 4; l++) if (l < L) {
    sc[l] = g_SC[((size_t)c_vidx[i][l] * Bq + b) * 256 + i * 16 + h];
    mx = fmaxf(mx, sc[l]);
  }
  float sum = 0.f;
  #pragma unroll
  for (int l = 0; l < 4; l++) if (l < L) { sc[l] = expf(sc[l] - mx); sum += sc[l]; }
  float inv = 1.f / sum;
  #pragma unroll
  for (int l = 0; l < 4; l++) if (l < L)
    g_A[(((size_t)i * 4 + l) * Bq + b) * 16 + h] = sc[l] * inv;
}

// per-branch mix: grid 8192, 256 thr
__global__ void k_mix(const float* __restrict__ b_in, int i) {
  int gid = blockIdx.x * 256 + threadIdx.x;
  int b = gid >> 8;
  int k = (gid & 255) * 4;
  int h = k >> 6;
  int L = c_nvec[i];
  int p0 = c_poff[i];
  float4 o = *(const float4*)(b_in + ((size_t)i * 3 + 2) * Dm + k);
  #pragma unroll
  for (int l = 0; l < 4; l++) if (l < L) {
    float a = g_A[(((size_t)i * 4 + l) * Bq + b) * 16 + h];
    const __half2* vp = (const __half2*)(g_V + ((size_t)(p0 + l) * Bq + b) * Dm + k);
    float2 f01 = __half22float2(vp[0]);
    float2 f23 = __half22float2(vp[1]);
    o.x += a * f01.x; o.y += a * f01.y; o.z += a * f23.x; o.w += a * f23.y;
  }
  *(uint2*)(g_Oh + (size_t)i * BD + toff(b, k, Bq)) = pack4h(o);
}

__global__ void k_convA(const float* __restrict__ xc, const float* __restrict__ xf,
                        const float* __restrict__ xbd, const float* __restrict__ xbg) {
  int v = blockIdx.y;
  const float* x = (v == 0) ? xc : (v == 1) ? xf : (v == 2) ? xbd : xbg;
  size_t i = (size_t)blockIdx.x * 256 + threadIdx.x;
  int m = (int)(i >> 8), k = ((int)i & 255) * 4;
  float4 val = ((const float4*)x)[i];
  uint2 hi, lo; split4h(val, hi, lo);
  size_t off = (size_t)v * BD + toff(m, k, Bq);
  *(uint2*)(g_Ah + off) = hi;
  *(uint2*)(g_Al + off) = lo;
}

__global__ void k_convW(const float* __restrict__ w_in, const float* __restrict__ w_out) {
  int z = blockIdx.y;
  const float* src = (z < 7) ? (w_in + (size_t)z * 3 * DD + 2 * DD) : (w_out + (size_t)(z - 7) * DD);
  size_t i = (size_t)blockIdx.x * 256 + threadIdx.x;
  int n = (int)(i >> 8), k = ((int)i & 255) * 4;
  float4 val = ((const float4*)src)[i];
  *(uint2*)(g_Wh + (size_t)z * DD + toff(n, k, Dm)) = pack4h(val);
}

// ======================= bulk-copy fp16 HMMA GEMM (K-chunk 64, warp-desynced) =======================
#define NCH 16
#define SMEM_SZ (1024 + 196608)

__device__ __forceinline__ uint32_t sw(uint32_t row, uint32_t g) {
  return row * 64 + ((g ^ ((row >> 1) & 3)) << 4);
}

template<int MODE>
__global__ void __launch_bounds__(256, 1) k_mma(const float* __restrict__ b_out,
                                                float* __restrict__ dout, int zoff) {
  constexpr int STG = (MODE == 2) ? 65536 : 49152;
  constexpr int NS  = (MODE == 2) ? 3 : 4;
  constexpr int NT  = (MODE == 2) ? 4 : 8;
  extern __shared__ __align__(128) char smem[];
  const uint32_t sb = smem_u32(smem);
  const int tid = threadIdx.x;
  const int wid = tid >> 5, lane = tid & 31;
  const int m0 = blockIdx.x * 128;
  const int n0 = blockIdx.y * ((MODE == 2) ? 128 : 256);
  const int wm = (wid & 1) * 64, wn = (wid >> 1) * (NT * 8);
  const int cst = (MODE == 2) ? 256 : 1024;
  const int RB  = (MODE == 2) ? 256 : 1024;
  constexpr uint32_t BOFF = (MODE == 2) ? 32768 : 16384;

  const __half *Ah, *Al = nullptr, *Bh, *Bl = nullptr;
  float* C = nullptr; __half* Ch = nullptr; const float* bias = nullptr;
  if (MODE == 0) {
    int p = zoff + blockIdx.z;
    int v = c_pairv[p], wi = c_pairi[p];
    Ah = g_Ah + (size_t)v * BD;
    Bh = g_Wh + (size_t)wi * DD;
    Ch = g_V + (size_t)p * BD;
  } else if (MODE == 1) {
    int i = zoff;
    Ah = g_Oh + (size_t)i * BD;
    Bh = g_Wh + (size_t)(7 + i) * DD;
    C = dout + (size_t)i * BD;
    bias = b_out + i * Dm;
  } else {
    int v = blockIdx.z;
    Ah = g_Ah + (size_t)v * BD;  Al = g_Al + (size_t)v * BD;
    Bh = g_Sh; Bl = g_Sl;
    C = g_SC + (size_t)v * Bq * 256;
  }

  if (tid == 0) {
    #pragma unroll
    for (int s = 0; s < NS; s++) {
      MBAR_INIT(sb + s * 8, 1);
      MBAR_INIT(sb + 128 + s * 8, 8);
    }
  }
  __syncthreads();

  auto issue = [&](int c) {
    int s = c % NS;
    uint32_t st = sb + 1024 + s * STG;
    uint32_t mb = sb + s * 8;
    MBAR_EXPECT(mb, STG);
    bulk_g2s(st,        Ah + ((size_t)(2*c)   * Bq + m0) * 32, 8192, mb);
    bulk_g2s(st + 8192, Ah + ((size_t)(2*c+1) * Bq + m0) * 32, 8192, mb);
    if (MODE == 2) {
      bulk_g2s(st + 16384, Al + ((size_t)(2*c)   * Bq + m0) * 32, 8192, mb);
      bulk_g2s(st + 24576, Al + ((size_t)(2*c+1) * Bq + m0) * 32, 8192, mb);
      bulk_g2s(st + 32768, Bh + ((size_t)(2*c)   * RB + n0) * 32, 8192, mb);
      bulk_g2s(st + 40960, Bh + ((size_t)(2*c+1) * RB + n0) * 32, 8192, mb);
      bulk_g2s(st + 49152, Bl + ((size_t)(2*c)   * RB + n0) * 32, 8192, mb);
      bulk_g2s(st + 57344, Bl + ((size_t)(2*c+1) * RB + n0) * 32, 8192, mb);
    } else {
      bulk_g2s(st + 16384, Bh + ((size_t)(2*c)   * RB + n0) * 32, 16384, mb);
      bulk_g2s(st + 32768, Bh + ((size_t)(2*c+1) * RB + n0) * 32, 16384, mb);
    }
  };
  if (tid == 0) {
    #pragma unroll
    for (int c = 0; c < NS; c++) issue(c);
  }

  float acc[4][NT][4];
  #pragma unroll
  for (int mt = 0; mt < 4; mt++)
    #pragma unroll
    for (int nt = 0; nt < NT; nt++)
      #pragma unroll
      for (int r = 0; r < 4; r++) acc[mt][nt][r] = 0.f;

  const int arow = wm + (lane & 15);
  const int agsel = lane >> 4;
  const int brow = wn + ((lane & 7) | ((lane & 16) >> 1));
  const int bgsel = (lane >> 3) & 1;

  for (int c = 0; c < NCH; c++) {
    const int s = c % NS;
    const uint32_t st = sb + 1024 + s * STG;
    MBAR_WAIT(sb + s * 8, (c / NS) & 1);
    #pragma unroll
    for (int ks = 0; ks < 4; ks++) {
      const int kp = ks >> 1, kk = (ks & 1) * 2;
      const uint32_t stA = st + kp * 8192;
      const uint32_t stB = st + BOFF + kp * ((MODE == 2) ? 8192 : 16384);
      uint32_t ah[4][4], al[4][4], bh[NT][2];
      #pragma unroll
      for (int mt = 0; mt < 4; mt++) {
        uint32_t ad = stA + sw(arow + mt * 16, kk + agsel);
        ldsm4(ah[mt][0], ah[mt][1], ah[mt][2], ah[mt][3], ad);
        if (MODE == 2) ldsm4(al[mt][0], al[mt][1], al[mt][2], al[mt][3], ad + 16384);
      }
      #pragma unroll
      for (int np = 0; np < NT / 2; np++) {
        uint32_t bd = stB + sw(brow + np * 16, kk + bgsel);
        ldsm4(bh[np*2][0], bh[np*2][1], bh[np*2+1][0], bh[np*2+1][1], bd);
      }
      uint32_t bl[NT][2];
      if (MODE == 2) {
        #pragma unroll
        for (int np = 0; np < NT / 2; np++) {
          uint32_t bd = stB + 16384 + sw(brow + np * 16, kk + bgsel);
          ldsm4(bl[np*2][0], bl[np*2][1], bl[np*2+1][0], bl[np*2+1][1], bd);
        }
      }
      #pragma unroll
      for (int mt = 0; mt < 4; mt++)
        #pragma unroll
        for (int nt = 0; nt < NT; nt++) {
          mma_f16(acc[mt][nt], ah[mt], bh[nt]);
          if (MODE == 2) {
            mma_f16(acc[mt][nt], al[mt], bh[nt]);
            mma_f16(acc[mt][nt], ah[mt], bl[nt]);
          }
        }
    }
    if (lane == 0) MBAR_ARRIVE(sb + 128 + s * 8);
    if (tid == 0 && c + NS < NCH) {
      MBAR_WAIT(sb + 128 + s * 8, (c / NS) & 1);
      issue(c + NS);
    }
  }

  // epilogue
  #pragma unroll
  for (int mt = 0; mt < 4; mt++) {
    int m = m0 + wm + mt * 16 + (lane >> 2);
    #pragma unroll
    for (int nt = 0; nt < NT; nt++) {
      int n = n0 + wn + nt * 8 + (lane & 3) * 2;
      float2 v0 = make_float2(acc[mt][nt][0], acc[mt][nt][1]);
      float2 v1 = make_float2(acc[mt][nt][2], acc[mt][nt][3]);
      if (MODE == 0) {
        __half2 h0{__float2half_rn(v0.x), __float2half_rn(v0.y)};
        __half2 h1{__float2half_rn(v1.x), __float2half_rn(v1.y)};
        *(__half2*)(Ch + (size_t)m * 1024 + n) = h0;
        *(__half2*)(Ch + (size_t)(m + 8) * 1024 + n) = h1;
      } else {
        if (MODE == 1) {
          float b0 = __ldg(bias + n), b1 = __ldg(bias + n + 1);
          v0.x += b0; v0.y += b1; v1.x += b0; v1.y += b1;
        }
        *(float2*)(C + (size_t)m * cst + n) = v0;
        *(float2*)(C + (size_t)(m + 8) * cst + n) = v1;
      }
    }
  }
}

// ======================= streams / events (created pre-main; capture-safe reuse) =======================
static cudaStream_t g_s1, g_s2;
static cudaEvent_t g_evF, g_evA, g_evW, g_evSM, g_evM0[NBR], g_evDone;
namespace {
struct StreamInit {
  StreamInit() {
    cudaStreamCreateWithFlags(&g_s1, cudaStreamNonBlocking);
    cudaStreamCreateWithFlags(&g_s2, cudaStreamNonBlocking);
    cudaEventCreateWithFlags(&g_evF, cudaEventDisableTiming);
    cudaEventCreateWithFlags(&g_evA, cudaEventDisableTiming);
    cudaEventCreateWithFlags(&g_evW, cudaEventDisableTiming);
    cudaEventCreateWithFlags(&g_evSM, cudaEventDisableTiming);
    for (int b = 0; b < NBR; b++) cudaEventCreateWithFlags(&g_evM0[b], cudaEventDisableTiming);
    cudaEventCreateWithFlags(&g_evDone, cudaEventDisableTiming);
  }
};
StreamInit g_si;
}

// ======================================================================
extern "C" void kernel_launch(void* const* d_in, const int* in_sizes, int n_in,
                              void* d_out, int out_size) {
  const float* xc     = (const float*)d_in[0];
  const float* xf     = (const float*)d_in[1];
  const float* xbd    = (const float*)d_in[2];
  const float* xbg    = (const float*)d_in[3];
  const float* tokens = (const float*)d_in[4];
  const float* w_in   = (const float*)d_in[5];
  const float* b_in   = (const float*)d_in[6];
  const float* w_out  = (const float*)d_in[7];
  const float* b_out  = (const float*)d_in[8];
  float* out = (float*)d_out;

  static const int h_poff[NBR] = {0,2,4,6,9,12,15};
  static const int h_nvec[NBR] = {2,2,2,3,3,3,4};
  static const int h_ord[NBR]  = {6,3,4,5,0,1,2};   // big branches first

  cudaFuncSetAttribute(k_mma<0>, cudaFuncAttributeMaxDynamicSharedMemorySize, SMEM_SZ);
  cudaFuncSetAttribute(k_mma<1>, cudaFuncAttributeMaxDynamicSharedMemorySize, SMEM_SZ);
  cudaFuncSetAttribute(k_mma<2>, cudaFuncAttributeMaxDynamicSharedMemorySize, SMEM_SZ);

  // fork point
  cudaEventRecord(g_evF, 0);

  // s1: weight conversion (independent of convA)
  cudaStreamWaitEvent(g_s1, g_evF, 0);
  k_convW<<<dim3(1024, 14), 256, 0, g_s1>>>(w_in, w_out);
  cudaEventRecord(g_evW, g_s1);

  // s2: score-vector chain (qh/zs/s need only raw inputs)
  cudaStreamWaitEvent(g_s2, g_evF, 0);
  k_qh<<<dim3(NBR, 16), 256, 0, g_s2>>>(tokens, w_in, b_in);
  k_zs<<<256, 256, 0, g_s2>>>();
  k_s<<<dim3(112, 4), 256, 0, g_s2>>>(w_in);

  // main: activation conversion
  k_convA<<<dim3(Bq, 4), 256>>>(xc, xf, xbd, xbg);
  cudaEventRecord(g_evA, 0);

  // s2: scores GEMM + softmax (needs convA)
  cudaStreamWaitEvent(g_s2, g_evA, 0);
  k_mma<2><<<dim3(Bq/128, 2, 4), 256, SMEM_SZ, g_s2>>>(b_out, out, 0);
  k_softmax<<<NBR * Bq * 16 / 256, 256, 0, g_s2>>>();
  cudaEventRecord(g_evSM, g_s2);

  // main: per-branch v-projections
  cudaStreamWaitEvent(0, g_evW, 0);
  for (int t = 0; t < NBR; t++) {
    int b = h_ord[t];
    k_mma<0><<<dim3(Bq/128, Dm/256, h_nvec[b]), 256, SMEM_SZ>>>(b_out, out, h_poff[b]);
    cudaEventRecord(g_evM0[b], 0);
  }

  // s1: per-branch mix + out-projection, pipelined against MODE0
  cudaStreamWaitEvent(g_s1, g_evSM, 0);
  for (int t = 0; t < NBR; t++) {
    int b = h_ord[t];
    cudaStreamWaitEvent(g_s1, g_evM0[b], 0);
    k_mix<<<Bq, 256, 0, g_s1>>>(b_in, b);
    k_mma<1><<<dim3(Bq/128, Dm/256, 1), 256, SMEM_SZ, g_s1>>>(b_out, out, b);
  }
  cudaEventRecord(g_evDone, g_s1);
  cudaStreamWaitEvent(0, g_evDone, 0);
}

// round 14
// speedup vs baseline: 8.3316x; 1.0349x over previous
#include <cuda_runtime.h>
#include <cuda_fp16.h>
#include <cstdint>

#define Bq 8192
#define Dm 1024
#define NBR 7
#define BD ((size_t)Bq * Dm)
#define DD ((size_t)Dm * Dm)

// ---------------- scratch (tiled, pre-swizzled fp16 planes: [kc][rows][32]) ----------------
__device__ float g_Q[NBR * Dm];
__device__ float g_SC[(size_t)4 * Bq * 256];
__device__ float g_A[(size_t)NBR * 4 * Bq * 16];
__device__ __align__(16) __half g_V[(size_t)19 * BD];
__device__ __align__(16) __half g_Sh[256 * Dm];
__device__ __align__(16) __half g_Sl[256 * Dm];
__device__ __align__(16) __half g_Ah[4 * BD];
__device__ __align__(16) __half g_Wh[14 * DD];
__device__ __align__(16) __half g_Oh[NBR * BD];

__constant__ int c_nvec[NBR] = {2,2,2,3,3,3,4};
__constant__ int c_vidx[NBR][4] = {{0,1,0,0},{0,2,0,0},{0,3,0,0},{0,1,2,0},{0,1,3,0},{0,2,3,0},{0,1,2,3}};
__constant__ int c_poff[NBR] = {0,2,4,6,9,12,15};
__constant__ int c_pairi[19] = {0,0,1,1,2,2,3,3,3,4,4,4,5,5,5,6,6,6,6};
__constant__ int c_pairv[19] = {0,1,0,2,0,3,0,1,2,0,1,3,0,2,3,0,1,2,3};

__device__ __forceinline__ size_t toff(int row, int k, int R) {
  return ((size_t)(k >> 5) * R + row) * 32 +
         (((((k >> 3) & 3) ^ ((row >> 1) & 3)) << 3) + (k & 7));
}

// ---------------- PTX helpers ----------------
__device__ __forceinline__ uint32_t smem_u32(const void* p) {
  uint32_t a;
  asm("{ .reg .u64 t; cvta.to.shared.u64 t, %1; cvt.u32.u64 %0, t; }" : "=r"(a) : "l"(p));
  return a;
}
#define MBAR_INIT(a, n) asm volatile("mbarrier.init.shared.b64 [%0], %1;" :: "r"(a), "r"(n) : "memory")
#define MBAR_EXPECT(a, b) asm volatile("mbarrier.arrive.expect_tx.shared.b64 _, [%0], %1;" :: "r"(a), "r"(b) : "memory")
#define MBAR_ARRIVE(a) asm volatile("mbarrier.arrive.shared.b64 _, [%0];" :: "r"(a) : "memory")
#define MBAR_WAIT(a, ph) do { \
  uint32_t _m = (a), _p = (ph), _d; \
  asm volatile("{ .reg .pred p; mbarrier.try_wait.parity.acquire.cta.shared::cta.b64 p, [%1], %2; selp.b32 %0,1,0,p; }" \
    : "=r"(_d) : "r"(_m), "r"(_p) : "memory"); \
  if (!_d) { asm volatile("{ .reg .pred P1; WL_%=: mbarrier.try_wait.parity.acquire.cta.shared::cta.b64 P1, [%0], %1, 0x989680; @P1 bra.uni WD_%=; bra.uni WL_%=; WD_%=: }" \
    :: "r"(_m), "r"(_p) : "memory"); } } while (0)

__device__ __forceinline__ void bulk_g2s(uint32_t dst, const void* src, uint32_t bytes, uint32_t mbar) {
  asm volatile("cp.async.bulk.shared::cluster.global.mbarrier::complete_tx::bytes [%0], [%1], %2, [%3];"
               :: "r"(dst), "l"(src), "r"(bytes), "r"(mbar) : "memory");
}
__device__ __forceinline__ void ldsm4(uint32_t& r0, uint32_t& r1, uint32_t& r2, uint32_t& r3, uint32_t addr) {
  asm volatile("ldmatrix.sync.aligned.m8n8.x4.shared.b16 {%0,%1,%2,%3}, [%4];"
               : "=r"(r0), "=r"(r1), "=r"(r2), "=r"(r3) : "r"(addr));
}
__device__ __forceinline__ void mma_f16(float* c, const uint32_t* a, const uint32_t* b) {
  asm volatile("mma.sync.aligned.m16n8k16.row.col.f32.f16.f16.f32 "
               "{%0,%1,%2,%3}, {%4,%5,%6,%7}, {%8,%9}, {%0,%1,%2,%3};"
               : "+f"(c[0]), "+f"(c[1]), "+f"(c[2]), "+f"(c[3])
               : "r"(a[0]), "r"(a[1]), "r"(a[2]), "r"(a[3]), "r"(b[0]), "r"(b[1]));
}

// ======================= fp32 -> fp16 pack =======================
__device__ __forceinline__ uint2 pack4h(float4 v) {
  __half2 a{__float2half_rn(v.x), __float2half_rn(v.y)};
  __half2 b{__float2half_rn(v.z), __float2half_rn(v.w)};
  return make_uint2(*(uint32_t*)&a, *(uint32_t*)&b);
}

// ======================= prep / conversion kernels =======================
__global__ void k_qh(const float* __restrict__ tokens, const float* __restrict__ w_in,
                     const float* __restrict__ b_in) {
  int i = blockIdx.x, rb = blockIdx.y, tid = threadIdx.x;
  int wid = tid >> 5, lane = tid & 31;
  __shared__ float tok[Dm];
  for (int k = tid; k < Dm; k += 256) tok[k] = tokens[i * Dm + k];
  __syncthreads();
  const float* wq = w_in + (size_t)i * 3 * DD;
  #pragma unroll
  for (int rr = 0; rr < 8; rr++) {
    int r = rb * 64 + wid * 8 + rr;
    const float4* row = (const float4*)(wq + (size_t)r * Dm);
    float acc = 0.f;
    #pragma unroll
    for (int j = 0; j < 8; j++) {
      float4 w = row[lane + j * 32];
      float4 t = *(const float4*)&tok[(lane + j * 32) * 4];
      acc += w.x * t.x + w.y * t.y + w.z * t.z + w.w * t.w;
    }
    #pragma unroll
    for (int o = 16; o; o >>= 1) acc += __shfl_xor_sync(0xFFFFFFFFu, acc, o);
    if (lane == 0) g_Q[i * Dm + r] = acc + b_in[i * 3 * Dm + r];
  }
}

__global__ void k_zs() {
  size_t i = ((size_t)blockIdx.x * 256 + threadIdx.x) * 4;
  *(uint2*)(g_Sh + i) = make_uint2(0, 0);
  *(uint2*)(g_Sl + i) = make_uint2(0, 0);
}

__global__ void k_s(const float* __restrict__ w_in) {
  int ih = blockIdx.x, tid = threadIdx.x;
  int i = ih >> 4, h = ih & 15;
  int k = blockIdx.y * 256 + tid;
  __shared__ float qh[64];
  if (tid < 64) qh[tid] = g_Q[i * Dm + h * 64 + tid];
  __syncthreads();
  const float* wk = w_in + (size_t)i * 3 * DD + DD + (size_t)(h * 64) * Dm + k;
  float acc = 0.f;
  #pragma unroll 8
  for (int j = 0; j < 64; j++) acc += wk[(size_t)j * Dm] * qh[j];
  float val = 0.125f * acc;
  __half hi = __float2half_rn(val);
  size_t off = toff(ih, k, 256);
  g_Sh[off] = hi;
  g_Sl[off] = __float2half_rn(val - __half2float(hi));
}

__global__ void k_softmax() {
  int idx = blockIdx.x * 256 + threadIdx.x;
  int h = idx & 15;
  int b = (idx >> 4) & (Bq - 1);
  int i = idx >> 17;
  int L = c_nvec[i];
  float sc[4];
  float mx = -1e30f;
  #pragma unroll
  for (int l = 0; l < 4; l++) if (l < L) {
    sc[l] = g_SC[((size_t)c_vidx[i][l] * Bq + b) * 256 + i * 16 + h];
    mx = fmaxf(mx, sc[l]);
  }
  float sum = 0.f;
  #pragma unroll
  for (int l = 0; l < 4; l++) if (l < L) { sc[l] = expf(sc[l] - mx); sum += sc[l]; }
  float inv = 1.f / sum;
  #pragma unroll
  for (int l = 0; l < 4; l++) if (l < L)
    g_A[(((size_t)i * 4 + l) * Bq + b) * 16 + h] = sc[l] * inv;
}

__global__ void k_mix(const float* __restrict__ b_in, int i) {
  int gid = blockIdx.x * 256 + threadIdx.x;
  int b = gid >> 8;
  int k = (gid & 255) * 4;
  int h = k >> 6;
  int L = c_nvec[i];
  int p0 = c_poff[i];
  float4 o = *(const float4*)(b_in + ((size_t)i * 3 + 2) * Dm + k);
  #pragma unroll
  for (int l = 0; l < 4; l++) if (l < L) {
    float a = g_A[(((size_t)i * 4 + l) * Bq + b) * 16 + h];
    const __half2* vp = (const __half2*)(g_V + ((size_t)(p0 + l) * Bq + b) * Dm + k);
    float2 f01 = __half22float2(vp[0]);
    float2 f23 = __half22float2(vp[1]);
    o.x += a * f01.x; o.y += a * f01.y; o.z += a * f23.x; o.w += a * f23.y;
  }
  *(uint2*)(g_Oh + (size_t)i * BD + toff(b, k, Bq)) = pack4h(o);
}

__global__ void k_convA(const float* __restrict__ xc, const float* __restrict__ xf,
                        const float* __restrict__ xbd, const float* __restrict__ xbg) {
  int v = blockIdx.y;
  const float* x = (v == 0) ? xc : (v == 1) ? xf : (v == 2) ? xbd : xbg;
  size_t i = (size_t)blockIdx.x * 256 + threadIdx.x;
  int m = (int)(i >> 8), k = ((int)i & 255) * 4;
  float4 val = ((const float4*)x)[i];
  *(uint2*)(g_Ah + (size_t)v * BD + toff(m, k, Bq)) = pack4h(val);
}

__global__ void k_convW(const float* __restrict__ w_in, const float* __restrict__ w_out) {
  int z = blockIdx.y;
  const float* src = (z < 7) ? (w_in + (size_t)z * 3 * DD + 2 * DD) : (w_out + (size_t)(z - 7) * DD);
  size_t i = (size_t)blockIdx.x * 256 + threadIdx.x;
  int n = (int)(i >> 8), k = ((int)i & 255) * 4;
  float4 val = ((const float4*)src)[i];
  *(uint2*)(g_Wh + (size_t)z * DD + toff(n, k, Dm)) = pack4h(val);
}

// ======================= bulk-copy fp16 HMMA GEMM (K-chunk 64, warp-desynced) =======================
// All modes: 48KB stage, NS=4.
// MODE 0 (v-proj): CTA 128x256, 1 term (A | Bh0 Bh1). C fp16.
// MODE 1 (out):    same, C fp32 + bias.
// MODE 2 (scores): CTA 128x128, 2 terms (A | Bh | Bl planes). C fp32 stride 256.
#define NCH 16
#define SMEM_SZ (1024 + 196608)

__device__ __forceinline__ uint32_t sw(uint32_t row, uint32_t g) {
  return row * 64 + ((g ^ ((row >> 1) & 3)) << 4);
}

template<int MODE>
__global__ void __launch_bounds__(256, 1) k_mma(const float* __restrict__ b_out,
                                                float* __restrict__ dout, int zoff) {
  constexpr int STG = 49152;
  constexpr int NS  = 4;
  constexpr int NT  = (MODE == 2) ? 4 : 8;
  extern __shared__ __align__(128) char smem[];
  const uint32_t sb = smem_u32(smem);
  const int tid = threadIdx.x;
  const int wid = tid >> 5, lane = tid & 31;
  const int m0 = blockIdx.x * 128;
  const int n0 = blockIdx.y * ((MODE == 2) ? 128 : 256);
  const int wm = (wid & 1) * 64, wn = (wid >> 1) * (NT * 8);
  const int cst = (MODE == 2) ? 256 : 1024;
  const int RB  = (MODE == 2) ? 256 : 1024;

  const __half *Ah, *Bh, *Bl = nullptr;
  float* C = nullptr; __half* Ch = nullptr; const float* bias = nullptr;
  if (MODE == 0) {
    int p = zoff + blockIdx.z;
    int v = c_pairv[p], wi = c_pairi[p];
    Ah = g_Ah + (size_t)v * BD;
    Bh = g_Wh + (size_t)wi * DD;
    Ch = g_V + (size_t)p * BD;
  } else if (MODE == 1) {
    int i = zoff;
    Ah = g_Oh + (size_t)i * BD;
    Bh = g_Wh + (size_t)(7 + i) * DD;
    C = dout + (size_t)i * BD;
    bias = b_out + i * Dm;
  } else {
    int v = blockIdx.z;
    Ah = g_Ah + (size_t)v * BD;
    Bh = g_Sh; Bl = g_Sl;
    C = g_SC + (size_t)v * Bq * 256;
  }

  if (tid == 0) {
    #pragma unroll
    for (int s = 0; s < NS; s++) {
      MBAR_INIT(sb + s * 8, 1);
      MBAR_INIT(sb + 128 + s * 8, 8);
    }
  }
  __syncthreads();

  auto issue = [&](int c) {
    int s = c % NS;
    uint32_t st = sb + 1024 + s * STG;
    uint32_t mb = sb + s * 8;
    MBAR_EXPECT(mb, STG);
    bulk_g2s(st,        Ah + ((size_t)(2*c)   * Bq + m0) * 32, 8192, mb);
    bulk_g2s(st + 8192, Ah + ((size_t)(2*c+1) * Bq + m0) * 32, 8192, mb);
    if (MODE == 2) {
      bulk_g2s(st + 16384, Bh + ((size_t)(2*c)   * RB + n0) * 32, 8192, mb);
      bulk_g2s(st + 24576, Bh + ((size_t)(2*c+1) * RB + n0) * 32, 8192, mb);
      bulk_g2s(st + 32768, Bl + ((size_t)(2*c)   * RB + n0) * 32, 8192, mb);
      bulk_g2s(st + 40960, Bl + ((size_t)(2*c+1) * RB + n0) * 32, 8192, mb);
    } else {
      bulk_g2s(st + 16384, Bh + ((size_t)(2*c)   * RB + n0) * 32, 16384, mb);
      bulk_g2s(st + 32768, Bh + ((size_t)(2*c+1) * RB + n0) * 32, 16384, mb);
    }
  };
  if (tid == 0) {
    #pragma unroll
    for (int c = 0; c < NS; c++) issue(c);
  }

  float acc[4][NT][4];
  #pragma unroll
  for (int mt = 0; mt < 4; mt++)
    #pragma unroll
    for (int nt = 0; nt < NT; nt++)
      #pragma unroll
      for (int r = 0; r < 4; r++) acc[mt][nt][r] = 0.f;

  const int arow = wm + (lane & 15);
  const int agsel = lane >> 4;
  const int brow = wn + ((lane & 7) | ((lane & 16) >> 1));
  const int bgsel = (lane >> 3) & 1;

  for (int c = 0; c < NCH; c++) {
    const int s = c % NS;
    const uint32_t st = sb + 1024 + s * STG;
    MBAR_WAIT(sb + s * 8, (c / NS) & 1);
    #pragma unroll
    for (int ks = 0; ks < 4; ks++) {
      const int kp = ks >> 1, kk = (ks & 1) * 2;
      const uint32_t stA = st + kp * 8192;
      const uint32_t stB = st + 16384 + kp * ((MODE == 2) ? 8192 : 16384);
      uint32_t ah[4][4], bh[NT][2];
      #pragma unroll
      for (int mt = 0; mt < 4; mt++) {
        uint32_t ad = stA + sw(arow + mt * 16, kk + agsel);
        ldsm4(ah[mt][0], ah[mt][1], ah[mt][2], ah[mt][3], ad);
      }
      #pragma unroll
      for (int np = 0; np < NT / 2; np++) {
        uint32_t bd = stB + sw(brow + np * 16, kk + bgsel);
        ldsm4(bh[np*2][0], bh[np*2][1], bh[np*2+1][0], bh[np*2+1][1], bd);
      }
      uint32_t bl[NT][2];
      if (MODE == 2) {
        #pragma unroll
        for (int np = 0; np < NT / 2; np++) {
          uint32_t bd = stB + 16384 + sw(brow + np * 16, kk + bgsel);
          ldsm4(bl[np*2][0], bl[np*2][1], bl[np*2+1][0], bl[np*2+1][1], bd);
        }
      }
      #pragma unroll
      for (int mt = 0; mt < 4; mt++)
        #pragma unroll
        for (int nt = 0; nt < NT; nt++) {
          mma_f16(acc[mt][nt], ah[mt], bh[nt]);
          if (MODE == 2) mma_f16(acc[mt][nt], ah[mt], bl[nt]);
        }
    }
    if (lane == 0) MBAR_ARRIVE(sb + 128 + s * 8);
    if (tid == 0 && c + NS < NCH) {
      MBAR_WAIT(sb + 128 + s * 8, (c / NS) & 1);
      issue(c + NS);
    }
  }

  // epilogue
  #pragma unroll
  for (int mt = 0; mt < 4; mt++) {
    int m = m0 + wm + mt * 16 + (lane >> 2);
    #pragma unroll
    for (int nt = 0; nt < NT; nt++) {
      int n = n0 + wn + nt * 8 + (lane & 3) * 2;
      float2 v0 = make_float2(acc[mt][nt][0], acc[mt][nt][1]);
      float2 v1 = make_float2(acc[mt][nt][2], acc[mt][nt][3]);
      if (MODE == 0) {
        __half2 h0{__float2half_rn(v0.x), __float2half_rn(v0.y)};
        __half2 h1{__float2half_rn(v1.x), __float2half_rn(v1.y)};
        *(__half2*)(Ch + (size_t)m * 1024 + n) = h0;
        *(__half2*)(Ch + (size_t)(m + 8) * 1024 + n) = h1;
      } else {
        if (MODE == 1) {
          float b0 = __ldg(bias + n), b1 = __ldg(bias + n + 1);
          v0.x += b0; v0.y += b1; v1.x += b0; v1.y += b1;
        }
        *(float2*)(C + (size_t)m * cst + n) = v0;
        *(float2*)(C + (size_t)(m + 8) * cst + n) = v1;
      }
    }
  }
}

// ======================= streams / events (created pre-main; capture-safe reuse) =======================
static cudaStream_t g_s1, g_s2;
static cudaEvent_t g_evF, g_evA, g_evW, g_evSM, g_evM0[NBR], g_evDone;
namespace {
struct StreamInit {
  StreamInit() {
    cudaStreamCreateWithFlags(&g_s1, cudaStreamNonBlocking);
    cudaStreamCreateWithFlags(&g_s2, cudaStreamNonBlocking);
    cudaEventCreateWithFlags(&g_evF, cudaEventDisableTiming);
    cudaEventCreateWithFlags(&g_evA, cudaEventDisableTiming);
    cudaEventCreateWithFlags(&g_evW, cudaEventDisableTiming);
    cudaEventCreateWithFlags(&g_evSM, cudaEventDisableTiming);
    for (int b = 0; b < NBR; b++) cudaEventCreateWithFlags(&g_evM0[b], cudaEventDisableTiming);
    cudaEventCreateWithFlags(&g_evDone, cudaEventDisableTiming);
  }
};
StreamInit g_si;
}

// ======================================================================
extern "C" void kernel_launch(void* const* d_in, const int* in_sizes, int n_in,
                              void* d_out, int out_size) {
  const float* xc     = (const float*)d_in[0];
  const float* xf     = (const float*)d_in[1];
  const float* xbd    = (const float*)d_in[2];
  const float* xbg    = (const float*)d_in[3];
  const float* tokens = (const float*)d_in[4];
  const float* w_in   = (const float*)d_in[5];
  const float* b_in   = (const float*)d_in[6];
  const float* w_out  = (const float*)d_in[7];
  const float* b_out  = (const float*)d_in[8];
  float* out = (float*)d_out;

  static const int h_poff[NBR] = {0,2,4,6,9,12,15};
  static const int h_nvec[NBR] = {2,2,2,3,3,3,4};
  static const int h_ord[NBR]  = {6,3,4,5,0,1,2};   // big branches first

  cudaFuncSetAttribute(k_mma<0>, cudaFuncAttributeMaxDynamicSharedMemorySize, SMEM_SZ);
  cudaFuncSetAttribute(k_mma<1>, cudaFuncAttributeMaxDynamicSharedMemorySize, SMEM_SZ);
  cudaFuncSetAttribute(k_mma<2>, cudaFuncAttributeMaxDynamicSharedMemorySize, SMEM_SZ);

  // fork point
  cudaEventRecord(g_evF, 0);

  // s1: weight conversion (independent of convA)
  cudaStreamWaitEvent(g_s1, g_evF, 0);
  k_convW<<<dim3(1024, 14), 256, 0, g_s1>>>(w_in, w_out);
  cudaEventRecord(g_evW, g_s1);

  // s2: score-vector chain
  cudaStreamWaitEvent(g_s2, g_evF, 0);
  k_qh<<<dim3(NBR, 16), 256, 0, g_s2>>>(tokens, w_in, b_in);
  k_zs<<<256, 256, 0, g_s2>>>();
  k_s<<<dim3(112, 4), 256, 0, g_s2>>>(w_in);

  // main: activation conversion (single fp16 plane now)
  k_convA<<<dim3(Bq, 4), 256>>>(xc, xf, xbd, xbg);
  cudaEventRecord(g_evA, 0);

  // s2: scores GEMM + softmax
  cudaStreamWaitEvent(g_s2, g_evA, 0);
  k_mma<2><<<dim3(Bq/128, 2, 4), 256, SMEM_SZ, g_s2>>>(b_out, out, 0);
  k_softmax<<<NBR * Bq * 16 / 256, 256, 0, g_s2>>>();
  cudaEventRecord(g_evSM, g_s2);

  // main: per-branch v-projections
  cudaStreamWaitEvent(0, g_evW, 0);
  for (int t = 0; t < NBR; t++) {
    int b = h_ord[t];
    k_mma<0><<<dim3(Bq/128, Dm/256, h_nvec[b]), 256, SMEM_SZ>>>(b_out, out, h_poff[b]);
    cudaEventRecord(g_evM0[b], 0);
  }

  // s1: per-branch mix + out-projection, pipelined against MODE0
  cudaStreamWaitEvent(g_s1, g_evSM, 0);
  for (int t = 0; t < NBR; t++) {
    int b = h_ord[t];
    cudaStreamWaitEvent(g_s1, g_evM0[b], 0);
    k_mix<<<Bq, 256, 0, g_s1>>>(b_in, b);
    k_mma<1><<<dim3(Bq/128, Dm/256, 1), 256, SMEM_SZ, g_s1>>>(b_out, out, b);
  }
  cudaEventRecord(g_evDone, g_s1);
  cudaStreamWaitEvent(0, g_evDone, 0);
}

// round 15
// speedup vs baseline: 8.4798x; 1.0178x over previous
#include <cuda_runtime.h>
#include <cuda_fp16.h>
#include <cstdint>

#define Bq 8192
#define Dm 1024
#define NBR 7
#define BD ((size_t)Bq * Dm)
#define DD ((size_t)Dm * Dm)

// ---------------- scratch (tiled, pre-swizzled fp16 planes: [kc][rows][32]) ----------------
__device__ float g_Q[NBR * Dm];
__device__ float g_SC[(size_t)4 * Bq * 128];
__device__ float g_A[(size_t)NBR * 4 * Bq * 16];
__device__ __align__(16) __half g_V[(size_t)19 * BD];
__device__ __align__(16) __half g_Sh[128 * Dm];
__device__ __align__(16) __half g_Sl[128 * Dm];
__device__ __align__(16) __half g_Ah[4 * BD];
__device__ __align__(16) __half g_Wh[14 * DD];
__device__ __align__(16) __half g_Oh[NBR * BD];

__constant__ int c_nvec[NBR] = {2,2,2,3,3,3,4};
__constant__ int c_vidx[NBR][4] = {{0,1,0,0},{0,2,0,0},{0,3,0,0},{0,1,2,0},{0,1,3,0},{0,2,3,0},{0,1,2,3}};
__constant__ int c_poff[NBR] = {0,2,4,6,9,12,15};
__constant__ int c_pairi[19] = {0,0,1,1,2,2,3,3,3,4,4,4,5,5,5,6,6,6,6};
__constant__ int c_pairv[19] = {0,1,0,2,0,3,0,1,2,0,1,3,0,2,3,0,1,2,3};

__device__ __forceinline__ size_t toff(int row, int k, int R) {
  return ((size_t)(k >> 5) * R + row) * 32 +
         (((((k >> 3) & 3) ^ ((row >> 1) & 3)) << 3) + (k & 7));
}

// ---------------- PTX helpers ----------------
__device__ __forceinline__ uint32_t smem_u32(const void* p) {
  uint32_t a;
  asm("{ .reg .u64 t; cvta.to.shared.u64 t, %1; cvt.u32.u64 %0, t; }" : "=r"(a) : "l"(p));
  return a;
}
#define MBAR_INIT(a, n) asm volatile("mbarrier.init.shared.b64 [%0], %1;" :: "r"(a), "r"(n) : "memory")
#define MBAR_EXPECT(a, b) asm volatile("mbarrier.arrive.expect_tx.shared.b64 _, [%0], %1;" :: "r"(a), "r"(b) : "memory")
#define MBAR_ARRIVE(a) asm volatile("mbarrier.arrive.shared.b64 _, [%0];" :: "r"(a) : "memory")
#define MBAR_WAIT(a, ph) do { \
  uint32_t _m = (a), _p = (ph), _d; \
  asm volatile("{ .reg .pred p; mbarrier.try_wait.parity.acquire.cta.shared::cta.b64 p, [%1], %2; selp.b32 %0,1,0,p; }" \
    : "=r"(_d) : "r"(_m), "r"(_p) : "memory"); \
  if (!_d) { asm volatile("{ .reg .pred P1; WL_%=: mbarrier.try_wait.parity.acquire.cta.shared::cta.b64 P1, [%0], %1, 0x989680; @P1 bra.uni WD_%=; bra.uni WL_%=; WD_%=: }" \
    :: "r"(_m), "r"(_p) : "memory"); } } while (0)

__device__ __forceinline__ void bulk_g2s(uint32_t dst, const void* src, uint32_t bytes, uint32_t mbar) {
  asm volatile("cp.async.bulk.shared::cluster.global.mbarrier::complete_tx::bytes [%0], [%1], %2, [%3];"
               :: "r"(dst), "l"(src), "r"(bytes), "r"(mbar) : "memory");
}
__device__ __forceinline__ void ldsm4(uint32_t& r0, uint32_t& r1, uint32_t& r2, uint32_t& r3, uint32_t addr) {
  asm volatile("ldmatrix.sync.aligned.m8n8.x4.shared.b16 {%0,%1,%2,%3}, [%4];"
               : "=r"(r0), "=r"(r1), "=r"(r2), "=r"(r3) : "r"(addr));
}
__device__ __forceinline__ void mma_f16(float* c, const uint32_t* a, const uint32_t* b) {
  asm volatile("mma.sync.aligned.m16n8k16.row.col.f32.f16.f16.f32 "
               "{%0,%1,%2,%3}, {%4,%5,%6,%7}, {%8,%9}, {%0,%1,%2,%3};"
               : "+f"(c[0]), "+f"(c[1]), "+f"(c[2]), "+f"(c[3])
               : "r"(a[0]), "r"(a[1]), "r"(a[2]), "r"(a[3]), "r"(b[0]), "r"(b[1]));
}

// ======================= fp32 -> fp16 pack =======================
__device__ __forceinline__ uint2 pack4h(float4 v) {
  __half2 a{__float2half_rn(v.x), __float2half_rn(v.y)};
  __half2 b{__float2half_rn(v.z), __float2half_rn(v.w)};
  return make_uint2(*(uint32_t*)&a, *(uint32_t*)&b);
}

// ======================= prep / conversion kernels =======================
__global__ void k_qh(const float* __restrict__ tokens, const float* __restrict__ w_in,
                     const float* __restrict__ b_in) {
  int i = blockIdx.x, rb = blockIdx.y, tid = threadIdx.x;
  int wid = tid >> 5, lane = tid & 31;
  __shared__ float tok[Dm];
  for (int k = tid; k < Dm; k += 256) tok[k] = tokens[i * Dm + k];
  __syncthreads();
  const float* wq = w_in + (size_t)i * 3 * DD;
  #pragma unroll
  for (int rr = 0; rr < 8; rr++) {
    int r = rb * 64 + wid * 8 + rr;
    const float4* row = (const float4*)(wq + (size_t)r * Dm);
    float acc = 0.f;
    #pragma unroll
    for (int j = 0; j < 8; j++) {
      float4 w = row[lane + j * 32];
      float4 t = *(const float4*)&tok[(lane + j * 32) * 4];
      acc += w.x * t.x + w.y * t.y + w.z * t.z + w.w * t.w;
    }
    #pragma unroll
    for (int o = 16; o; o >>= 1) acc += __shfl_xor_sync(0xFFFFFFFFu, acc, o);
    if (lane == 0) g_Q[i * Dm + r] = acc + b_in[i * 3 * Dm + r];
  }
}

__global__ void k_zs() {   // zero all of g_Sh/g_Sl (128 rows)
  size_t i = ((size_t)blockIdx.x * 256 + threadIdx.x) * 4;
  *(uint2*)(g_Sh + i) = make_uint2(0, 0);
  *(uint2*)(g_Sl + i) = make_uint2(0, 0);
}

__global__ void k_s(const float* __restrict__ w_in) {
  int ih = blockIdx.x, tid = threadIdx.x;
  int i = ih >> 4, h = ih & 15;
  int k = blockIdx.y * 256 + tid;
  __shared__ float qh[64];
  if (tid < 64) qh[tid] = g_Q[i * Dm + h * 64 + tid];
  __syncthreads();
  const float* wk = w_in + (size_t)i * 3 * DD + DD + (size_t)(h * 64) * Dm + k;
  float acc = 0.f;
  #pragma unroll 8
  for (int j = 0; j < 64; j++) acc += wk[(size_t)j * Dm] * qh[j];
  float val = 0.125f * acc;
  __half hi = __float2half_rn(val);
  size_t off = toff(ih, k, 128);
  g_Sh[off] = hi;
  g_Sl[off] = __float2half_rn(val - __half2float(hi));
}

__global__ void k_softmax() {
  int idx = blockIdx.x * 256 + threadIdx.x;
  int h = idx & 15;
  int b = (idx >> 4) & (Bq - 1);
  int i = idx >> 17;
  int L = c_nvec[i];
  float sc[4];
  float mx = -1e30f;
  #pragma unroll
  for (int l = 0; l < 4; l++) if (l < L) {
    sc[l] = g_SC[((size_t)c_vidx[i][l] * Bq + b) * 128 + i * 16 + h];
    mx = fmaxf(mx, sc[l]);
  }
  float sum = 0.f;
  #pragma unroll
  for (int l = 0; l < 4; l++) if (l < L) { sc[l] = expf(sc[l] - mx); sum += sc[l]; }
  float inv = 1.f / sum;
  #pragma unroll
  for (int l = 0; l < 4; l++) if (l < L)
    g_A[(((size_t)i * 4 + l) * Bq + b) * 16 + h] = sc[l] * inv;
}

__global__ void k_mix(const float* __restrict__ b_in, int i) {
  int gid = blockIdx.x * 256 + threadIdx.x;
  int b = gid >> 8;
  int k = (gid & 255) * 4;
  int h = k >> 6;
  int L = c_nvec[i];
  int p0 = c_poff[i];
  float4 o = *(const float4*)(b_in + ((size_t)i * 3 + 2) * Dm + k);
  #pragma unroll
  for (int l = 0; l < 4; l++) if (l < L) {
    float a = g_A[(((size_t)i * 4 + l) * Bq + b) * 16 + h];
    const __half2* vp = (const __half2*)(g_V + ((size_t)(p0 + l) * Bq + b) * Dm + k);
    float2 f01 = __half22float2(vp[0]);
    float2 f23 = __half22float2(vp[1]);
    o.x += a * f01.x; o.y += a * f01.y; o.z += a * f23.x; o.w += a * f23.y;
  }
  *(uint2*)(g_Oh + (size_t)i * BD + toff(b, k, Bq)) = pack4h(o);
}

__global__ void k_convA(const float* __restrict__ xc, const float* __restrict__ xf,
                        const float* __restrict__ xbd, const float* __restrict__ xbg) {
  int v = blockIdx.y;
  const float* x = (v == 0) ? xc : (v == 1) ? xf : (v == 2) ? xbd : xbg;
  size_t i = (size_t)blockIdx.x * 256 + threadIdx.x;
  int m = (int)(i >> 8), k = ((int)i & 255) * 4;
  float4 val = ((const float4*)x)[i];
  *(uint2*)(g_Ah + (size_t)v * BD + toff(m, k, Bq)) = pack4h(val);
}

__global__ void k_convW(const float* __restrict__ w_in, const float* __restrict__ w_out) {
  int z = blockIdx.y;
  const float* src = (z < 7) ? (w_in + (size_t)z * 3 * DD + 2 * DD) : (w_out + (size_t)(z - 7) * DD);
  size_t i = (size_t)blockIdx.x * 256 + threadIdx.x;
  int n = (int)(i >> 8), k = ((int)i & 255) * 4;
  float4 val = ((const float4*)src)[i];
  *(uint2*)(g_Wh + (size_t)z * DD + toff(n, k, Dm)) = pack4h(val);
}

// ======================= bulk-copy fp16 HMMA GEMM =======================
// 128x128 CTA tile, NT=4, K-chunk 64, NS=3, warp-desynced ping-pong.
// MODE 0/1: 2 CTAs/SM, stage 32KB (A 16K | B 16K).
// MODE 2:   1 CTA/SM, stage 48KB (A | Bh | Bl @ 16K), 2 terms, RB=128.
#define NCH 16
#define NS 3
#define SMEM01 (1024 + 3 * 32768)
#define SMEM2  (1024 + 3 * 49152)

__device__ __forceinline__ uint32_t sw(uint32_t row, uint32_t g) {
  return row * 64 + ((g ^ ((row >> 1) & 3)) << 4);
}

template<int MODE>
__global__ void __launch_bounds__(256, (MODE == 2) ? 1 : 2)
k_mma(const float* __restrict__ b_out, float* __restrict__ dout, int zoff) {
  constexpr int STG = (MODE == 2) ? 49152 : 32768;
  extern __shared__ __align__(128) char smem[];
  const uint32_t sb = smem_u32(smem);
  const int tid = threadIdx.x;
  const int wid = tid >> 5, lane = tid & 31;
  const int m0 = blockIdx.x * 128;
  const int n0 = blockIdx.y * 128;
  const int wm = (wid & 1) * 64, wn = (wid >> 1) * 32;
  const int cst = (MODE == 2) ? 128 : 1024;
  const int RB  = (MODE == 2) ? 128 : 1024;

  const __half *Ah, *Bh, *Bl = nullptr;
  float* C = nullptr; __half* Ch = nullptr; const float* bias = nullptr;
  if (MODE == 0) {
    int p = zoff + blockIdx.z;
    int v = c_pairv[p], wi = c_pairi[p];
    Ah = g_Ah + (size_t)v * BD;
    Bh = g_Wh + (size_t)wi * DD;
    Ch = g_V + (size_t)p * BD;
  } else if (MODE == 1) {
    int i = zoff;
    Ah = g_Oh + (size_t)i * BD;
    Bh = g_Wh + (size_t)(7 + i) * DD;
    C = dout + (size_t)i * BD;
    bias = b_out + i * Dm;
  } else {
    int v = blockIdx.z;
    Ah = g_Ah + (size_t)v * BD;
    Bh = g_Sh; Bl = g_Sl;
    C = g_SC + (size_t)v * Bq * 128;
  }

  if (tid == 0) {
    #pragma unroll
    for (int s = 0; s < NS; s++) {
      MBAR_INIT(sb + s * 8, 1);
      MBAR_INIT(sb + 128 + s * 8, 8);
    }
  }
  __syncthreads();

  auto issue = [&](int c) {
    int s = c % NS;
    uint32_t st = sb + 1024 + s * STG;
    uint32_t mb = sb + s * 8;
    MBAR_EXPECT(mb, STG);
    bulk_g2s(st,         Ah + ((size_t)(2*c)   * Bq + m0) * 32, 8192, mb);
    bulk_g2s(st + 8192,  Ah + ((size_t)(2*c+1) * Bq + m0) * 32, 8192, mb);
    bulk_g2s(st + 16384, Bh + ((size_t)(2*c)   * RB + n0) * 32, 8192, mb);
    bulk_g2s(st + 24576, Bh + ((size_t)(2*c+1) * RB + n0) * 32, 8192, mb);
    if (MODE == 2) {
      bulk_g2s(st + 32768, Bl + ((size_t)(2*c)   * RB + n0) * 32, 8192, mb);
      bulk_g2s(st + 40960, Bl + ((size_t)(2*c+1) * RB + n0) * 32, 8192, mb);
    }
  };
  if (tid == 0) {
    #pragma unroll
    for (int c = 0; c < NS; c++) issue(c);
  }

  float acc[4][4][4];
  #pragma unroll
  for (int mt = 0; mt < 4; mt++)
    #pragma unroll
    for (int nt = 0; nt < 4; nt++)
      #pragma unroll
      for (int r = 0; r < 4; r++) acc[mt][nt][r] = 0.f;

  const int arow = wm + (lane & 15);
  const int agsel = lane >> 4;
  const int brow = wn + ((lane & 7) | ((lane & 16) >> 1));
  const int bgsel = (lane >> 3) & 1;

  for (int c = 0; c < NCH; c++) {
    const int s = c % NS;
    const uint32_t st = sb + 1024 + s * STG;
    MBAR_WAIT(sb + s * 8, (c / NS) & 1);
    #pragma unroll
    for (int ks = 0; ks < 4; ks++) {
      const int kp = ks >> 1, kk = (ks & 1) * 2;
      const uint32_t stA = st + kp * 8192;
      const uint32_t stB = st + 16384 + kp * 8192;
      uint32_t ah[4][4], bh[4][2];
      #pragma unroll
      for (int mt = 0; mt < 4; mt++) {
        uint32_t ad = stA + sw(arow + mt * 16, kk + agsel);
        ldsm4(ah[mt][0], ah[mt][1], ah[mt][2], ah[mt][3], ad);
      }
      #pragma unroll
      for (int np = 0; np < 2; np++) {
        uint32_t bd = stB + sw(brow + np * 16, kk + bgsel);
        ldsm4(bh[np*2][0], bh[np*2][1], bh[np*2+1][0], bh[np*2+1][1], bd);
      }
      uint32_t bl[4][2];
      if (MODE == 2) {
        #pragma unroll
        for (int np = 0; np < 2; np++) {
          uint32_t bd = stB + 16384 + sw(brow + np * 16, kk + bgsel);
          ldsm4(bl[np*2][0], bl[np*2][1], bl[np*2+1][0], bl[np*2+1][1], bd);
        }
      }
      #pragma unroll
      for (int mt = 0; mt < 4; mt++)
        #pragma unroll
        for (int nt = 0; nt < 4; nt++) {
          mma_f16(acc[mt][nt], ah[mt], bh[nt]);
          if (MODE == 2) mma_f16(acc[mt][nt], ah[mt], bl[nt]);
        }
    }
    if (lane == 0) MBAR_ARRIVE(sb + 128 + s * 8);
    if (tid == 0 && c + NS < NCH) {
      MBAR_WAIT(sb + 128 + s * 8, (c / NS) & 1);
      issue(c + NS);
    }
  }

  // epilogue
  #pragma unroll
  for (int mt = 0; mt < 4; mt++) {
    int m = m0 + wm + mt * 16 + (lane >> 2);
    #pragma unroll
    for (int nt = 0; nt < 4; nt++) {
      int n = n0 + wn + nt * 8 + (lane & 3) * 2;
      float2 v0 = make_float2(acc[mt][nt][0], acc[mt][nt][1]);
      float2 v1 = make_float2(acc[mt][nt][2], acc[mt][nt][3]);
      if (MODE == 0) {
        __half2 h0{__float2half_rn(v0.x), __float2half_rn(v0.y)};
        __half2 h1{__float2half_rn(v1.x), __float2half_rn(v1.y)};
        *(__half2*)(Ch + (size_t)m * 1024 + n) = h0;
        *(__half2*)(Ch + (size_t)(m + 8) * 1024 + n) = h1;
      } else {
        if (MODE == 1) {
          float b0 = __ldg(bias + n), b1 = __ldg(bias + n + 1);
          v0.x += b0; v0.y += b1; v1.x += b0; v1.y += b1;
        }
        *(float2*)(C + (size_t)m * cst + n) = v0;
        *(float2*)(C + (size_t)(m + 8) * cst + n) = v1;
      }
    }
  }
}

// ======================= streams / events (created pre-main; capture-safe reuse) =======================
static cudaStream_t g_s1, g_s2;
static cudaEvent_t g_evF, g_evA, g_evW, g_evSM, g_evM0[NBR], g_evDone;
namespace {
struct StreamInit {
  StreamInit() {
    cudaStreamCreateWithFlags(&g_s1, cudaStreamNonBlocking);
    cudaStreamCreateWithFlags(&g_s2, cudaStreamNonBlocking);
    cudaEventCreateWithFlags(&g_evF, cudaEventDisableTiming);
    cudaEventCreateWithFlags(&g_evA, cudaEventDisableTiming);
    cudaEventCreateWithFlags(&g_evW, cudaEventDisableTiming);
    cudaEventCreateWithFlags(&g_evSM, cudaEventDisableTiming);
    for (int b = 0; b < NBR; b++) cudaEventCreateWithFlags(&g_evM0[b], cudaEventDisableTiming);
    cudaEventCreateWithFlags(&g_evDone, cudaEventDisableTiming);
  }
};
StreamInit g_si;
}

// ======================================================================
extern "C" void kernel_launch(void* const* d_in, const int* in_sizes, int n_in,
                              void* d_out, int out_size) {
  const float* xc     = (const float*)d_in[0];
  const float* xf     = (const float*)d_in[1];
  const float* xbd    = (const float*)d_in[2];
  const float* xbg    = (const float*)d_in[3];
  const float* tokens = (const float*)d_in[4];
  const float* w_in   = (const float*)d_in[5];
  const float* b_in   = (const float*)d_in[6];
  const float* w_out  = (const float*)d_in[7];
  const float* b_out  = (const float*)d_in[8];
  float* out = (float*)d_out;

  static const int h_poff[NBR] = {0,2,4,6,9,12,15};
  static const int h_nvec[NBR] = {2,2,2,3,3,3,4};
  static const int h_ord[NBR]  = {6,3,4,5,0,1,2};   // big branches first

  cudaFuncSetAttribute(k_mma<0>, cudaFuncAttributeMaxDynamicSharedMemorySize, SMEM01);
  cudaFuncSetAttribute(k_mma<1>, cudaFuncAttributeMaxDynamicSharedMemorySize, SMEM01);
  cudaFuncSetAttribute(k_mma<2>, cudaFuncAttributeMaxDynamicSharedMemorySize, SMEM2);

  // fork point
  cudaEventRecord(g_evF, 0);

  // s1: weight conversion
  cudaStreamWaitEvent(g_s1, g_evF, 0);
  k_convW<<<dim3(1024, 14), 256, 0, g_s1>>>(w_in, w_out);
  cudaEventRecord(g_evW, g_s1);

  // s2: score-vector chain
  cudaStreamWaitEvent(g_s2, g_evF, 0);
  k_qh<<<dim3(NBR, 16), 256, 0, g_s2>>>(tokens, w_in, b_in);
  k_zs<<<128, 256, 0, g_s2>>>();
  k_s<<<dim3(112, 4), 256, 0, g_s2>>>(w_in);

  // main: activation conversion (single fp16 plane)
  k_convA<<<dim3(Bq, 4), 256>>>(xc, xf, xbd, xbg);
  cudaEventRecord(g_evA, 0);

  // s2: scores GEMM + softmax
  cudaStreamWaitEvent(g_s2, g_evA, 0);
  k_mma<2><<<dim3(Bq/128, 1, 4), 256, SMEM2, g_s2>>>(b_out, out, 0);
  k_softmax<<<NBR * Bq * 16 / 256, 256, 0, g_s2>>>();
  cudaEventRecord(g_evSM, g_s2);

  // main: per-branch v-projections
  cudaStreamWaitEvent(0, g_evW, 0);
  for (int t = 0; t < NBR; t++) {
    int b = h_ord[t];
    k_mma<0><<<dim3(Bq/128, Dm/128, h_nvec[b]), 256, SMEM01>>>(b_out, out, h_poff[b]);
    cudaEventRecord(g_evM0[b], 0);
  }

  // s1: per-branch mix + out-projection, pipelined against MODE0
  cudaStreamWaitEvent(g_s1, g_evSM, 0);
  for (int t = 0; t < NBR; t++) {
    int b = h_ord[t];
    cudaStreamWaitEvent(g_s1, g_evM0[b], 0);
    k_mix<<<Bq, 256, 0, g_s1>>>(b_in, b);
    k_mma<1><<<dim3(Bq/128, Dm/128, 1), 256, SMEM01, g_s1>>>(b_out, out, b);
  }
  cudaEventRecord(g_evDone, g_s1);
  cudaStreamWaitEvent(0, g_evDone, 0);
}

// round 16
// speedup vs baseline: 8.6161x; 1.0161x over previous
#include <cuda_runtime.h>
#include <cuda_fp16.h>
#include <cstdint>

#define Bq 8192
#define Dm 1024
#define NBR 7
#define BD ((size_t)Bq * Dm)
#define DD ((size_t)Dm * Dm)

// ---------------- scratch (tiled, pre-swizzled fp16 planes: [kc][rows][32]) ----------------
__device__ float g_Q[NBR * Dm];
__device__ float g_SC[(size_t)4 * Bq * 128];
__device__ float g_A[(size_t)NBR * 4 * Bq * 16];
__device__ __align__(16) __half g_V[(size_t)19 * BD];
__device__ __align__(16) __half g_Sh[128 * Dm];
__device__ __align__(16) __half g_Sl[128 * Dm];
__device__ __align__(16) __half g_Ah[4 * BD];
__device__ __align__(16) __half g_Wh[14 * DD];
__device__ __align__(16) __half g_Oh[NBR * BD];

__constant__ int c_nvec[NBR] = {2,2,2,3,3,3,4};
__constant__ int c_vidx[NBR][4] = {{0,1,0,0},{0,2,0,0},{0,3,0,0},{0,1,2,0},{0,1,3,0},{0,2,3,0},{0,1,2,3}};
__constant__ int c_poff[NBR] = {0,2,4,6,9,12,15};
__constant__ int c_pairi[19] = {0,0,1,1,2,2,3,3,3,4,4,4,5,5,5,6,6,6,6};
__constant__ int c_pairv[19] = {0,1,0,2,0,3,0,1,2,0,1,3,0,2,3,0,1,2,3};

__device__ __forceinline__ size_t toff(int row, int k, int R) {
  return ((size_t)(k >> 5) * R + row) * 32 +
         (((((k >> 3) & 3) ^ ((row >> 1) & 3)) << 3) + (k & 7));
}

// ---------------- PTX helpers ----------------
__device__ __forceinline__ uint32_t smem_u32(const void* p) {
  uint32_t a;
  asm("{ .reg .u64 t; cvta.to.shared.u64 t, %1; cvt.u32.u64 %0, t; }" : "=r"(a) : "l"(p));
  return a;
}
#define MBAR_INIT(a, n) asm volatile("mbarrier.init.shared.b64 [%0], %1;" :: "r"(a), "r"(n) : "memory")
#define MBAR_EXPECT(a, b) asm volatile("mbarrier.arrive.expect_tx.shared.b64 _, [%0], %1;" :: "r"(a), "r"(b) : "memory")
#define MBAR_ARRIVE(a) asm volatile("mbarrier.arrive.shared.b64 _, [%0];" :: "r"(a) : "memory")
#define MBAR_WAIT(a, ph) do { \
  uint32_t _m = (a), _p = (ph), _d; \
  asm volatile("{ .reg .pred p; mbarrier.try_wait.parity.acquire.cta.shared::cta.b64 p, [%1], %2; selp.b32 %0,1,0,p; }" \
    : "=r"(_d) : "r"(_m), "r"(_p) : "memory"); \
  if (!_d) { asm volatile("{ .reg .pred P1; WL_%=: mbarrier.try_wait.parity.acquire.cta.shared::cta.b64 P1, [%0], %1, 0x989680; @P1 bra.uni WD_%=; bra.uni WL_%=; WD_%=: }" \
    :: "r"(_m), "r"(_p) : "memory"); } } while (0)

__device__ __forceinline__ void bulk_g2s(uint32_t dst, const void* src, uint32_t bytes, uint32_t mbar) {
  asm volatile("cp.async.bulk.shared::cluster.global.mbarrier::complete_tx::bytes [%0], [%1], %2, [%3];"
               :: "r"(dst), "l"(src), "r"(bytes), "r"(mbar) : "memory");
}
__device__ __forceinline__ void ldsm4(uint32_t& r0, uint32_t& r1, uint32_t& r2, uint32_t& r3, uint32_t addr) {
  asm volatile("ldmatrix.sync.aligned.m8n8.x4.shared.b16 {%0,%1,%2,%3}, [%4];"
               : "=r"(r0), "=r"(r1), "=r"(r2), "=r"(r3) : "r"(addr));
}
__device__ __forceinline__ void mma_f16(float* c, const uint32_t* a, const uint32_t* b) {
  asm volatile("mma.sync.aligned.m16n8k16.row.col.f32.f16.f16.f32 "
               "{%0,%1,%2,%3}, {%4,%5,%6,%7}, {%8,%9}, {%0,%1,%2,%3};"
               : "+f"(c[0]), "+f"(c[1]), "+f"(c[2]), "+f"(c[3])
               : "r"(a[0]), "r"(a[1]), "r"(a[2]), "r"(a[3]), "r"(b[0]), "r"(b[1]));
}

// ======================= fp32 -> fp16 pack =======================
__device__ __forceinline__ uint2 pack4h(float4 v) {
  __half2 a{__float2half_rn(v.x), __float2half_rn(v.y)};
  __half2 b{__float2half_rn(v.z), __float2half_rn(v.w)};
  return make_uint2(*(uint32_t*)&a, *(uint32_t*)&b);
}

// ======================= prep / conversion kernels =======================
__global__ void k_qh(const float* __restrict__ tokens, const float* __restrict__ w_in,
                     const float* __restrict__ b_in) {
  int i = blockIdx.x, rb = blockIdx.y, tid = threadIdx.x;
  int wid = tid >> 5, lane = tid & 31;
  __shared__ float tok[Dm];
  for (int k = tid; k < Dm; k += 256) tok[k] = tokens[i * Dm + k];
  __syncthreads();
  const float* wq = w_in + (size_t)i * 3 * DD;
  #pragma unroll
  for (int rr = 0; rr < 8; rr++) {
    int r = rb * 64 + wid * 8 + rr;
    const float4* row = (const float4*)(wq + (size_t)r * Dm);
    float acc = 0.f;
    #pragma unroll
    for (int j = 0; j < 8; j++) {
      float4 w = row[lane + j * 32];
      float4 t = *(const float4*)&tok[(lane + j * 32) * 4];
      acc += w.x * t.x + w.y * t.y + w.z * t.z + w.w * t.w;
    }
    #pragma unroll
    for (int o = 16; o; o >>= 1) acc += __shfl_xor_sync(0xFFFFFFFFu, acc, o);
    if (lane == 0) g_Q[i * Dm + r] = acc + b_in[i * 3 * Dm + r];
  }
}

__global__ void k_zs() {   // zero g_Sh/g_Sl (128 rows)
  size_t i = ((size_t)blockIdx.x * 256 + threadIdx.x) * 4;
  *(uint2*)(g_Sh + i) = make_uint2(0, 0);
  *(uint2*)(g_Sl + i) = make_uint2(0, 0);
}

__global__ void k_s(const float* __restrict__ w_in) {
  int ih = blockIdx.x, tid = threadIdx.x;
  int i = ih >> 4, h = ih & 15;
  int k = blockIdx.y * 256 + tid;
  __shared__ float qh[64];
  if (tid < 64) qh[tid] = g_Q[i * Dm + h * 64 + tid];
  __syncthreads();
  const float* wk = w_in + (size_t)i * 3 * DD + DD + (size_t)(h * 64) * Dm + k;
  float acc = 0.f;
  #pragma unroll 8
  for (int j = 0; j < 64; j++) acc += wk[(size_t)j * Dm] * qh[j];
  float val = 0.125f * acc;
  __half hi = __float2half_rn(val);
  size_t off = toff(ih, k, 128);
  g_Sh[off] = hi;
  g_Sl[off] = __float2half_rn(val - __half2float(hi));
}

__global__ void k_softmax() {
  int idx = blockIdx.x * 256 + threadIdx.x;
  int h = idx & 15;
  int b = (idx >> 4) & (Bq - 1);
  int i = idx >> 17;
  int L = c_nvec[i];
  float sc[4];
  float mx = -1e30f;
  #pragma unroll
  for (int l = 0; l < 4; l++) if (l < L) {
    sc[l] = g_SC[((size_t)c_vidx[i][l] * Bq + b) * 128 + i * 16 + h];
    mx = fmaxf(mx, sc[l]);
  }
  float sum = 0.f;
  #pragma unroll
  for (int l = 0; l < 4; l++) if (l < L) { sc[l] = expf(sc[l] - mx); sum += sc[l]; }
  float inv = 1.f / sum;
  #pragma unroll
  for (int l = 0; l < 4; l++) if (l < L)
    g_A[(((size_t)i * 4 + l) * Bq + b) * 16 + h] = sc[l] * inv;
}

__global__ void k_mix(const float* __restrict__ b_in, int i) {
  int gid = blockIdx.x * 256 + threadIdx.x;
  int b = gid >> 8;
  int k = (gid & 255) * 4;
  int h = k >> 6;
  int L = c_nvec[i];
  int p0 = c_poff[i];
  float4 o = *(const float4*)(b_in + ((size_t)i * 3 + 2) * Dm + k);
  #pragma unroll
  for (int l = 0; l < 4; l++) if (l < L) {
    float a = g_A[(((size_t)i * 4 + l) * Bq + b) * 16 + h];
    const __half2* vp = (const __half2*)(g_V + ((size_t)(p0 + l) * Bq + b) * Dm + k);
    float2 f01 = __half22float2(vp[0]);
    float2 f23 = __half22float2(vp[1]);
    o.x += a * f01.x; o.y += a * f01.y; o.z += a * f23.x; o.w += a * f23.y;
  }
  *(uint2*)(g_Oh + (size_t)i * BD + toff(b, k, Bq)) = pack4h(o);
}

// single-plane activation conversion, one v per launch
__global__ void k_convA1(const float* __restrict__ x, int v) {
  size_t i = (size_t)blockIdx.x * 256 + threadIdx.x;
  int m = (int)(i >> 8), k = ((int)i & 255) * 4;
  float4 val = ((const float4*)x)[i];
  *(uint2*)(g_Ah + (size_t)v * BD + toff(m, k, Bq)) = pack4h(val);
}

__global__ void k_convW(const float* __restrict__ w_in, const float* __restrict__ w_out) {
  int z = blockIdx.y;
  const float* src = (z < 7) ? (w_in + (size_t)z * 3 * DD + 2 * DD) : (w_out + (size_t)(z - 7) * DD);
  size_t i = (size_t)blockIdx.x * 256 + threadIdx.x;
  int n = (int)(i >> 8), k = ((int)i & 255) * 4;
  float4 val = ((const float4*)src)[i];
  *(uint2*)(g_Wh + (size_t)z * DD + toff(n, k, Dm)) = pack4h(val);
}

// ======================= bulk-copy fp16 HMMA GEMM (R14-proven config) =======================
// All modes: 48KB stage, NS=4, 1 CTA/SM, warp-desynced ping-pong, K-chunk 64.
// MODE 0 (v-proj): CTA 128x256, 1 term (A | Bh0 Bh1). C fp16.
// MODE 1 (out):    same, C fp32 + bias.
// MODE 2 (scores): CTA 128x128, 2 terms (A | Bh | Bl planes), RB=128, C fp32 stride 128.
#define NCH 16
#define SMEM_SZ (1024 + 196608)

__device__ __forceinline__ uint32_t sw(uint32_t row, uint32_t g) {
  return row * 64 + ((g ^ ((row >> 1) & 3)) << 4);
}

template<int MODE>
__global__ void __launch_bounds__(256, 1) k_mma(const float* __restrict__ b_out,
                                                float* __restrict__ dout, int zoff) {
  constexpr int STG = 49152;
  constexpr int NS  = 4;
  constexpr int NT  = (MODE == 2) ? 4 : 8;
  extern __shared__ __align__(128) char smem[];
  const uint32_t sb = smem_u32(smem);
  const int tid = threadIdx.x;
  const int wid = tid >> 5, lane = tid & 31;
  const int m0 = blockIdx.x * 128;
  const int n0 = blockIdx.y * ((MODE == 2) ? 128 : 256);
  const int wm = (wid & 1) * 64, wn = (wid >> 1) * (NT * 8);
  const int cst = (MODE == 2) ? 128 : 1024;
  const int RB  = (MODE == 2) ? 128 : 1024;

  const __half *Ah, *Bh, *Bl = nullptr;
  float* C = nullptr; __half* Ch = nullptr; const float* bias = nullptr;
  if (MODE == 0) {
    int p = zoff + blockIdx.z;
    int v = c_pairv[p], wi = c_pairi[p];
    Ah = g_Ah + (size_t)v * BD;
    Bh = g_Wh + (size_t)wi * DD;
    Ch = g_V + (size_t)p * BD;
  } else if (MODE == 1) {
    int i = zoff;
    Ah = g_Oh + (size_t)i * BD;
    Bh = g_Wh + (size_t)(7 + i) * DD;
    C = dout + (size_t)i * BD;
    bias = b_out + i * Dm;
  } else {
    int v = blockIdx.z;
    Ah = g_Ah + (size_t)v * BD;
    Bh = g_Sh; Bl = g_Sl;
    C = g_SC + (size_t)v * Bq * 128;
  }

  if (tid == 0) {
    #pragma unroll
    for (int s = 0; s < NS; s++) {
      MBAR_INIT(sb + s * 8, 1);
      MBAR_INIT(sb + 128 + s * 8, 8);
    }
  }
  __syncthreads();

  auto issue = [&](int c) {
    int s = c % NS;
    uint32_t st = sb + 1024 + s * STG;
    uint32_t mb = sb + s * 8;
    MBAR_EXPECT(mb, STG);
    bulk_g2s(st,        Ah + ((size_t)(2*c)   * Bq + m0) * 32, 8192, mb);
    bulk_g2s(st + 8192, Ah + ((size_t)(2*c+1) * Bq + m0) * 32, 8192, mb);
    if (MODE == 2) {
      bulk_g2s(st + 16384, Bh + ((size_t)(2*c)   * RB + n0) * 32, 8192, mb);
      bulk_g2s(st + 24576, Bh + ((size_t)(2*c+1) * RB + n0) * 32, 8192, mb);
      bulk_g2s(st + 32768, Bl + ((size_t)(2*c)   * RB + n0) * 32, 8192, mb);
      bulk_g2s(st + 40960, Bl + ((size_t)(2*c+1) * RB + n0) * 32, 8192, mb);
    } else {
      bulk_g2s(st + 16384, Bh + ((size_t)(2*c)   * RB + n0) * 32, 16384, mb);
      bulk_g2s(st + 32768, Bh + ((size_t)(2*c+1) * RB + n0) * 32, 16384, mb);
    }
  };
  if (tid == 0) {
    #pragma unroll
    for (int c = 0; c < NS; c++) issue(c);
  }

  float acc[4][NT][4];
  #pragma unroll
  for (int mt = 0; mt < 4; mt++)
    #pragma unroll
    for (int nt = 0; nt < NT; nt++)
      #pragma unroll
      for (int r = 0; r < 4; r++) acc[mt][nt][r] = 0.f;

  const int arow = wm + (lane & 15);
  const int agsel = lane >> 4;
  const int brow = wn + ((lane & 7) | ((lane & 16) >> 1));
  const int bgsel = (lane >> 3) & 1;

  for (int c = 0; c < NCH; c++) {
    const int s = c % NS;
    const uint32_t st = sb + 1024 + s * STG;
    MBAR_WAIT(sb + s * 8, (c / NS) & 1);
    #pragma unroll
    for (int ks = 0; ks < 4; ks++) {
      const int kp = ks >> 1, kk = (ks & 1) * 2;
      const uint32_t stA = st + kp * 8192;
      const uint32_t stB = st + 16384 + kp * ((MODE == 2) ? 8192 : 16384);
      uint32_t ah[4][4], bh[NT][2];
      #pragma unroll
      for (int mt = 0; mt < 4; mt++) {
        uint32_t ad = stA + sw(arow + mt * 16, kk + agsel);
        ldsm4(ah[mt][0], ah[mt][1], ah[mt][2], ah[mt][3], ad);
      }
      #pragma unroll
      for (int np = 0; np < NT / 2; np++) {
        uint32_t bd = stB + sw(brow + np * 16, kk + bgsel);
        ldsm4(bh[np*2][0], bh[np*2][1], bh[np*2+1][0], bh[np*2+1][1], bd);
      }
      uint32_t bl[NT][2];
      if (MODE == 2) {
        #pragma unroll
        for (int np = 0; np < NT / 2; np++) {
          uint32_t bd = stB + 16384 + sw(brow + np * 16, kk + bgsel);
          ldsm4(bl[np*2][0], bl[np*2][1], bl[np*2+1][0], bl[np*2+1][1], bd);
        }
      }
      #pragma unroll
      for (int mt = 0; mt < 4; mt++)
        #pragma unroll
        for (int nt = 0; nt < NT; nt++) {
          mma_f16(acc[mt][nt], ah[mt], bh[nt]);
          if (MODE == 2) mma_f16(acc[mt][nt], ah[mt], bl[nt]);
        }
    }
    if (lane == 0) MBAR_ARRIVE(sb + 128 + s * 8);
    if (tid == 0 && c + NS < NCH) {
      MBAR_WAIT(sb + 128 + s * 8, (c / NS) & 1);
      issue(c + NS);
    }
  }

  // epilogue
  #pragma unroll
  for (int mt = 0; mt < 4; mt++) {
    int m = m0 + wm + mt * 16 + (lane >> 2);
    #pragma unroll
    for (int nt = 0; nt < NT; nt++) {
      int n = n0 + wn + nt * 8 + (lane & 3) * 2;
      float2 v0 = make_float2(acc[mt][nt][0], acc[mt][nt][1]);
      float2 v1 = make_float2(acc[mt][nt][2], acc[mt][nt][3]);
      if (MODE == 0) {
        __half2 h0{__float2half_rn(v0.x), __float2half_rn(v0.y)};
        __half2 h1{__float2half_rn(v1.x), __float2half_rn(v1.y)};
        *(__half2*)(Ch + (size_t)m * 1024 + n) = h0;
        *(__half2*)(Ch + (size_t)(m + 8) * 1024 + n) = h1;
      } else {
        if (MODE == 1) {
          float b0 = __ldg(bias + n), b1 = __ldg(bias + n + 1);
          v0.x += b0; v0.y += b1; v1.x += b0; v1.y += b1;
        }
        *(float2*)(C + (size_t)m * cst + n) = v0;
        *(float2*)(C + (size_t)(m + 8) * cst + n) = v1;
      }
    }
  }
}

// ======================= streams / events (created pre-main; capture-safe reuse) =======================
static cudaStream_t g_s1, g_s2;
static cudaEvent_t g_evF, g_evA01, g_evA, g_evW, g_evSM, g_evM0[NBR], g_evDone;
namespace {
struct StreamInit {
  StreamInit() {
    cudaStreamCreateWithFlags(&g_s1, cudaStreamNonBlocking);
    cudaStreamCreateWithFlags(&g_s2, cudaStreamNonBlocking);
    cudaEventCreateWithFlags(&g_evF, cudaEventDisableTiming);
    cudaEventCreateWithFlags(&g_evA01, cudaEventDisableTiming);
    cudaEventCreateWithFlags(&g_evA, cudaEventDisableTiming);
    cudaEventCreateWithFlags(&g_evW, cudaEventDisableTiming);
    cudaEventCreateWithFlags(&g_evSM, cudaEventDisableTiming);
    for (int b = 0; b < NBR; b++) cudaEventCreateWithFlags(&g_evM0[b], cudaEventDisableTiming);
    cudaEventCreateWithFlags(&g_evDone, cudaEventDisableTiming);
  }
};
StreamInit g_si;
}

// ======================================================================
extern "C" void kernel_launch(void* const* d_in, const int* in_sizes, int n_in,
                              void* d_out, int out_size) {
  const float* xc     = (const float*)d_in[0];
  const float* xf     = (const float*)d_in[1];
  const float* xbd    = (const float*)d_in[2];
  const float* xbg    = (const float*)d_in[3];
  const float* tokens = (const float*)d_in[4];
  const float* w_in   = (const float*)d_in[5];
  const float* b_in   = (const float*)d_in[6];
  const float* w_out  = (const float*)d_in[7];
  const float* b_out  = (const float*)d_in[8];
  float* out = (float*)d_out;

  static const int h_poff[NBR] = {0,2,4,6,9,12,15};
  static const int h_nvec[NBR] = {2,2,2,3,3,3,4};
  static const int h_main[6]   = {6,3,4,5,1,2};      // branch 0 handled on s1
  static const int h_mix[NBR]  = {0,6,3,4,5,1,2};

  cudaFuncSetAttribute(k_mma<0>, cudaFuncAttributeMaxDynamicSharedMemorySize, SMEM_SZ);
  cudaFuncSetAttribute(k_mma<1>, cudaFuncAttributeMaxDynamicSharedMemorySize, SMEM_SZ);
  cudaFuncSetAttribute(k_mma<2>, cudaFuncAttributeMaxDynamicSharedMemorySize, SMEM_SZ);

  cudaEventRecord(g_evF, 0);

  // s1: weight conversion, then early MODE0 for branch 0 (pairs 0..1, v in {0,1})
  cudaStreamWaitEvent(g_s1, g_evF, 0);
  k_convW<<<dim3(1024, 14), 256, 0, g_s1>>>(w_in, w_out);
  cudaEventRecord(g_evW, g_s1);

  // s2: score-vector chain
  cudaStreamWaitEvent(g_s2, g_evF, 0);
  k_qh<<<dim3(NBR, 16), 256, 0, g_s2>>>(tokens, w_in, b_in);
  k_zs<<<128, 256, 0, g_s2>>>();
  k_s<<<dim3(112, 4), 256, 0, g_s2>>>(w_in);

  // main: activation conversion, split (v0,v1 first)
  k_convA1<<<Bq, 256>>>(xc, 0);
  k_convA1<<<Bq, 256>>>(xf, 1);
  cudaEventRecord(g_evA01, 0);
  k_convA1<<<Bq, 256>>>(xbd, 2);
  k_convA1<<<Bq, 256>>>(xbg, 3);
  cudaEventRecord(g_evA, 0);

  // s1: branch-0 v-projection as soon as v0/v1 are converted
  cudaStreamWaitEvent(g_s1, g_evA01, 0);
  k_mma<0><<<dim3(Bq/128, Dm/256, 2), 256, SMEM_SZ, g_s1>>>(b_out, out, 0);
  cudaEventRecord(g_evM0[0], g_s1);

  // s2: scores GEMM + softmax (needs all v)
  cudaStreamWaitEvent(g_s2, g_evA, 0);
  k_mma<2><<<dim3(Bq/128, 1, 4), 256, SMEM_SZ, g_s2>>>(b_out, out, 0);
  k_softmax<<<NBR * Bq * 16 / 256, 256, 0, g_s2>>>();
  cudaEventRecord(g_evSM, g_s2);

  // main: remaining per-branch v-projections
  cudaStreamWaitEvent(0, g_evW, 0);
  for (int t = 0; t < 6; t++) {
    int b = h_main[t];
    k_mma<0><<<dim3(Bq/128, Dm/256, h_nvec[b]), 256, SMEM_SZ>>>(b_out, out, h_poff[b]);
    cudaEventRecord(g_evM0[b], 0);
  }

  // s1: per-branch mix + out-projection, pipelined
  cudaStreamWaitEvent(g_s1, g_evSM, 0);
  for (int t = 0; t < NBR; t++) {
    int b = h_mix[t];
    if (b != 0) cudaStreamWaitEvent(g_s1, g_evM0[b], 0);
    k_mix<<<Bq, 256, 0, g_s1>>>(b_in, b);
    k_mma<1><<<dim3(Bq/128, Dm/256, 1), 256, SMEM_SZ, g_s1>>>(b_out, out, b);
  }
  cudaEventRecord(g_evDone, g_s1);
  cudaStreamWaitEvent(0, g_evDone, 0);
}

// round 17
// speedup vs baseline: 10.5096x; 1.2198x over previous
#include <cuda_runtime.h>
#include <cuda_fp16.h>
#include <cstdint>

#define Bq 8192
#define Dm 1024
#define NBR 7
#define BD ((size_t)Bq * Dm)
#define DD ((size_t)Dm * Dm)

// ---------------- scratch (tiled, pre-swizzled fp16 planes: [kc][rows][32]) ----------------
__device__ float g_Q[NBR * Dm];
__device__ float g_SC[(size_t)4 * Bq * 128];
__device__ float g_A[(size_t)NBR * 4 * Bq * 16];
__device__ __align__(16) __half g_Sh[128 * Dm];
__device__ __align__(16) __half g_Sl[128 * Dm];
__device__ __align__(16) __half g_Ah[4 * BD];
__device__ __align__(16) __half g_Wh[14 * DD];
__device__ __align__(16) __half g_Oh[NBR * BD];

__constant__ int c_nvec[NBR] = {2,2,2,3,3,3,4};
__constant__ int c_vidx[NBR][4] = {{0,1,0,0},{0,2,0,0},{0,3,0,0},{0,1,2,0},{0,1,3,0},{0,2,3,0},{0,1,2,3}};

__device__ __forceinline__ size_t toff(int row, int k, int R) {
  return ((size_t)(k >> 5) * R + row) * 32 +
         (((((k >> 3) & 3) ^ ((row >> 1) & 3)) << 3) + (k & 7));
}

// ---------------- PTX helpers ----------------
__device__ __forceinline__ uint32_t smem_u32(const void* p) {
  uint32_t a;
  asm("{ .reg .u64 t; cvta.to.shared.u64 t, %1; cvt.u32.u64 %0, t; }" : "=r"(a) : "l"(p));
  return a;
}
#define MBAR_INIT(a, n) asm volatile("mbarrier.init.shared.b64 [%0], %1;" :: "r"(a), "r"(n) : "memory")
#define MBAR_EXPECT(a, b) asm volatile("mbarrier.arrive.expect_tx.shared.b64 _, [%0], %1;" :: "r"(a), "r"(b) : "memory")
#define MBAR_ARRIVE(a) asm volatile("mbarrier.arrive.shared.b64 _, [%0];" :: "r"(a) : "memory")
#define MBAR_WAIT(a, ph) do { \
  uint32_t _m = (a), _p = (ph), _d; \
  asm volatile("{ .reg .pred p; mbarrier.try_wait.parity.acquire.cta.shared::cta.b64 p, [%1], %2; selp.b32 %0,1,0,p; }" \
    : "=r"(_d) : "r"(_m), "r"(_p) : "memory"); \
  if (!_d) { asm volatile("{ .reg .pred P1; WL_%=: mbarrier.try_wait.parity.acquire.cta.shared::cta.b64 P1, [%0], %1, 0x989680; @P1 bra.uni WD_%=; bra.uni WL_%=; WD_%=: }" \
    :: "r"(_m), "r"(_p) : "memory"); } } while (0)

__device__ __forceinline__ void bulk_g2s(uint32_t dst, const void* src, uint32_t bytes, uint32_t mbar) {
  asm volatile("cp.async.bulk.shared::cluster.global.mbarrier::complete_tx::bytes [%0], [%1], %2, [%3];"
               :: "r"(dst), "l"(src), "r"(bytes), "r"(mbar) : "memory");
}
__device__ __forceinline__ void ldsm4(uint32_t& r0, uint32_t& r1, uint32_t& r2, uint32_t& r3, uint32_t addr) {
  asm volatile("ldmatrix.sync.aligned.m8n8.x4.shared.b16 {%0,%1,%2,%3}, [%4];"
               : "=r"(r0), "=r"(r1), "=r"(r2), "=r"(r3) : "r"(addr));
}
__device__ __forceinline__ void mma_f16(float* c, const uint32_t* a, const uint32_t* b) {
  asm volatile("mma.sync.aligned.m16n8k16.row.col.f32.f16.f16.f32 "
               "{%0,%1,%2,%3}, {%4,%5,%6,%7}, {%8,%9}, {%0,%1,%2,%3};"
               : "+f"(c[0]), "+f"(c[1]), "+f"(c[2]), "+f"(c[3])
               : "r"(a[0]), "r"(a[1]), "r"(a[2]), "r"(a[3]), "r"(b[0]), "r"(b[1]));
}
typedef unsigned long long u64;
__device__ __forceinline__ u64 pk2(float lo, float hi) {
  u64 r; asm("mov.b64 %0, {%1,%2};" : "=l"(r) : "f"(lo), "f"(hi)); return r;
}
__device__ __forceinline__ void fma2(u64& d, u64 a, u64 b) {
  asm("fma.rn.f32x2 %0, %1, %2, %0;" : "+l"(d) : "l"(a), "l"(b));
}
__device__ __forceinline__ void upk2(u64 v, float& a, float& b) {
  asm("mov.b64 {%0,%1}, %2;" : "=f"(a), "=f"(b) : "l"(v));
}

// ======================= fp32 -> fp16 pack =======================
__device__ __forceinline__ uint2 pack4h(float4 v) {
  __half2 a{__float2half_rn(v.x), __float2half_rn(v.y)};
  __half2 b{__float2half_rn(v.z), __float2half_rn(v.w)};
  return make_uint2(*(uint32_t*)&a, *(uint32_t*)&b);
}

// ======================= prep / conversion kernels =======================
__global__ void k_qh(const float* __restrict__ tokens, const float* __restrict__ w_in,
                     const float* __restrict__ b_in) {
  int i = blockIdx.x, rb = blockIdx.y, tid = threadIdx.x;
  int wid = tid >> 5, lane = tid & 31;
  __shared__ float tok[Dm];
  for (int k = tid; k < Dm; k += 256) tok[k] = tokens[i * Dm + k];
  __syncthreads();
  const float* wq = w_in + (size_t)i * 3 * DD;
  #pragma unroll
  for (int rr = 0; rr < 8; rr++) {
    int r = rb * 64 + wid * 8 + rr;
    const float4* row = (const float4*)(wq + (size_t)r * Dm);
    float acc = 0.f;
    #pragma unroll
    for (int j = 0; j < 8; j++) {
      float4 w = row[lane + j * 32];
      float4 t = *(const float4*)&tok[(lane + j * 32) * 4];
      acc += w.x * t.x + w.y * t.y + w.z * t.z + w.w * t.w;
    }
    #pragma unroll
    for (int o = 16; o; o >>= 1) acc += __shfl_xor_sync(0xFFFFFFFFu, acc, o);
    if (lane == 0) g_Q[i * Dm + r] = acc + b_in[i * 3 * Dm + r];
  }
}

__global__ void k_zs() {
  size_t i = ((size_t)blockIdx.x * 256 + threadIdx.x) * 4;
  *(uint2*)(g_Sh + i) = make_uint2(0, 0);
  *(uint2*)(g_Sl + i) = make_uint2(0, 0);
}

__global__ void k_s(const float* __restrict__ w_in) {
  int ih = blockIdx.x, tid = threadIdx.x;
  int i = ih >> 4, h = ih & 15;
  int k = blockIdx.y * 256 + tid;
  __shared__ float qh[64];
  if (tid < 64) qh[tid] = g_Q[i * Dm + h * 64 + tid];
  __syncthreads();
  const float* wk = w_in + (size_t)i * 3 * DD + DD + (size_t)(h * 64) * Dm + k;
  float acc = 0.f;
  #pragma unroll 8
  for (int j = 0; j < 64; j++) acc += wk[(size_t)j * Dm] * qh[j];
  float val = 0.125f * acc;
  __half hi = __float2half_rn(val);
  size_t off = toff(ih, k, 128);
  g_Sh[off] = hi;
  g_Sl[off] = __float2half_rn(val - __half2float(hi));
}

__global__ void k_softmax() {
  int idx = blockIdx.x * 256 + threadIdx.x;
  int h = idx & 15;
  int b = (idx >> 4) & (Bq - 1);
  int i = idx >> 17;
  int L = c_nvec[i];
  float sc[4];
  float mx = -1e30f;
  #pragma unroll
  for (int l = 0; l < 4; l++) if (l < L) {
    sc[l] = g_SC[((size_t)c_vidx[i][l] * Bq + b) * 128 + i * 16 + h];
    mx = fmaxf(mx, sc[l]);
  }
  float sum = 0.f;
  #pragma unroll
  for (int l = 0; l < 4; l++) if (l < L) { sc[l] = expf(sc[l] - mx); sum += sc[l]; }
  float inv = 1.f / sum;
  #pragma unroll
  for (int l = 0; l < 4; l++) if (l < L)
    g_A[(((size_t)i * 4 + l) * Bq + b) * 16 + h] = sc[l] * inv;
}

__global__ void k_convA1(const float* __restrict__ x, int v) {
  size_t i = (size_t)blockIdx.x * 256 + threadIdx.x;
  int m = (int)(i >> 8), k = ((int)i & 255) * 4;
  float4 val = ((const float4*)x)[i];
  *(uint2*)(g_Ah + (size_t)v * BD + toff(m, k, Bq)) = pack4h(val);
}

__global__ void k_convW(const float* __restrict__ w_in, const float* __restrict__ w_out) {
  int z = blockIdx.y;
  const float* src = (z < 7) ? (w_in + (size_t)z * 3 * DD + 2 * DD) : (w_out + (size_t)(z - 7) * DD);
  size_t i = (size_t)blockIdx.x * 256 + threadIdx.x;
  int n = (int)(i >> 8), k = ((int)i & 255) * 4;
  float4 val = ((const float4*)src)[i];
  *(uint2*)(g_Wh + (size_t)z * DD + toff(n, k, Dm)) = pack4h(val);
}

__device__ __forceinline__ uint32_t sw(uint32_t row, uint32_t g) {
  return row * 64 + ((g ^ ((row >> 1) & 3)) << 4);
}

// ======================= fused mix+V-proj kernel (k_mp) =======================
// For branch i: g_Oh[i][b,n] = bv[n] + sum_k M_{h(n)}[b,k] * Wv_i[n,k],
//   M_h[b,k] = sum_l a[l][b][h] * x_l[b,k]  (mixed in fp32, stored fp16 in SMEM).
// CTA 128m x 256n (4 heads), k-chunk 32, NS=2 input stages + 2 mixed buffers.
template<int L>
__global__ void __launch_bounds__(256, 1) k_mp(const float* __restrict__ b_in, int i) {
  constexpr int STG = L * 8192 + 16384;     // x tiles + B tile
  extern __shared__ __align__(128) char smem[];
  const uint32_t sb = smem_u32(smem);
  const int tid = threadIdx.x;
  const int wid = tid >> 5, lane = tid & 31;
  const int m0 = blockIdx.x * 128, n0 = blockIdx.y * 256;
  const int h0 = blockIdx.y * 4;
  const int wm = (wid & 1) * 64, wn = (wid >> 1) * 64;
  const uint32_t mbase = sb + 1024;               // 2 x 32KB mixed buffers
  const uint32_t sbase = sb + 1024 + 65536;       // 2 x STG input stages

  const __half* X[L];
  #pragma unroll
  for (int l = 0; l < L; l++) X[l] = g_Ah + (size_t)c_vidx[i][l] * BD;
  const __half* Bw = g_Wh + (size_t)i * DD;

  // attention scalars for this thread's mixing row, packed {a,a} for f32x2
  const int r = tid >> 1;
  u64 ap[L][4];
  #pragma unroll
  for (int l = 0; l < L; l++) {
    float4 av = *(const float4*)(g_A + ((size_t)(i * 4 + l) * Bq + m0 + r) * 16 + h0);
    ap[l][0] = pk2(av.x, av.x); ap[l][1] = pk2(av.y, av.y);
    ap[l][2] = pk2(av.z, av.z); ap[l][3] = pk2(av.w, av.w);
  }
  const uint32_t xoff = r * 64 + (tid & 1) * 32;  // byte offset within an 8KB tile

  if (tid == 0) {
    #pragma unroll
    for (int s = 0; s < 2; s++) { MBAR_INIT(sb + s * 8, 1); MBAR_INIT(sb + 128 + s * 8, 8); }
  }
  __syncthreads();

  auto issue = [&](int c) {
    int s = c & 1;
    uint32_t st = sbase + s * STG;
    uint32_t mb = sb + s * 8;
    MBAR_EXPECT(mb, STG);
    #pragma unroll
    for (int l = 0; l < L; l++)
      bulk_g2s(st + l * 8192, X[l] + ((size_t)c * Bq + m0) * 32, 8192, mb);
    bulk_g2s(st + L * 8192, Bw + ((size_t)c * Dm + n0) * 32, 16384, mb);
  };
  if (tid == 0) { issue(0); issue(1); }

  float acc[4][8][4];
  #pragma unroll
  for (int mt = 0; mt < 4; mt++)
    #pragma unroll
    for (int nt = 0; nt < 8; nt++)
      #pragma unroll
      for (int q = 0; q < 4; q++) acc[mt][nt][q] = 0.f;

  const int arow = wm + (lane & 15);
  const int agsel = lane >> 4;
  const int brow = wn + ((lane & 7) | ((lane & 16) >> 1));
  const int bgsel = (lane >> 3) & 1;
  const uint32_t abhead = (uint32_t)(wid >> 1) * 8192;   // warp's head plane

  for (int c = 0; c < 32; c++) {
    const int s = c & 1;
    const uint32_t st = sbase + s * STG;
    const uint32_t mb_ = mbase + s * 32768;
    MBAR_WAIT(sb + s * 8, (c >> 1) & 1);

    // ---- mix: thread covers row r, 16 halves (tid&1 half-row), all 4 heads ----
    #pragma unroll
    for (int sub = 0; sub < 2; sub++) {
      u64 x2[L][4];
      #pragma unroll
      for (int l = 0; l < L; l++) {
        uint4 u = *(const uint4*)(smem + (st - sb) + l * 8192 + xoff + sub * 16);
        #pragma unroll
        for (int q = 0; q < 4; q++) {
          float2 f = __half22float2(((const __half2*)&u)[q]);
          x2[l][q] = pk2(f.x, f.y);
        }
      }
      #pragma unroll
      for (int hh = 0; hh < 4; hh++) {
        uint4 o;
        #pragma unroll
        for (int q = 0; q < 4; q++) {
          u64 d = 0ULL;
          #pragma unroll
          for (int l = 0; l < L; l++) fma2(d, ap[l][hh], x2[l][q]);
          float fx, fy; upk2(d, fx, fy);
          __half2 hv{__float2half_rn(fx), __float2half_rn(fy)};
          ((uint32_t*)&o)[q] = *(uint32_t*)&hv;
        }
        *(uint4*)(smem + (mb_ - sb) + hh * 8192 + xoff + sub * 16) = o;
      }
    }
    __syncthreads();

    // ---- HMMA: A from mixed buffer (own head), B = Wv tile ----
    const uint32_t stB = st + L * 8192;
    #pragma unroll
    for (int ks = 0; ks < 2; ks++) {
      uint32_t ah[4][4], bh[8][2];
      #pragma unroll
      for (int mt = 0; mt < 4; mt++) {
        uint32_t ad = mb_ + abhead + sw(arow + mt * 16, ks * 2 + agsel);
        ldsm4(ah[mt][0], ah[mt][1], ah[mt][2], ah[mt][3], ad);
      }
      #pragma unroll
      for (int np = 0; np < 4; np++) {
        uint32_t bd = stB + sw(brow + np * 16, ks * 2 + bgsel);
        ldsm4(bh[np*2][0], bh[np*2][1], bh[np*2+1][0], bh[np*2+1][1], bd);
      }
      #pragma unroll
      for (int mt = 0; mt < 4; mt++)
        #pragma unroll
        for (int nt = 0; nt < 8; nt++)
          mma_f16(acc[mt][nt], ah[mt], bh[nt]);
    }
    if (lane == 0) MBAR_ARRIVE(sb + 128 + s * 8);
    if (tid == 0 && c + 2 < 32) {
      MBAR_WAIT(sb + 128 + s * 8, (c >> 1) & 1);
      issue(c + 2);
    }
  }

  // ---- epilogue: + bv, pack fp16, write tiled g_Oh ----
  const float* bv = b_in + ((size_t)i * 3 + 2) * Dm;
  __half* Co = g_Oh + (size_t)i * BD;
  #pragma unroll
  for (int mt = 0; mt < 4; mt++) {
    int m = m0 + wm + mt * 16 + (lane >> 2);
    #pragma unroll
    for (int nt = 0; nt < 8; nt++) {
      int n = n0 + wn / 8 * 8 + nt * 8 + (lane & 3) * 2;   // wn covers 64 cols: nt*8 within
      n = n0 + wn + nt * 8 + (lane & 3) * 2;
      float b0 = __ldg(bv + n), b1 = __ldg(bv + n + 1);
      __half2 h0v{__float2half_rn(acc[mt][nt][0] + b0), __float2half_rn(acc[mt][nt][1] + b1)};
      __half2 h1v{__float2half_rn(acc[mt][nt][2] + b0), __float2half_rn(acc[mt][nt][3] + b1)};
      *(uint32_t*)(Co + toff(m, n, Bq)) = *(uint32_t*)&h0v;
      *(uint32_t*)(Co + toff(m + 8, n, Bq)) = *(uint32_t*)&h1v;
    }
  }
}

// ======================= bulk-copy fp16 HMMA GEMM (out-proj + scores) =======================
#define NCH 16
#define SMEM_SZ (1024 + 196608)

template<int MODE>
__global__ void __launch_bounds__(256, 1) k_mma(const float* __restrict__ b_out,
                                                float* __restrict__ dout, int zoff) {
  constexpr int STG = 49152;
  constexpr int NS  = 4;
  constexpr int NT  = (MODE == 2) ? 4 : 8;
  extern __shared__ __align__(128) char smem[];
  const uint32_t sb = smem_u32(smem);
  const int tid = threadIdx.x;
  const int wid = tid >> 5, lane = tid & 31;
  const int m0 = blockIdx.x * 128;
  const int n0 = blockIdx.y * ((MODE == 2) ? 128 : 256);
  const int wm = (wid & 1) * 64, wn = (wid >> 1) * (NT * 8);
  const int cst = (MODE == 2) ? 128 : 1024;
  const int RB  = (MODE == 2) ? 128 : 1024;

  const __half *Ah, *Bh, *Bl = nullptr;
  float* C = nullptr; const float* bias = nullptr;
  if (MODE == 1) {
    int i = zoff;
    Ah = g_Oh + (size_t)i * BD;
    Bh = g_Wh + (size_t)(7 + i) * DD;
    C = dout + (size_t)i * BD;
    bias = b_out + i * Dm;
  } else {
    int v = blockIdx.z;
    Ah = g_Ah + (size_t)v * BD;
    Bh = g_Sh; Bl = g_Sl;
    C = g_SC + (size_t)v * Bq * 128;
  }

  if (tid == 0) {
    #pragma unroll
    for (int s = 0; s < NS; s++) { MBAR_INIT(sb + s * 8, 1); MBAR_INIT(sb + 128 + s * 8, 8); }
  }
  __syncthreads();

  auto issue = [&](int c) {
    int s = c % NS;
    uint32_t st = sb + 1024 + s * STG;
    uint32_t mb = sb + s * 8;
    MBAR_EXPECT(mb, STG);
    bulk_g2s(st,        Ah + ((size_t)(2*c)   * Bq + m0) * 32, 8192, mb);
    bulk_g2s(st + 8192, Ah + ((size_t)(2*c+1) * Bq + m0) * 32, 8192, mb);
    if (MODE == 2) {
      bulk_g2s(st + 16384, Bh + ((size_t)(2*c)   * RB + n0) * 32, 8192, mb);
      bulk_g2s(st + 24576, Bh + ((size_t)(2*c+1) * RB + n0) * 32, 8192, mb);
      bulk_g2s(st + 32768, Bl + ((size_t)(2*c)   * RB + n0) * 32, 8192, mb);
      bulk_g2s(st + 40960, Bl + ((size_t)(2*c+1) * RB + n0) * 32, 8192, mb);
    } else {
      bulk_g2s(st + 16384, Bh + ((size_t)(2*c)   * RB + n0) * 32, 16384, mb);
      bulk_g2s(st + 32768, Bh + ((size_t)(2*c+1) * RB + n0) * 32, 16384, mb);
    }
  };
  if (tid == 0) {
    #pragma unroll
    for (int c = 0; c < NS; c++) issue(c);
  }

  float acc[4][NT][4];
  #pragma unroll
  for (int mt = 0; mt < 4; mt++)
    #pragma unroll
    for (int nt = 0; nt < NT; nt++)
      #pragma unroll
      for (int q = 0; q < 4; q++) acc[mt][nt][q] = 0.f;

  const int arow = wm + (lane & 15);
  const int agsel = lane >> 4;
  const int brow = wn + ((lane & 7) | ((lane & 16) >> 1));
  const int bgsel = (lane >> 3) & 1;

  for (int c = 0; c < NCH; c++) {
    const int s = c % NS;
    const uint32_t st = sb + 1024 + s * STG;
    MBAR_WAIT(sb + s * 8, (c / NS) & 1);
    #pragma unroll
    for (int ks = 0; ks < 4; ks++) {
      const int kp = ks >> 1, kk = (ks & 1) * 2;
      const uint32_t stA = st + kp * 8192;
      const uint32_t stB = st + 16384 + kp * ((MODE == 2) ? 8192 : 16384);
      uint32_t ah[4][4], bh[NT][2];
      #pragma unroll
      for (int mt = 0; mt < 4; mt++) {
        uint32_t ad = stA + sw(arow + mt * 16, kk + agsel);
        ldsm4(ah[mt][0], ah[mt][1], ah[mt][2], ah[mt][3], ad);
      }
      #pragma unroll
      for (int np = 0; np < NT / 2; np++) {
        uint32_t bd = stB + sw(brow + np * 16, kk + bgsel);
        ldsm4(bh[np*2][0], bh[np*2][1], bh[np*2+1][0], bh[np*2+1][1], bd);
      }
      uint32_t bl[NT][2];
      if (MODE == 2) {
        #pragma unroll
        for (int np = 0; np < NT / 2; np++) {
          uint32_t bd = stB + 16384 + sw(brow + np * 16, kk + bgsel);
          ldsm4(bl[np*2][0], bl[np*2][1], bl[np*2+1][0], bl[np*2+1][1], bd);
        }
      }
      #pragma unroll
      for (int mt = 0; mt < 4; mt++)
        #pragma unroll
        for (int nt = 0; nt < NT; nt++) {
          mma_f16(acc[mt][nt], ah[mt], bh[nt]);
          if (MODE == 2) mma_f16(acc[mt][nt], ah[mt], bl[nt]);
        }
    }
    if (lane == 0) MBAR_ARRIVE(sb + 128 + s * 8);
    if (tid == 0 && c + NS < NCH) {
      MBAR_WAIT(sb + 128 + s * 8, (c / NS) & 1);
      issue(c + NS);
    }
  }

  #pragma unroll
  for (int mt = 0; mt < 4; mt++) {
    int m = m0 + wm + mt * 16 + (lane >> 2);
    #pragma unroll
    for (int nt = 0; nt < NT; nt++) {
      int n = n0 + wn + nt * 8 + (lane & 3) * 2;
      float2 v0 = make_float2(acc[mt][nt][0], acc[mt][nt][1]);
      float2 v1 = make_float2(acc[mt][nt][2], acc[mt][nt][3]);
      if (MODE == 1) {
        float b0 = __ldg(bias + n), b1 = __ldg(bias + n + 1);
        v0.x += b0; v0.y += b1; v1.x += b0; v1.y += b1;
      }
      *(float2*)(C + (size_t)m * cst + n) = v0;
      *(float2*)(C + (size_t)(m + 8) * cst + n) = v1;
    }
  }
}

// ======================= streams / events =======================
static cudaStream_t g_s1, g_s2;
static cudaEvent_t g_evF, g_evA, g_evW, g_evSM, g_evMP[NBR], g_evDone;
namespace {
struct StreamInit {
  StreamInit() {
    cudaStreamCreateWithFlags(&g_s1, cudaStreamNonBlocking);
    cudaStreamCreateWithFlags(&g_s2, cudaStreamNonBlocking);
    cudaEventCreateWithFlags(&g_evF, cudaEventDisableTiming);
    cudaEventCreateWithFlags(&g_evA, cudaEventDisableTiming);
    cudaEventCreateWithFlags(&g_evW, cudaEventDisableTiming);
    cudaEventCreateWithFlags(&g_evSM, cudaEventDisableTiming);
    for (int b = 0; b < NBR; b++) cudaEventCreateWithFlags(&g_evMP[b], cudaEventDisableTiming);
    cudaEventCreateWithFlags(&g_evDone, cudaEventDisableTiming);
  }
};
StreamInit g_si;
}

// ======================================================================
extern "C" void kernel_launch(void* const* d_in, const int* in_sizes, int n_in,
                              void* d_out, int out_size) {
  const float* xc     = (const float*)d_in[0];
  const float* xf     = (const float*)d_in[1];
  const float* xbd    = (const float*)d_in[2];
  const float* xbg    = (const float*)d_in[3];
  const float* tokens = (const float*)d_in[4];
  const float* w_in   = (const float*)d_in[5];
  const float* b_in   = (const float*)d_in[6];
  const float* w_out  = (const float*)d_in[7];
  const float* b_out  = (const float*)d_in[8];
  float* out = (float*)d_out;

  static const int h_nvec[NBR] = {2,2,2,3,3,3,4};
  const int smem_mp[5] = {0, 0, 1024 + 65536 + 2*(2*8192+16384),
                                1024 + 65536 + 2*(3*8192+16384),
                                1024 + 65536 + 2*(4*8192+16384)};

  cudaFuncSetAttribute(k_mp<2>, cudaFuncAttributeMaxDynamicSharedMemorySize, smem_mp[2]);
  cudaFuncSetAttribute(k_mp<3>, cudaFuncAttributeMaxDynamicSharedMemorySize, smem_mp[3]);
  cudaFuncSetAttribute(k_mp<4>, cudaFuncAttributeMaxDynamicSharedMemorySize, smem_mp[4]);
  cudaFuncSetAttribute(k_mma<1>, cudaFuncAttributeMaxDynamicSharedMemorySize, SMEM_SZ);
  cudaFuncSetAttribute(k_mma<2>, cudaFuncAttributeMaxDynamicSharedMemorySize, SMEM_SZ);

  cudaEventRecord(g_evF, 0);

  // s1: weight conversion
  cudaStreamWaitEvent(g_s1, g_evF, 0);
  k_convW<<<dim3(1024, 14), 256, 0, g_s1>>>(w_in, w_out);
  cudaEventRecord(g_evW, g_s1);

  // s2: score-vector chain
  cudaStreamWaitEvent(g_s2, g_evF, 0);
  k_qh<<<dim3(NBR, 16), 256, 0, g_s2>>>(tokens, w_in, b_in);
  k_zs<<<128, 256, 0, g_s2>>>();
  k_s<<<dim3(112, 4), 256, 0, g_s2>>>(w_in);

  // main: activation conversion
  k_convA1<<<Bq, 256>>>(xc, 0);
  k_convA1<<<Bq, 256>>>(xf, 1);
  k_convA1<<<Bq, 256>>>(xbd, 2);
  k_convA1<<<Bq, 256>>>(xbg, 3);
  cudaEventRecord(g_evA, 0);

  // s2: scores GEMM + softmax
  cudaStreamWaitEvent(g_s2, g_evA, 0);
  k_mma<2><<<dim3(Bq/128, 1, 4), 256, SMEM_SZ, g_s2>>>(b_out, out, 0);
  k_softmax<<<NBR * Bq * 16 / 256, 256, 0, g_s2>>>();
  cudaEventRecord(g_evSM, g_s2);

  // main: per-branch fused mix+V-proj; s1: out-proj pipelined behind it
  cudaStreamWaitEvent(0, g_evW, 0);
  cudaStreamWaitEvent(0, g_evSM, 0);
  for (int b = 0; b < NBR; b++) {
    int L = h_nvec[b];
    if (L == 2)      k_mp<2><<<dim3(Bq/128, 4), 256, smem_mp[2]>>>(b_in, b);
    else if (L == 3) k_mp<3><<<dim3(Bq/128, 4), 256, smem_mp[3]>>>(b_in, b);
    else             k_mp<4><<<dim3(Bq/128, 4), 256, smem_mp[4]>>>(b_in, b);
    cudaEventRecord(g_evMP[b], 0);
    cudaStreamWaitEvent(g_s1, g_evMP[b], 0);
    k_mma<1><<<dim3(Bq/128, Dm/256, 1), 256, SMEM_SZ, g_s1>>>(b_out, out, b);
  }
  cudaEventRecord(g_evDone, g_s1);
  cudaStreamWaitEvent(0, g_evDone, 0);
}